// round 3
// baseline (speedup 1.0000x reference)
#include <cuda_runtime.h>
#include <math.h>

#define NN 65536
#define NE 524288
#define DN 128
#define DE 64
#define HH 128
#define DC (DN + HH)   // 256
#define EPSbn 1e-3f

// ---------------- scratch (no allocations allowed) ----------------
__device__ float g_hmsg[(size_t)NN * HH];   // per-node base message h(node_x)
__device__ float g_agg [(size_t)NN * HH];   // segment sum of msg by src
__device__ float g_u1  [(size_t)NN * HH];   // update hidden
__device__ float g_cnt [NN];                // degree (as float)

// folded (BN-absorbed) weights
__device__ float g_bmW1[DN * HH]; __device__ float g_bmB1[HH];
__device__ float g_bmW2[HH * HH]; __device__ float g_bmB2[HH];
__device__ float g_upW1[DC * HH]; __device__ float g_upB1[HH];
__device__ float g_upW2[HH * HH]; __device__ float g_upB2[HH];

__device__ __forceinline__ float gelu_f(float x) {
    // exact gelu: x * Phi(x)
    return x * normcdff(x);
}

// ---------------- BN folding ----------------
// BN(x) = x*s + t, s = g*rsqrt(v+eps), t = b - m*s
// BN(x)@W + bb = x@(s.*W rowwise) + (bb + t@W)
__global__ void fold_kernel(const float* __restrict__ g, const float* __restrict__ b,
                            const float* __restrict__ m, const float* __restrict__ v,
                            const float* __restrict__ W, const float* __restrict__ bb,
                            int K, int which) {
    float* Wo; float* Bo;
    if      (which == 0) { Wo = g_bmW1; Bo = g_bmB1; }
    else if (which == 1) { Wo = g_bmW2; Bo = g_bmB2; }
    else if (which == 2) { Wo = g_upW1; Bo = g_upB1; }
    else                 { Wo = g_upW2; Bo = g_upB2; }
    int j = threadIdx.x;
    float acc = 0.f;
    for (int i = 0; i < K; i++) {
        float s = g[i] * rsqrtf(v[i] + EPSbn);
        float t = b[i] - m[i] * s;
        float w = W[i * HH + j];
        Wo[i * HH + j] = s * w;
        acc += t * w;
    }
    Bo[j] = bb[j] + acc;
}

// ---------------- zero agg + cnt (runs every replay) ----------------
__global__ void zero_kernel() {
    int i = blockIdx.x * blockDim.x + threadIdx.x;
    if (i < NN * HH / 4) ((float4*)g_agg)[i] = make_float4(0.f, 0.f, 0.f, 0.f);
    if (i < NN / 4)      ((float4*)g_cnt)[i] = make_float4(0.f, 0.f, 0.f, 0.f);
}

__global__ void deg_kernel(const int* __restrict__ src) {
    int i = blockIdx.x * blockDim.x + threadIdx.x;
    if (i < NE) atomicAdd(&g_cnt[src[i]], 1.0f);
}

// ---------------- shared-mem micro GEMM: 4 rows x 8 cols per thread ----------------
template<int K, int XS>
__device__ __forceinline__ void tile_gemm(const float* Xs, const float* Ws,
                                          int r0, int c0, float acc[4][8]) {
#pragma unroll 8
    for (int k = 0; k < K; k++) {
        float4 w0 = *(const float4*)(Ws + k * HH + c0);
        float4 w1 = *(const float4*)(Ws + k * HH + c0 + 4);
        float wv[8] = {w0.x, w0.y, w0.z, w0.w, w1.x, w1.y, w1.z, w1.w};
        float av[4];
#pragma unroll
        for (int i = 0; i < 4; i++) av[i] = Xs[(r0 + i) * XS + k];
#pragma unroll
        for (int i = 0; i < 4; i++)
#pragma unroll
            for (int j = 0; j < 8; j++)
                acc[i][j] = fmaf(av[i], wv[j], acc[i][j]);
    }
}

// ---------------- node base-message MLP: 2 fused GEMMs, 128-row tiles ----------------
// smem: W1(16384) + W2(16384) + Xs(128*132) floats = 198656 B
__global__ void __launch_bounds__(512, 1)
node_mlp2_kernel(const float* __restrict__ X, int tiles) {
    extern __shared__ float sm[];
    float* W1s = sm;
    float* W2s = W1s + DN * HH;
    float* Xs  = W2s + HH * HH;
    int tid = threadIdx.x, tx = tid & 15, ty = tid >> 4;
    int r0 = ty * 4, c0 = tx * 8;
    for (int i = tid; i < DN * HH / 4; i += 512) {
        ((float4*)W1s)[i] = ((const float4*)g_bmW1)[i];
        ((float4*)W2s)[i] = ((const float4*)g_bmW2)[i];
    }
    float b1[8], b2[8];
#pragma unroll
    for (int j = 0; j < 8; j++) { b1[j] = g_bmB1[c0 + j]; b2[j] = g_bmB2[c0 + j]; }
    __syncthreads();
    for (int t = blockIdx.x; t < tiles; t += gridDim.x) {
        size_t base = (size_t)t * 128;
        for (int i = tid; i < 128 * DN / 4; i += 512) {
            int e = i * 4; int r = e >> 7; int k = e & 127;
            *(float4*)(Xs + r * 132 + k) = ((const float4*)(X + base * DN))[i];
        }
        __syncthreads();
        float acc[4][8] = {};
        tile_gemm<DN, 132>(Xs, W1s, r0, c0, acc);
        __syncthreads();   // everyone done reading Xs
#pragma unroll
        for (int i = 0; i < 4; i++)
#pragma unroll
            for (int j = 0; j < 8; j++)
                Xs[(r0 + i) * 132 + c0 + j] = gelu_f(acc[i][j] + b1[j]);
        __syncthreads();
        float acc2[4][8] = {};
        tile_gemm<HH, 132>(Xs, W2s, r0, c0, acc2);
#pragma unroll
        for (int i = 0; i < 4; i++) {
            float4 o0, o1;
            o0.x = gelu_f(acc2[i][0] + b2[0]); o0.y = gelu_f(acc2[i][1] + b2[1]);
            o0.z = gelu_f(acc2[i][2] + b2[2]); o0.w = gelu_f(acc2[i][3] + b2[3]);
            o1.x = gelu_f(acc2[i][4] + b2[4]); o1.y = gelu_f(acc2[i][5] + b2[5]);
            o1.z = gelu_f(acc2[i][6] + b2[6]); o1.w = gelu_f(acc2[i][7] + b2[7]);
            *(float4*)(g_hmsg + (base + r0 + i) * HH + c0)     = o0;
            *(float4*)(g_hmsg + (base + r0 + i) * HH + c0 + 4) = o1;
        }
        __syncthreads();
    }
}

// ---------------- fused edge kernel: 2 GEMMs + gather + atomic scatter ----------------
// smem: W1(8192) + W2(16384) + As(128*68) + E1s(128*132) floats + 256 ints = 201728 B
__global__ void __launch_bounds__(512, 1)
edge_kernel(const float* __restrict__ EA,
            const float* __restrict__ W1, const float* __restrict__ B1,
            const float* __restrict__ W2, const float* __restrict__ B2,
            const int* __restrict__ esrc, const int* __restrict__ edst, int tiles) {
    extern __shared__ float sm[];
    float* W1s = sm;
    float* W2s = W1s + DE * HH;
    float* As  = W2s + HH * HH;
    float* E1s = As + 128 * 68;
    int* src_s = (int*)(E1s + 128 * 132);
    int* dst_s = src_s + 128;
    int tid = threadIdx.x, tx = tid & 15, ty = tid >> 4;
    int r0 = ty * 4, c0 = tx * 8;
    for (int i = tid; i < DE * HH / 4; i += 512) ((float4*)W1s)[i] = ((const float4*)W1)[i];
    for (int i = tid; i < HH * HH / 4; i += 512) ((float4*)W2s)[i] = ((const float4*)W2)[i];
    float b1[8], b2[8];
#pragma unroll
    for (int j = 0; j < 8; j++) { b1[j] = B1[c0 + j]; b2[j] = B2[c0 + j]; }
    __syncthreads();
    for (int t = blockIdx.x; t < tiles; t += gridDim.x) {
        size_t base = (size_t)t * 128;
        for (int i = tid; i < 128 * DE / 4; i += 512) {
            int e = i * 4; int r = e >> 6; int k = e & 63;
            *(float4*)(As + r * 68 + k) = ((const float4*)(EA + base * DE))[i];
        }
        if (tid < 128)      src_s[tid] = esrc[base + tid];
        else if (tid < 256) dst_s[tid - 128] = edst[base + tid - 128];
        __syncthreads();
        float acc[4][8] = {};
        tile_gemm<DE, 68>(As, W1s, r0, c0, acc);
#pragma unroll
        for (int i = 0; i < 4; i++)
#pragma unroll
            for (int j = 0; j < 8; j++)
                E1s[(r0 + i) * 132 + c0 + j] = gelu_f(acc[i][j] + b1[j]);
        __syncthreads();
        float acc2[4][8] = {};
        tile_gemm<HH, 132>(E1s, W2s, r0, c0, acc2);
#pragma unroll
        for (int i = 0; i < 4; i++) {
            int r = r0 + i;
            int dd = dst_s[r], ss = src_s[r];
            const float4* hp = (const float4*)(g_hmsg + (size_t)dd * HH + c0);
            float4 h0 = hp[0], h1 = hp[1];
            float m[8];
            m[0] = gelu_f(acc2[i][0] + b2[0]) * h0.x;
            m[1] = gelu_f(acc2[i][1] + b2[1]) * h0.y;
            m[2] = gelu_f(acc2[i][2] + b2[2]) * h0.z;
            m[3] = gelu_f(acc2[i][3] + b2[3]) * h0.w;
            m[4] = gelu_f(acc2[i][4] + b2[4]) * h1.x;
            m[5] = gelu_f(acc2[i][5] + b2[5]) * h1.y;
            m[6] = gelu_f(acc2[i][6] + b2[6]) * h1.z;
            m[7] = gelu_f(acc2[i][7] + b2[7]) * h1.w;
            float* ap = g_agg + (size_t)ss * HH + c0;
#pragma unroll
            for (int j = 0; j < 8; j++) atomicAdd(ap + j, m[j]);
        }
        __syncthreads();
    }
}

// ---------------- update stage 1: [node_x | agg/cnt] (K=256) -> gelu -> g_u1 ----------------
// smem: W1(32768) + Xs(64*260) floats = 197632 B
__global__ void __launch_bounds__(256, 1)
update1_kernel(const float* __restrict__ X, int tiles) {
    extern __shared__ float sm[];
    float* W1s = sm;
    float* Xs  = W1s + DC * HH;
    int tid = threadIdx.x, tx = tid & 15, ty = tid >> 4;
    int r0 = ty * 4, c0 = tx * 8;
    for (int i = tid; i < DC * HH / 4; i += 256) ((float4*)W1s)[i] = ((const float4*)g_upW1)[i];
    float b1[8];
#pragma unroll
    for (int j = 0; j < 8; j++) b1[j] = g_upB1[c0 + j];
    __syncthreads();
    for (int t = blockIdx.x; t < tiles; t += gridDim.x) {
        size_t base = (size_t)t * 64;
        for (int i = tid; i < 64 * DN / 4; i += 256) {
            int e = i * 4; int r = e >> 7; int k = e & 127;
            *(float4*)(Xs + r * 260 + k) = ((const float4*)(X + base * DN))[i];
        }
        for (int i = tid; i < 64 * HH / 4; i += 256) {
            int e = i * 4; int r = e >> 7; int k = e & 127;
            float4 v = ((const float4*)(g_agg + base * HH))[i];
            float s = 1.0f / fmaxf(g_cnt[base + r], 1.0f);
            v.x *= s; v.y *= s; v.z *= s; v.w *= s;
            *(float4*)(Xs + r * 260 + 128 + k) = v;
        }
        __syncthreads();
        float acc[4][8] = {};
        tile_gemm<DC, 260>(Xs, W1s, r0, c0, acc);
#pragma unroll
        for (int i = 0; i < 4; i++) {
            float4 o0, o1;
            o0.x = gelu_f(acc[i][0] + b1[0]); o0.y = gelu_f(acc[i][1] + b1[1]);
            o0.z = gelu_f(acc[i][2] + b1[2]); o0.w = gelu_f(acc[i][3] + b1[3]);
            o1.x = gelu_f(acc[i][4] + b1[4]); o1.y = gelu_f(acc[i][5] + b1[5]);
            o1.z = gelu_f(acc[i][6] + b1[6]); o1.w = gelu_f(acc[i][7] + b1[7]);
            *(float4*)(g_u1 + (base + r0 + i) * HH + c0)     = o0;
            *(float4*)(g_u1 + (base + r0 + i) * HH + c0 + 4) = o1;
        }
        __syncthreads();
    }
}

// ---------------- update stage 2: g_u1 @ upW2' -> gelu -> d_out ----------------
// smem: W(16384) + Xs(64*132) floats = 99328 B (2 blocks/SM)
__global__ void __launch_bounds__(256, 2)
mlp1_kernel(float* __restrict__ out, int tiles) {
    extern __shared__ float sm[];
    float* Ws = sm;
    float* Xs = Ws + HH * HH;
    int tid = threadIdx.x, tx = tid & 15, ty = tid >> 4;
    int r0 = ty * 4, c0 = tx * 8;
    for (int i = tid; i < HH * HH / 4; i += 256) ((float4*)Ws)[i] = ((const float4*)g_upW2)[i];
    float b[8];
#pragma unroll
    for (int j = 0; j < 8; j++) b[j] = g_upB2[c0 + j];
    __syncthreads();
    for (int t = blockIdx.x; t < tiles; t += gridDim.x) {
        size_t base = (size_t)t * 64;
        for (int i = tid; i < 64 * HH / 4; i += 256) {
            int e = i * 4; int r = e >> 7; int k = e & 127;
            *(float4*)(Xs + r * 132 + k) = ((const float4*)(g_u1 + base * HH))[i];
        }
        __syncthreads();
        float acc[4][8] = {};
        tile_gemm<HH, 132>(Xs, Ws, r0, c0, acc);
#pragma unroll
        for (int i = 0; i < 4; i++) {
            float4 o0, o1;
            o0.x = gelu_f(acc[i][0] + b[0]); o0.y = gelu_f(acc[i][1] + b[1]);
            o0.z = gelu_f(acc[i][2] + b[2]); o0.w = gelu_f(acc[i][3] + b[3]);
            o1.x = gelu_f(acc[i][4] + b[4]); o1.y = gelu_f(acc[i][5] + b[5]);
            o1.z = gelu_f(acc[i][6] + b[6]); o1.w = gelu_f(acc[i][7] + b[7]);
            *(float4*)(out + (base + r0 + i) * HH + c0)     = o0;
            *(float4*)(out + (base + r0 + i) * HH + c0 + 4) = o1;
        }
        __syncthreads();
    }
}

// ---------------- launch ----------------
extern "C" void kernel_launch(void* const* d_in, const int* in_sizes, int n_in,
                              void* d_out, int out_size) {
    const float* node_x = (const float*)d_in[0];
    const float* eattr  = (const float*)d_in[1];
    const float* bm_g1 = (const float*)d_in[2];
    const float* bm_b1 = (const float*)d_in[3];
    const float* bm_m1 = (const float*)d_in[4];
    const float* bm_v1 = (const float*)d_in[5];
    const float* bm_w1 = (const float*)d_in[6];
    const float* bm_bb1= (const float*)d_in[7];
    const float* bm_g2 = (const float*)d_in[8];
    const float* bm_b2 = (const float*)d_in[9];
    const float* bm_m2 = (const float*)d_in[10];
    const float* bm_v2 = (const float*)d_in[11];
    const float* bm_w2 = (const float*)d_in[12];
    const float* bm_bb2= (const float*)d_in[13];
    const float* et_w1 = (const float*)d_in[14];
    const float* et_b1 = (const float*)d_in[15];
    const float* et_w2 = (const float*)d_in[16];
    const float* et_b2 = (const float*)d_in[17];
    const float* up_g1 = (const float*)d_in[18];
    const float* up_b1 = (const float*)d_in[19];
    const float* up_m1 = (const float*)d_in[20];
    const float* up_v1 = (const float*)d_in[21];
    const float* up_w1 = (const float*)d_in[22];
    const float* up_bb1= (const float*)d_in[23];
    const float* up_g2 = (const float*)d_in[24];
    const float* up_b2 = (const float*)d_in[25];
    const float* up_m2 = (const float*)d_in[26];
    const float* up_v2 = (const float*)d_in[27];
    const float* up_w2 = (const float*)d_in[28];
    const float* up_bb2= (const float*)d_in[29];
    const int*   esrc  = (const int*)d_in[30];
    const int*   edst  = (const int*)d_in[31];
    float* out = (float*)d_out;

    const int SM_NODE = (DN*HH + HH*HH + 128*132) * 4;
    const int SM_EDGE = (DE*HH + HH*HH + 128*68 + 128*132) * 4 + 256 * 4;
    const int SM_UP1  = (DC*HH + 64*260) * 4;
    const int SM_UP2  = (HH*HH + 64*132) * 4;
    cudaFuncSetAttribute(node_mlp2_kernel, cudaFuncAttributeMaxDynamicSharedMemorySize, SM_NODE);
    cudaFuncSetAttribute(edge_kernel,      cudaFuncAttributeMaxDynamicSharedMemorySize, SM_EDGE);
    cudaFuncSetAttribute(update1_kernel,   cudaFuncAttributeMaxDynamicSharedMemorySize, SM_UP1);
    cudaFuncSetAttribute(mlp1_kernel,      cudaFuncAttributeMaxDynamicSharedMemorySize, SM_UP2);

    fold_kernel<<<1, 128>>>(bm_g1, bm_b1, bm_m1, bm_v1, bm_w1, bm_bb1, DN, 0);
    fold_kernel<<<1, 128>>>(bm_g2, bm_b2, bm_m2, bm_v2, bm_w2, bm_bb2, HH, 1);
    fold_kernel<<<1, 128>>>(up_g1, up_b1, up_m1, up_v1, up_w1, up_bb1, DC, 2);
    fold_kernel<<<1, 128>>>(up_g2, up_b2, up_m2, up_v2, up_w2, up_bb2, HH, 3);

    zero_kernel<<<(NN * HH / 4 + 255) / 256, 256>>>();
    deg_kernel<<<(NE + 255) / 256, 256>>>(esrc);

    node_mlp2_kernel<<<148, 512, SM_NODE>>>(node_x, NN / 128);
    edge_kernel<<<148, 512, SM_EDGE>>>(eattr, et_w1, et_b1, et_w2, et_b2, esrc, edst, NE / 128);
    update1_kernel<<<148, 256, SM_UP1>>>(node_x, NN / 64);
    mlp1_kernel<<<296, 256, SM_UP2>>>(out, NN / 64);
}

// round 8
// speedup vs baseline: 2.0245x; 2.0245x over previous
#include <cuda_runtime.h>
#include <math.h>
#include <stdint.h>

#define NN 65536
#define NE 524288
#define DN 128
#define DE 64
#define HH 128
#define DC (DN + HH)
#define EPSbn 1e-3f

// ---------------- scratch ----------------
__device__ float g_hmsg[(size_t)NN * HH];
__device__ float g_agg [(size_t)NN * HH];
__device__ float g_u1  [(size_t)NN * HH];
__device__ float g_cnt [NN];

__device__ float g_bmW1[DN * HH]; __device__ float g_bmB1[HH];
__device__ float g_bmW2[HH * HH]; __device__ float g_bmB2[HH];
__device__ float g_upW1[DC * HH]; __device__ float g_upB1[HH];
__device__ float g_upW2[HH * HH]; __device__ float g_upB2[HH];

__device__ __forceinline__ float gelu_f(float x) { return x * normcdff(x); }

// tf32 round: destination must be .b32 per PTX spec
__device__ __forceinline__ float to_tf32(float x) {
    uint32_t r; asm("cvt.rna.tf32.f32 %0, %1;" : "=r"(r) : "f"(x));
    return __uint_as_float(r);
}

// ---------------- warp-level tf32 MMA GEMM ----------------
// Warp computes D[16 x 128] += X[16 x 8*KT] @ Wt^T, operands in smem.
// Xs: row-major [row][k], pitch xp (pad so xp mod 32 == 4)
// Wt: [n][k] (transposed weight), pitch wp (pad so wp mod 32 == 4)
// acc[nt][0..3]: c0,c1 = (row g, cols 2tig,2tig+1), c2,c3 = (row g+8) within n-tile nt.
// s-loop unroll bounded to 2 to keep SASS footprint / compile time sane.
template<int KT>
__device__ __forceinline__ void warp_gemm(const float* __restrict__ Xs, int xp,
                                          const float* __restrict__ Wt, int wp,
                                          int m0, float (&acc)[16][4]) {
    const int l = threadIdx.x & 31, g = l >> 2, tig = l & 3;
    const float* xr0 = Xs + (m0 + g) * xp + tig;
    const float* xr1 = xr0 + 8 * xp;
    const float* wbase = Wt + g * wp + tig;
#pragma unroll 2
    for (int s = 0; s < KT; s++) {
        const int k0 = 8 * s;
        float a0 = xr0[k0], a1 = xr1[k0], a2 = xr0[k0 + 4], a3 = xr1[k0 + 4];
#pragma unroll
        for (int nt = 0; nt < 16; nt++) {
            const float* wr = wbase + nt * 8 * wp;
            float b0 = wr[k0], b1 = wr[k0 + 4];
            asm volatile(
                "mma.sync.aligned.m16n8k8.row.col.f32.tf32.tf32.f32 "
                "{%0,%1,%2,%3}, {%4,%5,%6,%7}, {%8,%9}, {%0,%1,%2,%3};"
                : "+f"(acc[nt][0]), "+f"(acc[nt][1]), "+f"(acc[nt][2]), "+f"(acc[nt][3])
                : "r"(__float_as_uint(a0)), "r"(__float_as_uint(a1)),
                  "r"(__float_as_uint(a2)), "r"(__float_as_uint(a3)),
                  "r"(__float_as_uint(b0)), "r"(__float_as_uint(b1)));
        }
    }
}

// ---------------- BN folding (parallel) ----------------
__global__ void fold_kernel(const float* __restrict__ g, const float* __restrict__ b,
                            const float* __restrict__ m, const float* __restrict__ v,
                            const float* __restrict__ W, const float* __restrict__ bb,
                            int K, int which) {
    float* Wo; float* Bo;
    if      (which == 0) { Wo = g_bmW1; Bo = g_bmB1; }
    else if (which == 1) { Wo = g_bmW2; Bo = g_bmB2; }
    else if (which == 2) { Wo = g_upW1; Bo = g_upB1; }
    else                 { Wo = g_upW2; Bo = g_upB2; }
    __shared__ float red[256];
    int j = blockIdx.x, tid = threadIdx.x;
    float acc = 0.f;
    for (int i = tid; i < K; i += 256) {
        float s = g[i] * rsqrtf(v[i] + EPSbn);
        float t = b[i] - m[i] * s;
        float w = W[i * HH + j];
        Wo[i * HH + j] = s * w;
        acc += t * w;
    }
    red[tid] = acc; __syncthreads();
    for (int o = 128; o > 0; o >>= 1) { if (tid < o) red[tid] += red[tid + o]; __syncthreads(); }
    if (tid == 0) Bo[j] = bb[j] + red[0];
}

__global__ void zero_kernel() {
    int i = blockIdx.x * blockDim.x + threadIdx.x;
    if (i < NN * HH / 4) ((float4*)g_agg)[i] = make_float4(0.f, 0.f, 0.f, 0.f);
    if (i < NN / 4)      ((float4*)g_cnt)[i] = make_float4(0.f, 0.f, 0.f, 0.f);
}

__global__ void deg_kernel(const int* __restrict__ src) {
    int i = blockIdx.x * blockDim.x + threadIdx.x;
    if (i < NE) atomicAdd(&g_cnt[src[i]], 1.0f);
}

// ============== node base-message MLP: two fused 128x128 GEMMs ==============
// smem floats: W1t 128*132 | W2t 128*132 | Xs 128*132 | b1 128 | b2 128
#define SMN_TOT ((3 * 128 * 132 + 256) * 4)
__global__ void __launch_bounds__(256, 1)
node_tc(const float* __restrict__ X, int tiles) {
    extern __shared__ float sm[];
    float* W1t = sm;
    float* W2t = W1t + 128 * 132;
    float* Xs  = W2t + 128 * 132;
    float* b1s = Xs + 128 * 132;
    float* b2s = b1s + 128;
    const int tid = threadIdx.x, wid = tid >> 5, l = tid & 31, g = l >> 2, tig = l & 3;
    const int m0 = wid * 16;
    for (int i = tid; i < 128 * 128; i += 256) {
        int k = i >> 7, n = i & 127;
        W1t[n * 132 + k] = to_tf32(g_bmW1[i]);
        W2t[n * 132 + k] = to_tf32(g_bmW2[i]);
    }
    if (tid < 128) { b1s[tid] = g_bmB1[tid]; b2s[tid] = g_bmB2[tid]; }
    __syncthreads();
    for (int t = blockIdx.x; t < tiles; t += gridDim.x) {
        size_t base = (size_t)t * 128;
        for (int i = tid; i < 128 * 32; i += 256) {
            int r = i >> 5, kq = (i & 31) * 4;
            float4 v = *(const float4*)(X + (base + r) * 128 + kq);
            float* p = Xs + r * 132 + kq;
            p[0] = to_tf32(v.x); p[1] = to_tf32(v.y); p[2] = to_tf32(v.z); p[3] = to_tf32(v.w);
        }
        __syncthreads();
        float acc[16][4] = {};
        warp_gemm<16>(Xs, 132, W1t, 132, m0, acc);
        __syncthreads();
#pragma unroll
        for (int nt = 0; nt < 16; nt++) {
            int cn = nt * 8 + 2 * tig;
            Xs[(m0 + g) * 132 + cn]         = to_tf32(gelu_f(acc[nt][0] + b1s[cn]));
            Xs[(m0 + g) * 132 + cn + 1]     = to_tf32(gelu_f(acc[nt][1] + b1s[cn + 1]));
            Xs[(m0 + g + 8) * 132 + cn]     = to_tf32(gelu_f(acc[nt][2] + b1s[cn]));
            Xs[(m0 + g + 8) * 132 + cn + 1] = to_tf32(gelu_f(acc[nt][3] + b1s[cn + 1]));
        }
        __syncthreads();
        float acc2[16][4] = {};
        warp_gemm<16>(Xs, 132, W2t, 132, m0, acc2);
#pragma unroll
        for (int nt = 0; nt < 16; nt++) {
            int cn = nt * 8 + 2 * tig;
            float2 v0 = make_float2(gelu_f(acc2[nt][0] + b2s[cn]), gelu_f(acc2[nt][1] + b2s[cn + 1]));
            float2 v1 = make_float2(gelu_f(acc2[nt][2] + b2s[cn]), gelu_f(acc2[nt][3] + b2s[cn + 1]));
            *(float2*)(g_hmsg + (base + m0 + g) * 128 + cn)     = v0;
            *(float2*)(g_hmsg + (base + m0 + g + 8) * 128 + cn) = v1;
        }
        __syncthreads();
    }
}

// ============== edge kernel: e-MLP (K=64, K=128) + gather + atomic scatter ==============
// floats: W1t 128*68 | EAs 128*68 | W2t 128*132 | H1s 128*132 | b1 128 | b2 128, then ints src/dst
#define SME_FLOATS (2 * 128 * 68 + 2 * 128 * 132 + 256)
#define SME_TOT (SME_FLOATS * 4 + 256 * 4)
__global__ void __launch_bounds__(256, 1)
edge_tc(const float* __restrict__ EA,
        const float* __restrict__ W1, const float* __restrict__ B1,
        const float* __restrict__ W2, const float* __restrict__ B2,
        const int* __restrict__ esrc, const int* __restrict__ edst, int tiles) {
    extern __shared__ float sm[];
    float* W1t = sm;                       // 128 x 68
    float* EAs = W1t + 128 * 68;           // 128 x 68
    float* W2t = EAs + 128 * 68;           // 128 x 132
    float* H1s = W2t + 128 * 132;          // 128 x 132
    float* b1s = H1s + 128 * 132;
    float* b2s = b1s + 128;
    int* src_s = (int*)(b2s + 128);
    int* dst_s = src_s + 128;
    const int tid = threadIdx.x, wid = tid >> 5, l = tid & 31, g = l >> 2, tig = l & 3;
    const int m0 = wid * 16;
    for (int i = tid; i < 64 * 128; i += 256) { int k = i >> 7, n = i & 127; W1t[n * 68 + k] = to_tf32(W1[i]); }
    for (int i = tid; i < 128 * 128; i += 256) { int k = i >> 7, n = i & 127; W2t[n * 132 + k] = to_tf32(W2[i]); }
    if (tid < 128) { b1s[tid] = B1[tid]; b2s[tid] = B2[tid]; }
    __syncthreads();
    for (int t = blockIdx.x; t < tiles; t += gridDim.x) {
        size_t base = (size_t)t * 128;
        for (int i = tid; i < 128 * 16; i += 256) {
            int r = i >> 4, kq = (i & 15) * 4;
            float4 v = *(const float4*)(EA + (base + r) * 64 + kq);
            float* p = EAs + r * 68 + kq;
            p[0] = to_tf32(v.x); p[1] = to_tf32(v.y); p[2] = to_tf32(v.z); p[3] = to_tf32(v.w);
        }
        if (tid < 128) src_s[tid] = esrc[base + tid];
        else           dst_s[tid - 128] = edst[base + tid - 128];
        __syncthreads();
        float acc[16][4] = {};
        warp_gemm<8>(EAs, 68, W1t, 68, m0, acc);
#pragma unroll
        for (int nt = 0; nt < 16; nt++) {
            int cn = nt * 8 + 2 * tig;
            H1s[(m0 + g) * 132 + cn]         = to_tf32(gelu_f(acc[nt][0] + b1s[cn]));
            H1s[(m0 + g) * 132 + cn + 1]     = to_tf32(gelu_f(acc[nt][1] + b1s[cn + 1]));
            H1s[(m0 + g + 8) * 132 + cn]     = to_tf32(gelu_f(acc[nt][2] + b1s[cn]));
            H1s[(m0 + g + 8) * 132 + cn + 1] = to_tf32(gelu_f(acc[nt][3] + b1s[cn + 1]));
        }
        __syncthreads();
        float acc2[16][4] = {};
        warp_gemm<16>(H1s, 132, W2t, 132, m0, acc2);
        // epilogue: msg = gelu(e)*hmsg[dst], atomic into agg[src]
        {
            int r0 = m0 + g, r1 = m0 + g + 8;
            int dd0 = dst_s[r0], ss0 = src_s[r0];
            int dd1 = dst_s[r1], ss1 = src_s[r1];
            const float* hp0 = g_hmsg + (size_t)dd0 * 128;
            const float* hp1 = g_hmsg + (size_t)dd1 * 128;
            float* ap0 = g_agg + (size_t)ss0 * 128;
            float* ap1 = g_agg + (size_t)ss1 * 128;
#pragma unroll 4
            for (int nt = 0; nt < 16; nt++) {
                int cn = nt * 8 + 2 * tig;
                float2 h0 = *(const float2*)(hp0 + cn);
                float2 h1 = *(const float2*)(hp1 + cn);
                atomicAdd(ap0 + cn,     gelu_f(acc2[nt][0] + b2s[cn])     * h0.x);
                atomicAdd(ap0 + cn + 1, gelu_f(acc2[nt][1] + b2s[cn + 1]) * h0.y);
                atomicAdd(ap1 + cn,     gelu_f(acc2[nt][2] + b2s[cn])     * h1.x);
                atomicAdd(ap1 + cn + 1, gelu_f(acc2[nt][3] + b2s[cn + 1]) * h1.y);
            }
        }
        __syncthreads();
    }
}

// ============== update stage 1: [node_x | agg/cnt] @ upW1 (K=256) ==============
// floats: W1t 128*260 | Xs 128*132 | b1 128
#define SMU_TOT ((128 * 260 + 128 * 132 + 128) * 4)
__global__ void __launch_bounds__(256, 1)
up1_tc(const float* __restrict__ X, int tiles) {
    extern __shared__ float sm[];
    float* W1t = sm;                 // [n=128][k=256] pitch 260
    float* Xs  = W1t + 128 * 260;    // 128 x 132
    float* b1s = Xs + 128 * 132;
    const int tid = threadIdx.x, wid = tid >> 5, l = tid & 31, g = l >> 2, tig = l & 3;
    const int m0 = wid * 16;
    for (int i = tid; i < 256 * 128; i += 256) { int k = i >> 7, n = i & 127; W1t[n * 260 + k] = to_tf32(g_upW1[i]); }
    if (tid < 128) b1s[tid] = g_upB1[tid];
    __syncthreads();
    for (int t = blockIdx.x; t < tiles; t += gridDim.x) {
        size_t base = (size_t)t * 128;
        // K half 1: node_x
        for (int i = tid; i < 128 * 32; i += 256) {
            int r = i >> 5, kq = (i & 31) * 4;
            float4 v = *(const float4*)(X + (base + r) * 128 + kq);
            float* p = Xs + r * 132 + kq;
            p[0] = to_tf32(v.x); p[1] = to_tf32(v.y); p[2] = to_tf32(v.z); p[3] = to_tf32(v.w);
        }
        __syncthreads();
        float acc[16][4] = {};
        warp_gemm<16>(Xs, 132, W1t, 260, m0, acc);
        __syncthreads();
        // K half 2: agg / max(cnt,1)
        for (int i = tid; i < 128 * 32; i += 256) {
            int r = i >> 5, kq = (i & 31) * 4;
            float sc = 1.0f / fmaxf(g_cnt[base + r], 1.0f);
            float4 v = *(const float4*)(g_agg + (base + r) * 128 + kq);
            float* p = Xs + r * 132 + kq;
            p[0] = to_tf32(v.x * sc); p[1] = to_tf32(v.y * sc);
            p[2] = to_tf32(v.z * sc); p[3] = to_tf32(v.w * sc);
        }
        __syncthreads();
        warp_gemm<16>(Xs, 132, W1t + 128, 260, m0, acc);
#pragma unroll
        for (int nt = 0; nt < 16; nt++) {
            int cn = nt * 8 + 2 * tig;
            float2 v0 = make_float2(gelu_f(acc[nt][0] + b1s[cn]), gelu_f(acc[nt][1] + b1s[cn + 1]));
            float2 v1 = make_float2(gelu_f(acc[nt][2] + b1s[cn]), gelu_f(acc[nt][3] + b1s[cn + 1]));
            *(float2*)(g_u1 + (base + m0 + g) * 128 + cn)     = v0;
            *(float2*)(g_u1 + (base + m0 + g + 8) * 128 + cn) = v1;
        }
        __syncthreads();
    }
}

// ============== update stage 2: g_u1 @ upW2 -> gelu -> out ==============
#define SMM_TOT ((2 * 128 * 132 + 128) * 4)
__global__ void __launch_bounds__(256, 1)
mlp1_tc(float* __restrict__ out, int tiles) {
    extern __shared__ float sm[];
    float* Wt = sm;
    float* Xs = Wt + 128 * 132;
    float* bs = Xs + 128 * 132;
    const int tid = threadIdx.x, wid = tid >> 5, l = tid & 31, g = l >> 2, tig = l & 3;
    const int m0 = wid * 16;
    for (int i = tid; i < 128 * 128; i += 256) { int k = i >> 7, n = i & 127; Wt[n * 132 + k] = to_tf32(g_upW2[i]); }
    if (tid < 128) bs[tid] = g_upB2[tid];
    __syncthreads();
    for (int t = blockIdx.x; t < tiles; t += gridDim.x) {
        size_t base = (size_t)t * 128;
        for (int i = tid; i < 128 * 32; i += 256) {
            int r = i >> 5, kq = (i & 31) * 4;
            float4 v = *(const float4*)(g_u1 + (base + r) * 128 + kq);
            float* p = Xs + r * 132 + kq;
            p[0] = to_tf32(v.x); p[1] = to_tf32(v.y); p[2] = to_tf32(v.z); p[3] = to_tf32(v.w);
        }
        __syncthreads();
        float acc[16][4] = {};
        warp_gemm<16>(Xs, 132, Wt, 132, m0, acc);
#pragma unroll
        for (int nt = 0; nt < 16; nt++) {
            int cn = nt * 8 + 2 * tig;
            float2 v0 = make_float2(gelu_f(acc[nt][0] + bs[cn]), gelu_f(acc[nt][1] + bs[cn + 1]));
            float2 v1 = make_float2(gelu_f(acc[nt][2] + bs[cn]), gelu_f(acc[nt][3] + bs[cn + 1]));
            *(float2*)(out + (base + m0 + g) * 128 + cn)     = v0;
            *(float2*)(out + (base + m0 + g + 8) * 128 + cn) = v1;
        }
        __syncthreads();
    }
}

// ---------------- launch ----------------
extern "C" void kernel_launch(void* const* d_in, const int* in_sizes, int n_in,
                              void* d_out, int out_size) {
    const float* node_x = (const float*)d_in[0];
    const float* eattr  = (const float*)d_in[1];
    const float* bm_g1 = (const float*)d_in[2];
    const float* bm_b1 = (const float*)d_in[3];
    const float* bm_m1 = (const float*)d_in[4];
    const float* bm_v1 = (const float*)d_in[5];
    const float* bm_w1 = (const float*)d_in[6];
    const float* bm_bb1= (const float*)d_in[7];
    const float* bm_g2 = (const float*)d_in[8];
    const float* bm_b2 = (const float*)d_in[9];
    const float* bm_m2 = (const float*)d_in[10];
    const float* bm_v2 = (const float*)d_in[11];
    const float* bm_w2 = (const float*)d_in[12];
    const float* bm_bb2= (const float*)d_in[13];
    const float* et_w1 = (const float*)d_in[14];
    const float* et_b1 = (const float*)d_in[15];
    const float* et_w2 = (const float*)d_in[16];
    const float* et_b2 = (const float*)d_in[17];
    const float* up_g1 = (const float*)d_in[18];
    const float* up_b1 = (const float*)d_in[19];
    const float* up_m1 = (const float*)d_in[20];
    const float* up_v1 = (const float*)d_in[21];
    const float* up_w1 = (const float*)d_in[22];
    const float* up_bb1= (const float*)d_in[23];
    const float* up_g2 = (const float*)d_in[24];
    const float* up_b2 = (const float*)d_in[25];
    const float* up_m2 = (const float*)d_in[26];
    const float* up_v2 = (const float*)d_in[27];
    const float* up_w2 = (const float*)d_in[28];
    const float* up_bb2= (const float*)d_in[29];
    const int*   esrc  = (const int*)d_in[30];
    const int*   edst  = (const int*)d_in[31];
    float* out = (float*)d_out;

    cudaFuncSetAttribute(node_tc, cudaFuncAttributeMaxDynamicSharedMemorySize, SMN_TOT);
    cudaFuncSetAttribute(edge_tc, cudaFuncAttributeMaxDynamicSharedMemorySize, SME_TOT);
    cudaFuncSetAttribute(up1_tc,  cudaFuncAttributeMaxDynamicSharedMemorySize, SMU_TOT);
    cudaFuncSetAttribute(mlp1_tc, cudaFuncAttributeMaxDynamicSharedMemorySize, SMM_TOT);

    fold_kernel<<<128, 256>>>(bm_g1, bm_b1, bm_m1, bm_v1, bm_w1, bm_bb1, DN, 0);
    fold_kernel<<<128, 256>>>(bm_g2, bm_b2, bm_m2, bm_v2, bm_w2, bm_bb2, HH, 1);
    fold_kernel<<<128, 256>>>(up_g1, up_b1, up_m1, up_v1, up_w1, up_bb1, DC, 2);
    fold_kernel<<<128, 256>>>(up_g2, up_b2, up_m2, up_v2, up_w2, up_bb2, HH, 3);

    zero_kernel<<<(NN * HH / 4 + 255) / 256, 256>>>();
    deg_kernel<<<(NE + 255) / 256, 256>>>(esrc);

    node_tc<<<148, 256, SMN_TOT>>>(node_x, NN / 128);
    edge_tc<<<148, 256, SME_TOT>>>(eattr, et_w1, et_b1, et_w2, et_b2, esrc, edst, NE / 128);
    up1_tc<<<148, 256, SMU_TOT>>>(node_x, NN / 128);
    mlp1_tc<<<148, 256, SMM_TOT>>>(out, NN / 128);
}

// round 10
// speedup vs baseline: 2.5319x; 1.2506x over previous
#include <cuda_runtime.h>
#include <math.h>
#include <stdint.h>

#define NN 65536
#define NE 524288
#define DN 128
#define DE 64
#define HH 128
#define DC (DN + HH)
#define EPSbn 1e-3f

// ---------------- scratch ----------------
__device__ float g_hmsg[(size_t)NN * HH];
__device__ float g_agg [(size_t)NN * HH];
__device__ float g_u1  [(size_t)NN * HH];
__device__ float g_cnt [NN];

__device__ float g_bmW1[DN * HH]; __device__ float g_bmB1[HH];
__device__ float g_bmW2[HH * HH]; __device__ float g_bmB2[HH];
__device__ float g_upW1[DC * HH]; __device__ float g_upB1[HH];
__device__ float g_upW2[HH * HH]; __device__ float g_upB2[HH];

// fast exact-enough gelu: 0.5*x*(1+erf(x/sqrt2)), erf via A&S 7.1.26 (|err|<1.5e-7)
__device__ __forceinline__ float gelu_f(float x) {
    float z  = x * 0.70710678118654752f;
    float az = fabsf(z);
    float t;
    asm("rcp.approx.f32 %0, %1;" : "=f"(t) : "f"(fmaf(0.3275911f, az, 1.0f)));
    float p = fmaf(1.061405429f, t, -1.453152027f);
    p = fmaf(p, t, 1.421413741f);
    p = fmaf(p, t, -0.284496736f);
    p = fmaf(p, t, 0.254829592f);
    p = p * t;
    float e = __expf(-z * z);
    float erfa = fmaf(-p, e, 1.0f);      // erf(|z|)
    float erfz = copysignf(erfa, z);
    return 0.5f * x * (1.0f + erfz);
}

// tf32 round: destination must be .b32 per PTX spec
__device__ __forceinline__ float to_tf32(float x) {
    uint32_t r; asm("cvt.rna.tf32.f32 %0, %1;" : "=r"(r) : "f"(x));
    return __uint_as_float(r);
}

// ---------------- warp-level tf32 MMA GEMM ----------------
// Warp computes D[16 x 128] += X[16 x 8*KT] @ Wt^T, operands in smem.
// Xs: row-major [row][k], pitch xp (pad so xp mod 32 == 4)
// Wt: [n][k] (transposed weight), pitch wp (pad so wp mod 32 == 4)
// acc[nt][0..3]: c0,c1 = (row g, cols 2tig,2tig+1), c2,c3 = (row g+8) within n-tile nt.
// s-loop unroll bounded to 2 to keep SASS footprint / compile time sane.
template<int KT>
__device__ __forceinline__ void warp_gemm(const float* __restrict__ Xs, int xp,
                                          const float* __restrict__ Wt, int wp,
                                          int m0, float (&acc)[16][4]) {
    const int l = threadIdx.x & 31, g = l >> 2, tig = l & 3;
    const float* xr0 = Xs + (m0 + g) * xp + tig;
    const float* xr1 = xr0 + 8 * xp;
    const float* wbase = Wt + g * wp + tig;
#pragma unroll 2
    for (int s = 0; s < KT; s++) {
        const int k0 = 8 * s;
        float a0 = xr0[k0], a1 = xr1[k0], a2 = xr0[k0 + 4], a3 = xr1[k0 + 4];
#pragma unroll
        for (int nt = 0; nt < 16; nt++) {
            const float* wr = wbase + nt * 8 * wp;
            float b0 = wr[k0], b1 = wr[k0 + 4];
            asm volatile(
                "mma.sync.aligned.m16n8k8.row.col.f32.tf32.tf32.f32 "
                "{%0,%1,%2,%3}, {%4,%5,%6,%7}, {%8,%9}, {%0,%1,%2,%3};"
                : "+f"(acc[nt][0]), "+f"(acc[nt][1]), "+f"(acc[nt][2]), "+f"(acc[nt][3])
                : "r"(__float_as_uint(a0)), "r"(__float_as_uint(a1)),
                  "r"(__float_as_uint(a2)), "r"(__float_as_uint(a3)),
                  "r"(__float_as_uint(b0)), "r"(__float_as_uint(b1)));
        }
    }
}

// ---------------- BN folding (parallel) ----------------
__global__ void fold_kernel(const float* __restrict__ g, const float* __restrict__ b,
                            const float* __restrict__ m, const float* __restrict__ v,
                            const float* __restrict__ W, const float* __restrict__ bb,
                            int K, int which) {
    float* Wo; float* Bo;
    if      (which == 0) { Wo = g_bmW1; Bo = g_bmB1; }
    else if (which == 1) { Wo = g_bmW2; Bo = g_bmB2; }
    else if (which == 2) { Wo = g_upW1; Bo = g_upB1; }
    else                 { Wo = g_upW2; Bo = g_upB2; }
    __shared__ float red[256];
    int j = blockIdx.x, tid = threadIdx.x;
    float acc = 0.f;
    for (int i = tid; i < K; i += 256) {
        float s = g[i] * rsqrtf(v[i] + EPSbn);
        float t = b[i] - m[i] * s;
        float w = W[i * HH + j];
        Wo[i * HH + j] = s * w;
        acc += t * w;
    }
    red[tid] = acc; __syncthreads();
    for (int o = 128; o > 0; o >>= 1) { if (tid < o) red[tid] += red[tid + o]; __syncthreads(); }
    if (tid == 0) Bo[j] = bb[j] + red[0];
}

__global__ void zero_kernel() {
    int i = blockIdx.x * blockDim.x + threadIdx.x;
    if (i < NN * HH / 4) ((float4*)g_agg)[i] = make_float4(0.f, 0.f, 0.f, 0.f);
    if (i < NN / 4)      ((float4*)g_cnt)[i] = make_float4(0.f, 0.f, 0.f, 0.f);
}

__global__ void deg_kernel(const int* __restrict__ src) {
    int i = blockIdx.x * blockDim.x + threadIdx.x;
    if (i < NE) atomicAdd(&g_cnt[src[i]], 1.0f);
}

// ============== node base-message MLP: two fused 128x128 GEMMs ==============
// smem floats: W1t 128*132 | W2t 128*132 | Xs 128*132 | b1 128 | b2 128
#define SMN_TOT ((3 * 128 * 132 + 256) * 4)
__global__ void __launch_bounds__(256, 1)
node_tc(const float* __restrict__ X, int tiles) {
    extern __shared__ float sm[];
    float* W1t = sm;
    float* W2t = W1t + 128 * 132;
    float* Xs  = W2t + 128 * 132;
    float* b1s = Xs + 128 * 132;
    float* b2s = b1s + 128;
    const int tid = threadIdx.x, wid = tid >> 5, l = tid & 31, g = l >> 2, tig = l & 3;
    const int m0 = wid * 16;
    for (int i = tid; i < 128 * 128; i += 256) {
        int k = i >> 7, n = i & 127;
        W1t[n * 132 + k] = to_tf32(g_bmW1[i]);
        W2t[n * 132 + k] = to_tf32(g_bmW2[i]);
    }
    if (tid < 128) { b1s[tid] = g_bmB1[tid]; b2s[tid] = g_bmB2[tid]; }
    __syncthreads();
    for (int t = blockIdx.x; t < tiles; t += gridDim.x) {
        size_t base = (size_t)t * 128;
        for (int i = tid; i < 128 * 32; i += 256) {
            int r = i >> 5, kq = (i & 31) * 4;
            float4 v = *(const float4*)(X + (base + r) * 128 + kq);
            float* p = Xs + r * 132 + kq;
            p[0] = to_tf32(v.x); p[1] = to_tf32(v.y); p[2] = to_tf32(v.z); p[3] = to_tf32(v.w);
        }
        __syncthreads();
        float acc[16][4] = {};
        warp_gemm<16>(Xs, 132, W1t, 132, m0, acc);
        __syncthreads();
#pragma unroll
        for (int nt = 0; nt < 16; nt++) {
            int cn = nt * 8 + 2 * tig;
            Xs[(m0 + g) * 132 + cn]         = to_tf32(gelu_f(acc[nt][0] + b1s[cn]));
            Xs[(m0 + g) * 132 + cn + 1]     = to_tf32(gelu_f(acc[nt][1] + b1s[cn + 1]));
            Xs[(m0 + g + 8) * 132 + cn]     = to_tf32(gelu_f(acc[nt][2] + b1s[cn]));
            Xs[(m0 + g + 8) * 132 + cn + 1] = to_tf32(gelu_f(acc[nt][3] + b1s[cn + 1]));
        }
        __syncthreads();
        float acc2[16][4] = {};
        warp_gemm<16>(Xs, 132, W2t, 132, m0, acc2);
#pragma unroll
        for (int nt = 0; nt < 16; nt++) {
            int cn = nt * 8 + 2 * tig;
            float2 v0 = make_float2(gelu_f(acc2[nt][0] + b2s[cn]), gelu_f(acc2[nt][1] + b2s[cn + 1]));
            float2 v1 = make_float2(gelu_f(acc2[nt][2] + b2s[cn]), gelu_f(acc2[nt][3] + b2s[cn + 1]));
            *(float2*)(g_hmsg + (base + m0 + g) * 128 + cn)     = v0;
            *(float2*)(g_hmsg + (base + m0 + g + 8) * 128 + cn) = v1;
        }
        __syncthreads();
    }
}

// ============== edge kernel: e-MLP (K=64, K=128) + gather + atomic scatter ==============
// floats: W1t 128*68 | EAs 128*68 | W2t 128*132 | H1s 128*132 | b1 128 | b2 128, then ints src/dst
#define SME_FLOATS (2 * 128 * 68 + 2 * 128 * 132 + 256)
#define SME_TOT (SME_FLOATS * 4 + 256 * 4)
__global__ void __launch_bounds__(256, 1)
edge_tc(const float* __restrict__ EA,
        const float* __restrict__ W1, const float* __restrict__ B1,
        const float* __restrict__ W2, const float* __restrict__ B2,
        const int* __restrict__ esrc, const int* __restrict__ edst, int tiles) {
    extern __shared__ float sm[];
    float* W1t = sm;                       // 128 x 68
    float* EAs = W1t + 128 * 68;           // 128 x 68
    float* W2t = EAs + 128 * 68;           // 128 x 132
    float* H1s = W2t + 128 * 132;          // 128 x 132
    float* b1s = H1s + 128 * 132;
    float* b2s = b1s + 128;
    int* src_s = (int*)(b2s + 128);
    int* dst_s = src_s + 128;
    const int tid = threadIdx.x, wid = tid >> 5, l = tid & 31, g = l >> 2, tig = l & 3;
    const int m0 = wid * 16;
    for (int i = tid; i < 64 * 128; i += 256) { int k = i >> 7, n = i & 127; W1t[n * 68 + k] = to_tf32(W1[i]); }
    for (int i = tid; i < 128 * 128; i += 256) { int k = i >> 7, n = i & 127; W2t[n * 132 + k] = to_tf32(W2[i]); }
    if (tid < 128) { b1s[tid] = B1[tid]; b2s[tid] = B2[tid]; }
    __syncthreads();
    for (int t = blockIdx.x; t < tiles; t += gridDim.x) {
        size_t base = (size_t)t * 128;
        for (int i = tid; i < 128 * 16; i += 256) {
            int r = i >> 4, kq = (i & 15) * 4;
            float4 v = *(const float4*)(EA + (base + r) * 64 + kq);
            float* p = EAs + r * 68 + kq;
            p[0] = to_tf32(v.x); p[1] = to_tf32(v.y); p[2] = to_tf32(v.z); p[3] = to_tf32(v.w);
        }
        if (tid < 128) src_s[tid] = esrc[base + tid];
        else           dst_s[tid - 128] = edst[base + tid - 128];
        __syncthreads();
        float acc[16][4] = {};
        warp_gemm<8>(EAs, 68, W1t, 68, m0, acc);
#pragma unroll
        for (int nt = 0; nt < 16; nt++) {
            int cn = nt * 8 + 2 * tig;
            H1s[(m0 + g) * 132 + cn]         = to_tf32(gelu_f(acc[nt][0] + b1s[cn]));
            H1s[(m0 + g) * 132 + cn + 1]     = to_tf32(gelu_f(acc[nt][1] + b1s[cn + 1]));
            H1s[(m0 + g + 8) * 132 + cn]     = to_tf32(gelu_f(acc[nt][2] + b1s[cn]));
            H1s[(m0 + g + 8) * 132 + cn + 1] = to_tf32(gelu_f(acc[nt][3] + b1s[cn + 1]));
        }
        __syncthreads();
        float acc2[16][4] = {};
        warp_gemm<16>(H1s, 132, W2t, 132, m0, acc2);
        // epilogue: msg = gelu(e)*hmsg[dst], atomic into agg[src]
        {
            int r0 = m0 + g, r1 = m0 + g + 8;
            int dd0 = dst_s[r0], ss0 = src_s[r0];
            int dd1 = dst_s[r1], ss1 = src_s[r1];
            const float* hp0 = g_hmsg + (size_t)dd0 * 128;
            const float* hp1 = g_hmsg + (size_t)dd1 * 128;
            float* ap0 = g_agg + (size_t)ss0 * 128;
            float* ap1 = g_agg + (size_t)ss1 * 128;
#pragma unroll 4
            for (int nt = 0; nt < 16; nt++) {
                int cn = nt * 8 + 2 * tig;
                float2 h0 = *(const float2*)(hp0 + cn);
                float2 h1 = *(const float2*)(hp1 + cn);
                atomicAdd(ap0 + cn,     gelu_f(acc2[nt][0] + b2s[cn])     * h0.x);
                atomicAdd(ap0 + cn + 1, gelu_f(acc2[nt][1] + b2s[cn + 1]) * h0.y);
                atomicAdd(ap1 + cn,     gelu_f(acc2[nt][2] + b2s[cn])     * h1.x);
                atomicAdd(ap1 + cn + 1, gelu_f(acc2[nt][3] + b2s[cn + 1]) * h1.y);
            }
        }
        __syncthreads();
    }
}

// ============== update stage 1: [node_x | agg/cnt] @ upW1 (K=256) ==============
// floats: W1t 128*260 | Xs 128*132 | b1 128
#define SMU_TOT ((128 * 260 + 128 * 132 + 128) * 4)
__global__ void __launch_bounds__(256, 1)
up1_tc(const float* __restrict__ X, int tiles) {
    extern __shared__ float sm[];
    float* W1t = sm;                 // [n=128][k=256] pitch 260
    float* Xs  = W1t + 128 * 260;    // 128 x 132
    float* b1s = Xs + 128 * 132;
    const int tid = threadIdx.x, wid = tid >> 5, l = tid & 31, g = l >> 2, tig = l & 3;
    const int m0 = wid * 16;
    for (int i = tid; i < 256 * 128; i += 256) { int k = i >> 7, n = i & 127; W1t[n * 260 + k] = to_tf32(g_upW1[i]); }
    if (tid < 128) b1s[tid] = g_upB1[tid];
    __syncthreads();
    for (int t = blockIdx.x; t < tiles; t += gridDim.x) {
        size_t base = (size_t)t * 128;
        // K half 1: node_x
        for (int i = tid; i < 128 * 32; i += 256) {
            int r = i >> 5, kq = (i & 31) * 4;
            float4 v = *(const float4*)(X + (base + r) * 128 + kq);
            float* p = Xs + r * 132 + kq;
            p[0] = to_tf32(v.x); p[1] = to_tf32(v.y); p[2] = to_tf32(v.z); p[3] = to_tf32(v.w);
        }
        __syncthreads();
        float acc[16][4] = {};
        warp_gemm<16>(Xs, 132, W1t, 260, m0, acc);
        __syncthreads();
        // K half 2: agg / max(cnt,1)
        for (int i = tid; i < 128 * 32; i += 256) {
            int r = i >> 5, kq = (i & 31) * 4;
            float sc = 1.0f / fmaxf(g_cnt[base + r], 1.0f);
            float4 v = *(const float4*)(g_agg + (base + r) * 128 + kq);
            float* p = Xs + r * 132 + kq;
            p[0] = to_tf32(v.x * sc); p[1] = to_tf32(v.y * sc);
            p[2] = to_tf32(v.z * sc); p[3] = to_tf32(v.w * sc);
        }
        __syncthreads();
        warp_gemm<16>(Xs, 132, W1t + 128, 260, m0, acc);
#pragma unroll
        for (int nt = 0; nt < 16; nt++) {
            int cn = nt * 8 + 2 * tig;
            float2 v0 = make_float2(gelu_f(acc[nt][0] + b1s[cn]), gelu_f(acc[nt][1] + b1s[cn + 1]));
            float2 v1 = make_float2(gelu_f(acc[nt][2] + b1s[cn]), gelu_f(acc[nt][3] + b1s[cn + 1]));
            *(float2*)(g_u1 + (base + m0 + g) * 128 + cn)     = v0;
            *(float2*)(g_u1 + (base + m0 + g + 8) * 128 + cn) = v1;
        }
        __syncthreads();
    }
}

// ============== update stage 2: g_u1 @ upW2 -> gelu -> out ==============
#define SMM_TOT ((2 * 128 * 132 + 128) * 4)
__global__ void __launch_bounds__(256, 1)
mlp1_tc(float* __restrict__ out, int tiles) {
    extern __shared__ float sm[];
    float* Wt = sm;
    float* Xs = Wt + 128 * 132;
    float* bs = Xs + 128 * 132;
    const int tid = threadIdx.x, wid = tid >> 5, l = tid & 31, g = l >> 2, tig = l & 3;
    const int m0 = wid * 16;
    for (int i = tid; i < 128 * 128; i += 256) { int k = i >> 7, n = i & 127; Wt[n * 132 + k] = to_tf32(g_upW2[i]); }
    if (tid < 128) bs[tid] = g_upB2[tid];
    __syncthreads();
    for (int t = blockIdx.x; t < tiles; t += gridDim.x) {
        size_t base = (size_t)t * 128;
        for (int i = tid; i < 128 * 32; i += 256) {
            int r = i >> 5, kq = (i & 31) * 4;
            float4 v = *(const float4*)(g_u1 + (base + r) * 128 + kq);
            float* p = Xs + r * 132 + kq;
            p[0] = to_tf32(v.x); p[1] = to_tf32(v.y); p[2] = to_tf32(v.z); p[3] = to_tf32(v.w);
        }
        __syncthreads();
        float acc[16][4] = {};
        warp_gemm<16>(Xs, 132, Wt, 132, m0, acc);
#pragma unroll
        for (int nt = 0; nt < 16; nt++) {
            int cn = nt * 8 + 2 * tig;
            float2 v0 = make_float2(gelu_f(acc[nt][0] + bs[cn]), gelu_f(acc[nt][1] + bs[cn + 1]));
            float2 v1 = make_float2(gelu_f(acc[nt][2] + bs[cn]), gelu_f(acc[nt][3] + bs[cn + 1]));
            *(float2*)(out + (base + m0 + g) * 128 + cn)     = v0;
            *(float2*)(out + (base + m0 + g + 8) * 128 + cn) = v1;
        }
        __syncthreads();
    }
}

// ---------------- launch ----------------
extern "C" void kernel_launch(void* const* d_in, const int* in_sizes, int n_in,
                              void* d_out, int out_size) {
    const float* node_x = (const float*)d_in[0];
    const float* eattr  = (const float*)d_in[1];
    const float* bm_g1 = (const float*)d_in[2];
    const float* bm_b1 = (const float*)d_in[3];
    const float* bm_m1 = (const float*)d_in[4];
    const float* bm_v1 = (const float*)d_in[5];
    const float* bm_w1 = (const float*)d_in[6];
    const float* bm_bb1= (const float*)d_in[7];
    const float* bm_g2 = (const float*)d_in[8];
    const float* bm_b2 = (const float*)d_in[9];
    const float* bm_m2 = (const float*)d_in[10];
    const float* bm_v2 = (const float*)d_in[11];
    const float* bm_w2 = (const float*)d_in[12];
    const float* bm_bb2= (const float*)d_in[13];
    const float* et_w1 = (const float*)d_in[14];
    const float* et_b1 = (const float*)d_in[15];
    const float* et_w2 = (const float*)d_in[16];
    const float* et_b2 = (const float*)d_in[17];
    const float* up_g1 = (const float*)d_in[18];
    const float* up_b1 = (const float*)d_in[19];
    const float* up_m1 = (const float*)d_in[20];
    const float* up_v1 = (const float*)d_in[21];
    const float* up_w1 = (const float*)d_in[22];
    const float* up_bb1= (const float*)d_in[23];
    const float* up_g2 = (const float*)d_in[24];
    const float* up_b2 = (const float*)d_in[25];
    const float* up_m2 = (const float*)d_in[26];
    const float* up_v2 = (const float*)d_in[27];
    const float* up_w2 = (const float*)d_in[28];
    const float* up_bb2= (const float*)d_in[29];
    const int*   esrc  = (const int*)d_in[30];
    const int*   edst  = (const int*)d_in[31];
    float* out = (float*)d_out;

    cudaFuncSetAttribute(node_tc, cudaFuncAttributeMaxDynamicSharedMemorySize, SMN_TOT);
    cudaFuncSetAttribute(edge_tc, cudaFuncAttributeMaxDynamicSharedMemorySize, SME_TOT);
    cudaFuncSetAttribute(up1_tc,  cudaFuncAttributeMaxDynamicSharedMemorySize, SMU_TOT);
    cudaFuncSetAttribute(mlp1_tc, cudaFuncAttributeMaxDynamicSharedMemorySize, SMM_TOT);

    fold_kernel<<<128, 256>>>(bm_g1, bm_b1, bm_m1, bm_v1, bm_w1, bm_bb1, DN, 0);
    fold_kernel<<<128, 256>>>(bm_g2, bm_b2, bm_m2, bm_v2, bm_w2, bm_bb2, HH, 1);
    fold_kernel<<<128, 256>>>(up_g1, up_b1, up_m1, up_v1, up_w1, up_bb1, DC, 2);
    fold_kernel<<<128, 256>>>(up_g2, up_b2, up_m2, up_v2, up_w2, up_bb2, HH, 3);

    zero_kernel<<<(NN * HH / 4 + 255) / 256, 256>>>();
    deg_kernel<<<(NE + 255) / 256, 256>>>(esrc);

    node_tc<<<148, 256, SMN_TOT>>>(node_x, NN / 128);
    edge_tc<<<148, 256, SME_TOT>>>(eattr, et_w1, et_b1, et_w2, et_b2, esrc, edst, NE / 128);
    up1_tc<<<148, 256, SMU_TOT>>>(node_x, NN / 128);
    mlp1_tc<<<148, 256, SMM_TOT>>>(out, NN / 128);
}

// round 12
// speedup vs baseline: 2.6024x; 1.0279x over previous
#include <cuda_runtime.h>
#include <math.h>
#include <stdint.h>

#define NN 65536
#define NE 524288
#define DN 128
#define DE 64
#define HH 128
#define DC (DN + HH)
#define EPSbn 1e-3f

// ---------------- scratch ----------------
__device__ float g_hmsg[(size_t)NN * HH];
__device__ float g_agg [(size_t)NN * HH];
__device__ float g_u1  [(size_t)NN * HH];
__device__ float g_cnt [NN];

__device__ float g_bmW1[DN * HH]; __device__ float g_bmB1[HH];
__device__ float g_bmW2[HH * HH]; __device__ float g_bmB2[HH];
__device__ float g_upW1[DC * HH]; __device__ float g_upB1[HH];
__device__ float g_upW2[HH * HH]; __device__ float g_upB2[HH];

// fast exact-enough gelu: 0.5*x*(1+erf(x/sqrt2)), erf via A&S 7.1.26 (|err|<1.5e-7)
__device__ __forceinline__ float gelu_f(float x) {
    float z  = x * 0.70710678118654752f;
    float az = fabsf(z);
    float t;
    asm("rcp.approx.f32 %0, %1;" : "=f"(t) : "f"(fmaf(0.3275911f, az, 1.0f)));
    float p = fmaf(1.061405429f, t, -1.453152027f);
    p = fmaf(p, t, 1.421413741f);
    p = fmaf(p, t, -0.284496736f);
    p = fmaf(p, t, 0.254829592f);
    p = p * t;
    float e = __expf(-z * z);
    float erfa = fmaf(-p, e, 1.0f);      // erf(|z|)
    float erfz = copysignf(erfa, z);
    return 0.5f * x * (1.0f + erfz);
}

// tf32 round: destination must be .b32 per PTX spec
__device__ __forceinline__ float to_tf32(float x) {
    uint32_t r; asm("cvt.rna.tf32.f32 %0, %1;" : "=r"(r) : "f"(x));
    return __uint_as_float(r);
}

// ---------------- warp-level tf32 MMA GEMM ----------------
// Warp computes D[16 x 128] += X[16 x 8*KT] @ Wt^T, operands in smem.
// Xs: row-major [row][k], pitch xp (pad so xp mod 32 == 4)
// Wt: [n][k] (transposed weight), pitch wp (pad so wp mod 32 == 4)
// acc[nt][0..3]: c0,c1 = (row g, cols 2tig,2tig+1), c2,c3 = (row g+8) within n-tile nt.
// s-loop unroll bounded to 2 to keep SASS footprint / compile time sane.
template<int KT>
__device__ __forceinline__ void warp_gemm(const float* __restrict__ Xs, int xp,
                                          const float* __restrict__ Wt, int wp,
                                          int m0, float (&acc)[16][4]) {
    const int l = threadIdx.x & 31, g = l >> 2, tig = l & 3;
    const float* xr0 = Xs + (m0 + g) * xp + tig;
    const float* xr1 = xr0 + 8 * xp;
    const float* wbase = Wt + g * wp + tig;
#pragma unroll 2
    for (int s = 0; s < KT; s++) {
        const int k0 = 8 * s;
        float a0 = xr0[k0], a1 = xr1[k0], a2 = xr0[k0 + 4], a3 = xr1[k0 + 4];
#pragma unroll
        for (int nt = 0; nt < 16; nt++) {
            const float* wr = wbase + nt * 8 * wp;
            float b0 = wr[k0], b1 = wr[k0 + 4];
            asm volatile(
                "mma.sync.aligned.m16n8k8.row.col.f32.tf32.tf32.f32 "
                "{%0,%1,%2,%3}, {%4,%5,%6,%7}, {%8,%9}, {%0,%1,%2,%3};"
                : "+f"(acc[nt][0]), "+f"(acc[nt][1]), "+f"(acc[nt][2]), "+f"(acc[nt][3])
                : "r"(__float_as_uint(a0)), "r"(__float_as_uint(a1)),
                  "r"(__float_as_uint(a2)), "r"(__float_as_uint(a3)),
                  "r"(__float_as_uint(b0)), "r"(__float_as_uint(b1)));
        }
    }
}

// ---------------- BN folding (all four in one launch) ----------------
struct FoldArgs {
    const float* g[4]; const float* b[4]; const float* m[4]; const float* v[4];
    const float* W[4]; const float* bb[4]; int K[4];
};

__global__ void fold_all(FoldArgs a) {
    const int which = blockIdx.x >> 7;     // 0..3
    const int j = blockIdx.x & 127;        // output column
    float* Wo; float* Bo;
    if      (which == 0) { Wo = g_bmW1; Bo = g_bmB1; }
    else if (which == 1) { Wo = g_bmW2; Bo = g_bmB2; }
    else if (which == 2) { Wo = g_upW1; Bo = g_upB1; }
    else                 { Wo = g_upW2; Bo = g_upB2; }
    const float* g = a.g[which]; const float* b = a.b[which];
    const float* m = a.m[which]; const float* v = a.v[which];
    const float* W = a.W[which]; const float* bb = a.bb[which];
    const int K = a.K[which];
    __shared__ float red[256];
    int tid = threadIdx.x;
    float acc = 0.f;
    for (int i = tid; i < K; i += 256) {
        float s = g[i] * rsqrtf(v[i] + EPSbn);
        float t = b[i] - m[i] * s;
        float w = W[i * HH + j];
        Wo[i * HH + j] = s * w;
        acc += t * w;
    }
    red[tid] = acc; __syncthreads();
    for (int o = 128; o > 0; o >>= 1) { if (tid < o) red[tid] += red[tid + o]; __syncthreads(); }
    if (tid == 0) Bo[j] = bb[j] + red[0];
}

__global__ void zero_kernel() {
    int i = blockIdx.x * blockDim.x + threadIdx.x;
    if (i < NN * HH / 4) ((float4*)g_agg)[i] = make_float4(0.f, 0.f, 0.f, 0.f);
    if (i < NN / 4)      ((float4*)g_cnt)[i] = make_float4(0.f, 0.f, 0.f, 0.f);
}

__global__ void deg_kernel(const int* __restrict__ src) {
    int i = blockIdx.x * blockDim.x + threadIdx.x;
    if (i < NE) atomicAdd(&g_cnt[src[i]], 1.0f);
}

// ============== node base-message MLP: two fused 128x128 GEMMs ==============
// smem floats: W1t 128*132 | W2t 128*132 | Xs 128*132 | b1 128 | b2 128
#define SMN_TOT ((3 * 128 * 132 + 256) * 4)
__global__ void __launch_bounds__(256, 1)
node_tc(const float* __restrict__ X, int tiles) {
    extern __shared__ float sm[];
    float* W1t = sm;
    float* W2t = W1t + 128 * 132;
    float* Xs  = W2t + 128 * 132;
    float* b1s = Xs + 128 * 132;
    float* b2s = b1s + 128;
    const int tid = threadIdx.x, wid = tid >> 5, l = tid & 31, g = l >> 2, tig = l & 3;
    const int m0 = wid * 16;
    for (int i = tid; i < 128 * 128; i += 256) {
        int k = i >> 7, n = i & 127;
        W1t[n * 132 + k] = to_tf32(g_bmW1[i]);
        W2t[n * 132 + k] = to_tf32(g_bmW2[i]);
    }
    if (tid < 128) { b1s[tid] = g_bmB1[tid]; b2s[tid] = g_bmB2[tid]; }
    __syncthreads();
    for (int t = blockIdx.x; t < tiles; t += gridDim.x) {
        size_t base = (size_t)t * 128;
        for (int i = tid; i < 128 * 32; i += 256) {
            int r = i >> 5, kq = (i & 31) * 4;
            float4 v = *(const float4*)(X + (base + r) * 128 + kq);
            float* p = Xs + r * 132 + kq;
            p[0] = to_tf32(v.x); p[1] = to_tf32(v.y); p[2] = to_tf32(v.z); p[3] = to_tf32(v.w);
        }
        __syncthreads();
        float acc[16][4] = {};
        warp_gemm<16>(Xs, 132, W1t, 132, m0, acc);
        __syncthreads();
#pragma unroll
        for (int nt = 0; nt < 16; nt++) {
            int cn = nt * 8 + 2 * tig;
            Xs[(m0 + g) * 132 + cn]         = to_tf32(gelu_f(acc[nt][0] + b1s[cn]));
            Xs[(m0 + g) * 132 + cn + 1]     = to_tf32(gelu_f(acc[nt][1] + b1s[cn + 1]));
            Xs[(m0 + g + 8) * 132 + cn]     = to_tf32(gelu_f(acc[nt][2] + b1s[cn]));
            Xs[(m0 + g + 8) * 132 + cn + 1] = to_tf32(gelu_f(acc[nt][3] + b1s[cn + 1]));
        }
        __syncthreads();
        float acc2[16][4] = {};
        warp_gemm<16>(Xs, 132, W2t, 132, m0, acc2);
#pragma unroll
        for (int nt = 0; nt < 16; nt++) {
            int cn = nt * 8 + 2 * tig;
            float2 v0 = make_float2(gelu_f(acc2[nt][0] + b2s[cn]), gelu_f(acc2[nt][1] + b2s[cn + 1]));
            float2 v1 = make_float2(gelu_f(acc2[nt][2] + b2s[cn]), gelu_f(acc2[nt][3] + b2s[cn + 1]));
            *(float2*)(g_hmsg + (base + m0 + g) * 128 + cn)     = v0;
            *(float2*)(g_hmsg + (base + m0 + g + 8) * 128 + cn) = v1;
        }
        __syncthreads();
    }
}

// ============== edge kernel: e-MLP (K=64, K=128) + gather + vectorized atomic scatter ==============
// floats: W1t 128*68 | EAs 128*68 | W2t 128*132 | H1s 128*132 | b1 128 | b2 128, then ints src/dst
#define SME_FLOATS (2 * 128 * 68 + 2 * 128 * 132 + 256)
#define SME_TOT (SME_FLOATS * 4 + 256 * 4)
__global__ void __launch_bounds__(256, 1)
edge_tc(const float* __restrict__ EA,
        const float* __restrict__ W1, const float* __restrict__ B1,
        const float* __restrict__ W2, const float* __restrict__ B2,
        const int* __restrict__ esrc, const int* __restrict__ edst, int tiles) {
    extern __shared__ float sm[];
    float* W1t = sm;                       // 128 x 68
    float* EAs = W1t + 128 * 68;           // 128 x 68
    float* W2t = EAs + 128 * 68;           // 128 x 132
    float* H1s = W2t + 128 * 132;          // 128 x 132
    float* b1s = H1s + 128 * 132;
    float* b2s = b1s + 128;
    int* src_s = (int*)(b2s + 128);
    int* dst_s = src_s + 128;
    const int tid = threadIdx.x, wid = tid >> 5, l = tid & 31, g = l >> 2, tig = l & 3;
    const int m0 = wid * 16;
    for (int i = tid; i < 64 * 128; i += 256) { int k = i >> 7, n = i & 127; W1t[n * 68 + k] = to_tf32(W1[i]); }
    for (int i = tid; i < 128 * 128; i += 256) { int k = i >> 7, n = i & 127; W2t[n * 132 + k] = to_tf32(W2[i]); }
    if (tid < 128) { b1s[tid] = B1[tid]; b2s[tid] = B2[tid]; }
    __syncthreads();
    for (int t = blockIdx.x; t < tiles; t += gridDim.x) {
        size_t base = (size_t)t * 128;
        for (int i = tid; i < 128 * 16; i += 256) {
            int r = i >> 4, kq = (i & 15) * 4;
            float4 v = *(const float4*)(EA + (base + r) * 64 + kq);
            float* p = EAs + r * 68 + kq;
            p[0] = to_tf32(v.x); p[1] = to_tf32(v.y); p[2] = to_tf32(v.z); p[3] = to_tf32(v.w);
        }
        if (tid < 128) src_s[tid] = esrc[base + tid];
        else           dst_s[tid - 128] = edst[base + tid - 128];
        __syncthreads();
        float acc[16][4] = {};
        warp_gemm<8>(EAs, 68, W1t, 68, m0, acc);
#pragma unroll
        for (int nt = 0; nt < 16; nt++) {
            int cn = nt * 8 + 2 * tig;
            H1s[(m0 + g) * 132 + cn]         = to_tf32(gelu_f(acc[nt][0] + b1s[cn]));
            H1s[(m0 + g) * 132 + cn + 1]     = to_tf32(gelu_f(acc[nt][1] + b1s[cn + 1]));
            H1s[(m0 + g + 8) * 132 + cn]     = to_tf32(gelu_f(acc[nt][2] + b1s[cn]));
            H1s[(m0 + g + 8) * 132 + cn + 1] = to_tf32(gelu_f(acc[nt][3] + b1s[cn + 1]));
        }
        __syncthreads();
        float acc2[16][4] = {};
        warp_gemm<16>(H1s, 132, W2t, 132, m0, acc2);
        // epilogue: msg = gelu(e)*hmsg[dst], float2 atomics into agg[src]
        {
            int r0 = m0 + g, r1 = m0 + g + 8;
            int dd0 = dst_s[r0], ss0 = src_s[r0];
            int dd1 = dst_s[r1], ss1 = src_s[r1];
            const float* hp0 = g_hmsg + (size_t)dd0 * 128;
            const float* hp1 = g_hmsg + (size_t)dd1 * 128;
            float* ap0 = g_agg + (size_t)ss0 * 128;
            float* ap1 = g_agg + (size_t)ss1 * 128;
#pragma unroll 4
            for (int nt = 0; nt < 16; nt++) {
                int cn = nt * 8 + 2 * tig;
                float2 h0 = *(const float2*)(hp0 + cn);
                float2 h1 = *(const float2*)(hp1 + cn);
                float2 m0v = make_float2(gelu_f(acc2[nt][0] + b2s[cn])     * h0.x,
                                         gelu_f(acc2[nt][1] + b2s[cn + 1]) * h0.y);
                float2 m1v = make_float2(gelu_f(acc2[nt][2] + b2s[cn])     * h1.x,
                                         gelu_f(acc2[nt][3] + b2s[cn + 1]) * h1.y);
                atomicAdd(reinterpret_cast<float2*>(ap0 + cn), m0v);
                atomicAdd(reinterpret_cast<float2*>(ap1 + cn), m1v);
            }
        }
        __syncthreads();
    }
}

// ============== update stage 1: [node_x | agg/cnt] @ upW1 (K=256) ==============
// floats: W1t 128*260 | Xs 128*132 | b1 128
#define SMU_TOT ((128 * 260 + 128 * 132 + 128) * 4)
__global__ void __launch_bounds__(256, 1)
up1_tc(const float* __restrict__ X, int tiles) {
    extern __shared__ float sm[];
    float* W1t = sm;                 // [n=128][k=256] pitch 260
    float* Xs  = W1t + 128 * 260;    // 128 x 132
    float* b1s = Xs + 128 * 132;
    const int tid = threadIdx.x, wid = tid >> 5, l = tid & 31, g = l >> 2, tig = l & 3;
    const int m0 = wid * 16;
    for (int i = tid; i < 256 * 128; i += 256) { int k = i >> 7, n = i & 127; W1t[n * 260 + k] = to_tf32(g_upW1[i]); }
    if (tid < 128) b1s[tid] = g_upB1[tid];
    __syncthreads();
    for (int t = blockIdx.x; t < tiles; t += gridDim.x) {
        size_t base = (size_t)t * 128;
        // K half 1: node_x
        for (int i = tid; i < 128 * 32; i += 256) {
            int r = i >> 5, kq = (i & 31) * 4;
            float4 v = *(const float4*)(X + (base + r) * 128 + kq);
            float* p = Xs + r * 132 + kq;
            p[0] = to_tf32(v.x); p[1] = to_tf32(v.y); p[2] = to_tf32(v.z); p[3] = to_tf32(v.w);
        }
        __syncthreads();
        float acc[16][4] = {};
        warp_gemm<16>(Xs, 132, W1t, 260, m0, acc);
        __syncthreads();
        // K half 2: agg / max(cnt,1)
        for (int i = tid; i < 128 * 32; i += 256) {
            int r = i >> 5, kq = (i & 31) * 4;
            float sc = 1.0f / fmaxf(g_cnt[base + r], 1.0f);
            float4 v = *(const float4*)(g_agg + (base + r) * 128 + kq);
            float* p = Xs + r * 132 + kq;
            p[0] = to_tf32(v.x * sc); p[1] = to_tf32(v.y * sc);
            p[2] = to_tf32(v.z * sc); p[3] = to_tf32(v.w * sc);
        }
        __syncthreads();
        warp_gemm<16>(Xs, 132, W1t + 128, 260, m0, acc);
#pragma unroll
        for (int nt = 0; nt < 16; nt++) {
            int cn = nt * 8 + 2 * tig;
            float2 v0 = make_float2(gelu_f(acc[nt][0] + b1s[cn]), gelu_f(acc[nt][1] + b1s[cn + 1]));
            float2 v1 = make_float2(gelu_f(acc[nt][2] + b1s[cn]), gelu_f(acc[nt][3] + b1s[cn + 1]));
            *(float2*)(g_u1 + (base + m0 + g) * 128 + cn)     = v0;
            *(float2*)(g_u1 + (base + m0 + g + 8) * 128 + cn) = v1;
        }
        __syncthreads();
    }
}

// ============== update stage 2: g_u1 @ upW2 -> gelu -> out ==============
#define SMM_TOT ((2 * 128 * 132 + 128) * 4)
__global__ void __launch_bounds__(256, 1)
mlp1_tc(float* __restrict__ out, int tiles) {
    extern __shared__ float sm[];
    float* Wt = sm;
    float* Xs = Wt + 128 * 132;
    float* bs = Xs + 128 * 132;
    const int tid = threadIdx.x, wid = tid >> 5, l = tid & 31, g = l >> 2, tig = l & 3;
    const int m0 = wid * 16;
    for (int i = tid; i < 128 * 128; i += 256) { int k = i >> 7, n = i & 127; Wt[n * 132 + k] = to_tf32(g_upW2[i]); }
    if (tid < 128) bs[tid] = g_upB2[tid];
    __syncthreads();
    for (int t = blockIdx.x; t < tiles; t += gridDim.x) {
        size_t base = (size_t)t * 128;
        for (int i = tid; i < 128 * 32; i += 256) {
            int r = i >> 5, kq = (i & 31) * 4;
            float4 v = *(const float4*)(g_u1 + (base + r) * 128 + kq);
            float* p = Xs + r * 132 + kq;
            p[0] = to_tf32(v.x); p[1] = to_tf32(v.y); p[2] = to_tf32(v.z); p[3] = to_tf32(v.w);
        }
        __syncthreads();
        float acc[16][4] = {};
        warp_gemm<16>(Xs, 132, Wt, 132, m0, acc);
#pragma unroll
        for (int nt = 0; nt < 16; nt++) {
            int cn = nt * 8 + 2 * tig;
            float2 v0 = make_float2(gelu_f(acc[nt][0] + bs[cn]), gelu_f(acc[nt][1] + bs[cn + 1]));
            float2 v1 = make_float2(gelu_f(acc[nt][2] + bs[cn]), gelu_f(acc[nt][3] + bs[cn + 1]));
            *(float2*)(out + (base + m0 + g) * 128 + cn)     = v0;
            *(float2*)(out + (base + m0 + g + 8) * 128 + cn) = v1;
        }
        __syncthreads();
    }
}

// ---------------- launch ----------------
extern "C" void kernel_launch(void* const* d_in, const int* in_sizes, int n_in,
                              void* d_out, int out_size) {
    const float* node_x = (const float*)d_in[0];
    const float* eattr  = (const float*)d_in[1];
    const float* bm_g1 = (const float*)d_in[2];
    const float* bm_b1 = (const float*)d_in[3];
    const float* bm_m1 = (const float*)d_in[4];
    const float* bm_v1 = (const float*)d_in[5];
    const float* bm_w1 = (const float*)d_in[6];
    const float* bm_bb1= (const float*)d_in[7];
    const float* bm_g2 = (const float*)d_in[8];
    const float* bm_b2 = (const float*)d_in[9];
    const float* bm_m2 = (const float*)d_in[10];
    const float* bm_v2 = (const float*)d_in[11];
    const float* bm_w2 = (const float*)d_in[12];
    const float* bm_bb2= (const float*)d_in[13];
    const float* et_w1 = (const float*)d_in[14];
    const float* et_b1 = (const float*)d_in[15];
    const float* et_w2 = (const float*)d_in[16];
    const float* et_b2 = (const float*)d_in[17];
    const float* up_g1 = (const float*)d_in[18];
    const float* up_b1 = (const float*)d_in[19];
    const float* up_m1 = (const float*)d_in[20];
    const float* up_v1 = (const float*)d_in[21];
    const float* up_w1 = (const float*)d_in[22];
    const float* up_bb1= (const float*)d_in[23];
    const float* up_g2 = (const float*)d_in[24];
    const float* up_b2 = (const float*)d_in[25];
    const float* up_m2 = (const float*)d_in[26];
    const float* up_v2 = (const float*)d_in[27];
    const float* up_w2 = (const float*)d_in[28];
    const float* up_bb2= (const float*)d_in[29];
    const int*   esrc  = (const int*)d_in[30];
    const int*   edst  = (const int*)d_in[31];
    float* out = (float*)d_out;

    cudaFuncSetAttribute(node_tc, cudaFuncAttributeMaxDynamicSharedMemorySize, SMN_TOT);
    cudaFuncSetAttribute(edge_tc, cudaFuncAttributeMaxDynamicSharedMemorySize, SME_TOT);
    cudaFuncSetAttribute(up1_tc,  cudaFuncAttributeMaxDynamicSharedMemorySize, SMU_TOT);
    cudaFuncSetAttribute(mlp1_tc, cudaFuncAttributeMaxDynamicSharedMemorySize, SMM_TOT);

    FoldArgs fa;
    fa.g[0] = bm_g1; fa.b[0] = bm_b1; fa.m[0] = bm_m1; fa.v[0] = bm_v1; fa.W[0] = bm_w1; fa.bb[0] = bm_bb1; fa.K[0] = DN;
    fa.g[1] = bm_g2; fa.b[1] = bm_b2; fa.m[1] = bm_m2; fa.v[1] = bm_v2; fa.W[1] = bm_w2; fa.bb[1] = bm_bb2; fa.K[1] = HH;
    fa.g[2] = up_g1; fa.b[2] = up_b1; fa.m[2] = up_m1; fa.v[2] = up_v1; fa.W[2] = up_w1; fa.bb[2] = up_bb1; fa.K[2] = DC;
    fa.g[3] = up_g2; fa.b[3] = up_b2; fa.m[3] = up_m2; fa.v[3] = up_v2; fa.W[3] = up_w2; fa.bb[3] = up_bb2; fa.K[3] = HH;
    fold_all<<<512, 256>>>(fa);

    zero_kernel<<<(NN * HH / 4 + 255) / 256, 256>>>();
    deg_kernel<<<(NE + 255) / 256, 256>>>(esrc);

    node_tc<<<148, 256, SMN_TOT>>>(node_x, NN / 128);
    edge_tc<<<148, 256, SME_TOT>>>(eattr, et_w1, et_b1, et_w2, et_b2, esrc, edst, NE / 128);
    up1_tc<<<148, 256, SMU_TOT>>>(node_x, NN / 128);
    mlp1_tc<<<148, 256, SMM_TOT>>>(out, NN / 128);
}

// round 13
// speedup vs baseline: 3.0971x; 1.1901x over previous
#include <cuda_runtime.h>
#include <math.h>
#include <stdint.h>

#define NN 65536
#define NE 524288
#define DN 128
#define DE 64
#define HH 128
#define DC (DN + HH)
#define EPSbn 1e-3f

// ---------------- scratch ----------------
__device__ float g_hmsg[(size_t)NN * HH];
__device__ float g_agg [(size_t)NN * HH];
__device__ float g_u1  [(size_t)NN * HH];
__device__ float g_cnt [NN];

__device__ float g_bmW1[DN * HH]; __device__ float g_bmB1[HH];
__device__ float g_bmW2[HH * HH]; __device__ float g_bmB2[HH];
__device__ float g_upW1[DC * HH]; __device__ float g_upB1[HH];
__device__ float g_upW2[HH * HH]; __device__ float g_upB2[HH];

// fast exact-enough gelu: 0.5*x*(1+erf(x/sqrt2)), erf via A&S 7.1.26 (|err|<1.5e-7)
__device__ __forceinline__ float gelu_f(float x) {
    float z  = x * 0.70710678118654752f;
    float az = fabsf(z);
    float t;
    asm("rcp.approx.f32 %0, %1;" : "=f"(t) : "f"(fmaf(0.3275911f, az, 1.0f)));
    float p = fmaf(1.061405429f, t, -1.453152027f);
    p = fmaf(p, t, 1.421413741f);
    p = fmaf(p, t, -0.284496736f);
    p = fmaf(p, t, 0.254829592f);
    p = p * t;
    float e = __expf(-z * z);
    float erfa = fmaf(-p, e, 1.0f);      // erf(|z|)
    float erfz = copysignf(erfa, z);
    return 0.5f * x * (1.0f + erfz);
}

// tf32 round: destination must be .b32 per PTX spec
__device__ __forceinline__ float to_tf32(float x) {
    uint32_t r; asm("cvt.rna.tf32.f32 %0, %1;" : "=r"(r) : "f"(x));
    return __uint_as_float(r);
}

// ---------------- warp-level tf32 MMA GEMM (half-N: 16 rows x 64 cols) ----------------
// Warp computes D[16 x 64] += X[16 x 8*KT] @ Wt^T slice, operands in smem.
// Xs: row-major [row][k], pitch xp (pad xp mod 32 == 4); Wt: [n][k], pitch wp.
// n range covered: [n0, n0+64). acc[nt][0..3]: rows (g, g+8), cols (2tig, 2tig+1) in n-tile nt.
template<int KT>
__device__ __forceinline__ void warp_gemm8(const float* __restrict__ Xs, int xp,
                                           const float* __restrict__ Wt, int wp,
                                           int m0, int n0, float (&acc)[8][4]) {
    const int l = threadIdx.x & 31, g = l >> 2, tig = l & 3;
    const float* xr0 = Xs + (m0 + g) * xp + tig;
    const float* xr1 = xr0 + 8 * xp;
    const float* wbase = Wt + (n0 + g) * wp + tig;
#pragma unroll 2
    for (int s = 0; s < KT; s++) {
        const int k0 = 8 * s;
        float a0 = xr0[k0], a1 = xr1[k0], a2 = xr0[k0 + 4], a3 = xr1[k0 + 4];
#pragma unroll
        for (int nt = 0; nt < 8; nt++) {
            const float* wr = wbase + nt * 8 * wp;
            float b0 = wr[k0], b1 = wr[k0 + 4];
            asm volatile(
                "mma.sync.aligned.m16n8k8.row.col.f32.tf32.tf32.f32 "
                "{%0,%1,%2,%3}, {%4,%5,%6,%7}, {%8,%9}, {%0,%1,%2,%3};"
                : "+f"(acc[nt][0]), "+f"(acc[nt][1]), "+f"(acc[nt][2]), "+f"(acc[nt][3])
                : "r"(__float_as_uint(a0)), "r"(__float_as_uint(a1)),
                  "r"(__float_as_uint(a2)), "r"(__float_as_uint(a3)),
                  "r"(__float_as_uint(b0)), "r"(__float_as_uint(b1)));
        }
    }
}

// ---------------- BN folding (all four in one launch) ----------------
struct FoldArgs {
    const float* g[4]; const float* b[4]; const float* m[4]; const float* v[4];
    const float* W[4]; const float* bb[4]; int K[4];
};

__global__ void fold_all(FoldArgs a) {
    const int which = blockIdx.x >> 7;     // 0..3
    const int j = blockIdx.x & 127;        // output column
    float* Wo; float* Bo;
    if      (which == 0) { Wo = g_bmW1; Bo = g_bmB1; }
    else if (which == 1) { Wo = g_bmW2; Bo = g_bmB2; }
    else if (which == 2) { Wo = g_upW1; Bo = g_upB1; }
    else                 { Wo = g_upW2; Bo = g_upB2; }
    const float* g = a.g[which]; const float* b = a.b[which];
    const float* m = a.m[which]; const float* v = a.v[which];
    const float* W = a.W[which]; const float* bb = a.bb[which];
    const int K = a.K[which];
    __shared__ float red[256];
    int tid = threadIdx.x;
    float acc = 0.f;
    for (int i = tid; i < K; i += 256) {
        float s = g[i] * rsqrtf(v[i] + EPSbn);
        float t = b[i] - m[i] * s;
        float w = W[i * HH + j];
        Wo[i * HH + j] = s * w;
        acc += t * w;
    }
    red[tid] = acc; __syncthreads();
    for (int o = 128; o > 0; o >>= 1) { if (tid < o) red[tid] += red[tid + o]; __syncthreads(); }
    if (tid == 0) Bo[j] = bb[j] + red[0];
}

__global__ void zero_kernel() {
    int i = blockIdx.x * blockDim.x + threadIdx.x;
    if (i < NN * HH / 4) ((float4*)g_agg)[i] = make_float4(0.f, 0.f, 0.f, 0.f);
    if (i < NN / 4)      ((float4*)g_cnt)[i] = make_float4(0.f, 0.f, 0.f, 0.f);
}

__global__ void deg_kernel(const int* __restrict__ src) {
    int i = blockIdx.x * blockDim.x + threadIdx.x;
    if (i < NE) atomicAdd(&g_cnt[src[i]], 1.0f);
}

// ============== node base-message MLP: two fused 128x128 GEMMs, 512 thr ==============
// smem floats: W1t 128*132 | W2t 128*132 | Xs 128*132 | b1 128 | b2 128
#define SMN_TOT ((3 * 128 * 132 + 256) * 4)
__global__ void __launch_bounds__(512, 1)
node_tc(const float* __restrict__ X, int tiles) {
    extern __shared__ float sm[];
    float* W1t = sm;
    float* W2t = W1t + 128 * 132;
    float* Xs  = W2t + 128 * 132;
    float* b1s = Xs + 128 * 132;
    float* b2s = b1s + 128;
    const int tid = threadIdx.x, wid = tid >> 5, l = tid & 31, g = l >> 2, tig = l & 3;
    const int m0 = (wid >> 1) * 16, n0 = (wid & 1) * 64;
    for (int i = tid; i < 128 * 128; i += 512) {
        int k = i >> 7, n = i & 127;
        W1t[n * 132 + k] = to_tf32(g_bmW1[i]);
        W2t[n * 132 + k] = to_tf32(g_bmW2[i]);
    }
    if (tid < 128) { b1s[tid] = g_bmB1[tid]; b2s[tid] = g_bmB2[tid]; }
    __syncthreads();
    for (int t = blockIdx.x; t < tiles; t += gridDim.x) {
        size_t base = (size_t)t * 128;
        for (int i = tid; i < 128 * 32; i += 512) {
            int r = i >> 5, kq = (i & 31) * 4;
            float4 v = *(const float4*)(X + (base + r) * 128 + kq);
            float* p = Xs + r * 132 + kq;
            p[0] = to_tf32(v.x); p[1] = to_tf32(v.y); p[2] = to_tf32(v.z); p[3] = to_tf32(v.w);
        }
        __syncthreads();
        float acc[8][4] = {};
        warp_gemm8<16>(Xs, 132, W1t, 132, m0, n0, acc);
        __syncthreads();
#pragma unroll
        for (int nt = 0; nt < 8; nt++) {
            int cn = n0 + nt * 8 + 2 * tig;
            Xs[(m0 + g) * 132 + cn]         = to_tf32(gelu_f(acc[nt][0] + b1s[cn]));
            Xs[(m0 + g) * 132 + cn + 1]     = to_tf32(gelu_f(acc[nt][1] + b1s[cn + 1]));
            Xs[(m0 + g + 8) * 132 + cn]     = to_tf32(gelu_f(acc[nt][2] + b1s[cn]));
            Xs[(m0 + g + 8) * 132 + cn + 1] = to_tf32(gelu_f(acc[nt][3] + b1s[cn + 1]));
        }
        __syncthreads();
        float acc2[8][4] = {};
        warp_gemm8<16>(Xs, 132, W2t, 132, m0, n0, acc2);
#pragma unroll
        for (int nt = 0; nt < 8; nt++) {
            int cn = n0 + nt * 8 + 2 * tig;
            float2 v0 = make_float2(gelu_f(acc2[nt][0] + b2s[cn]), gelu_f(acc2[nt][1] + b2s[cn + 1]));
            float2 v1 = make_float2(gelu_f(acc2[nt][2] + b2s[cn]), gelu_f(acc2[nt][3] + b2s[cn + 1]));
            *(float2*)(g_hmsg + (base + m0 + g) * 128 + cn)     = v0;
            *(float2*)(g_hmsg + (base + m0 + g + 8) * 128 + cn) = v1;
        }
        __syncthreads();
    }
}

// ============== edge kernel: e-MLP + gather + vectorized atomic scatter, 512 thr ==============
// floats: W1t 128*68 | EAs 128*68 | W2t 128*132 | H1s 128*132 | b1 128 | b2 128, then ints src/dst
#define SME_FLOATS (2 * 128 * 68 + 2 * 128 * 132 + 256)
#define SME_TOT (SME_FLOATS * 4 + 256 * 4)
__global__ void __launch_bounds__(512, 1)
edge_tc(const float* __restrict__ EA,
        const float* __restrict__ W1, const float* __restrict__ B1,
        const float* __restrict__ W2, const float* __restrict__ B2,
        const int* __restrict__ esrc, const int* __restrict__ edst, int tiles) {
    extern __shared__ float sm[];
    float* W1t = sm;                       // 128 x 68
    float* EAs = W1t + 128 * 68;           // 128 x 68
    float* W2t = EAs + 128 * 68;           // 128 x 132
    float* H1s = W2t + 128 * 132;          // 128 x 132
    float* b1s = H1s + 128 * 132;
    float* b2s = b1s + 128;
    int* src_s = (int*)(b2s + 128);
    int* dst_s = src_s + 128;
    const int tid = threadIdx.x, wid = tid >> 5, l = tid & 31, g = l >> 2, tig = l & 3;
    const int m0 = (wid >> 1) * 16, n0 = (wid & 1) * 64;
    for (int i = tid; i < 64 * 128; i += 512) { int k = i >> 7, n = i & 127; W1t[n * 68 + k] = to_tf32(W1[i]); }
    for (int i = tid; i < 128 * 128; i += 512) { int k = i >> 7, n = i & 127; W2t[n * 132 + k] = to_tf32(W2[i]); }
    if (tid < 128) { b1s[tid] = B1[tid]; b2s[tid] = B2[tid]; }
    __syncthreads();
    for (int t = blockIdx.x; t < tiles; t += gridDim.x) {
        size_t base = (size_t)t * 128;
        for (int i = tid; i < 128 * 16; i += 512) {
            int r = i >> 4, kq = (i & 15) * 4;
            float4 v = *(const float4*)(EA + (base + r) * 64 + kq);
            float* p = EAs + r * 68 + kq;
            p[0] = to_tf32(v.x); p[1] = to_tf32(v.y); p[2] = to_tf32(v.z); p[3] = to_tf32(v.w);
        }
        if (tid < 128)      src_s[tid] = esrc[base + tid];
        else if (tid < 256) dst_s[tid - 128] = edst[base + tid - 128];
        __syncthreads();
        float acc[8][4] = {};
        warp_gemm8<8>(EAs, 68, W1t, 68, m0, n0, acc);
#pragma unroll
        for (int nt = 0; nt < 8; nt++) {
            int cn = n0 + nt * 8 + 2 * tig;
            H1s[(m0 + g) * 132 + cn]         = to_tf32(gelu_f(acc[nt][0] + b1s[cn]));
            H1s[(m0 + g) * 132 + cn + 1]     = to_tf32(gelu_f(acc[nt][1] + b1s[cn + 1]));
            H1s[(m0 + g + 8) * 132 + cn]     = to_tf32(gelu_f(acc[nt][2] + b1s[cn]));
            H1s[(m0 + g + 8) * 132 + cn + 1] = to_tf32(gelu_f(acc[nt][3] + b1s[cn + 1]));
        }
        __syncthreads();
        float acc2[8][4] = {};
        warp_gemm8<16>(H1s, 132, W2t, 132, m0, n0, acc2);
        // epilogue: msg = gelu(e)*hmsg[dst], float2 atomics into agg[src]
        {
            int r0 = m0 + g, r1 = m0 + g + 8;
            int dd0 = dst_s[r0], ss0 = src_s[r0];
            int dd1 = dst_s[r1], ss1 = src_s[r1];
            const float* hp0 = g_hmsg + (size_t)dd0 * 128;
            const float* hp1 = g_hmsg + (size_t)dd1 * 128;
            float* ap0 = g_agg + (size_t)ss0 * 128;
            float* ap1 = g_agg + (size_t)ss1 * 128;
#pragma unroll 4
            for (int nt = 0; nt < 8; nt++) {
                int cn = n0 + nt * 8 + 2 * tig;
                float2 h0 = *(const float2*)(hp0 + cn);
                float2 h1 = *(const float2*)(hp1 + cn);
                float2 m0v = make_float2(gelu_f(acc2[nt][0] + b2s[cn])     * h0.x,
                                         gelu_f(acc2[nt][1] + b2s[cn + 1]) * h0.y);
                float2 m1v = make_float2(gelu_f(acc2[nt][2] + b2s[cn])     * h1.x,
                                         gelu_f(acc2[nt][3] + b2s[cn + 1]) * h1.y);
                atomicAdd(reinterpret_cast<float2*>(ap0 + cn), m0v);
                atomicAdd(reinterpret_cast<float2*>(ap1 + cn), m1v);
            }
        }
        __syncthreads();
    }
}

// ============== update stage 1: [node_x | agg/cnt] @ upW1 (K=256), 512 thr ==============
// floats: W1t 128*260 | Xs 128*132 | b1 128
#define SMU_TOT ((128 * 260 + 128 * 132 + 128) * 4)
__global__ void __launch_bounds__(512, 1)
up1_tc(const float* __restrict__ X, int tiles) {
    extern __shared__ float sm[];
    float* W1t = sm;                 // [n=128][k=256] pitch 260
    float* Xs  = W1t + 128 * 260;    // 128 x 132
    float* b1s = Xs + 128 * 132;
    const int tid = threadIdx.x, wid = tid >> 5, l = tid & 31, g = l >> 2, tig = l & 3;
    const int m0 = (wid >> 1) * 16, n0 = (wid & 1) * 64;
    for (int i = tid; i < 256 * 128; i += 512) { int k = i >> 7, n = i & 127; W1t[n * 260 + k] = to_tf32(g_upW1[i]); }
    if (tid < 128) b1s[tid] = g_upB1[tid];
    __syncthreads();
    for (int t = blockIdx.x; t < tiles; t += gridDim.x) {
        size_t base = (size_t)t * 128;
        // K half 1: node_x
        for (int i = tid; i < 128 * 32; i += 512) {
            int r = i >> 5, kq = (i & 31) * 4;
            float4 v = *(const float4*)(X + (base + r) * 128 + kq);
            float* p = Xs + r * 132 + kq;
            p[0] = to_tf32(v.x); p[1] = to_tf32(v.y); p[2] = to_tf32(v.z); p[3] = to_tf32(v.w);
        }
        __syncthreads();
        float acc[8][4] = {};
        warp_gemm8<16>(Xs, 132, W1t, 260, m0, n0, acc);
        __syncthreads();
        // K half 2: agg / max(cnt,1)
        for (int i = tid; i < 128 * 32; i += 512) {
            int r = i >> 5, kq = (i & 31) * 4;
            float sc = 1.0f / fmaxf(g_cnt[base + r], 1.0f);
            float4 v = *(const float4*)(g_agg + (base + r) * 128 + kq);
            float* p = Xs + r * 132 + kq;
            p[0] = to_tf32(v.x * sc); p[1] = to_tf32(v.y * sc);
            p[2] = to_tf32(v.z * sc); p[3] = to_tf32(v.w * sc);
        }
        __syncthreads();
        warp_gemm8<16>(Xs, 132, W1t + 128, 260, m0, n0, acc);
#pragma unroll
        for (int nt = 0; nt < 8; nt++) {
            int cn = n0 + nt * 8 + 2 * tig;
            float2 v0 = make_float2(gelu_f(acc[nt][0] + b1s[cn]), gelu_f(acc[nt][1] + b1s[cn + 1]));
            float2 v1 = make_float2(gelu_f(acc[nt][2] + b1s[cn]), gelu_f(acc[nt][3] + b1s[cn + 1]));
            *(float2*)(g_u1 + (base + m0 + g) * 128 + cn)     = v0;
            *(float2*)(g_u1 + (base + m0 + g + 8) * 128 + cn) = v1;
        }
        __syncthreads();
    }
}

// ============== update stage 2: g_u1 @ upW2 -> gelu -> out, 512 thr ==============
#define SMM_TOT ((2 * 128 * 132 + 128) * 4)
__global__ void __launch_bounds__(512, 1)
mlp1_tc(float* __restrict__ out, int tiles) {
    extern __shared__ float sm[];
    float* Wt = sm;
    float* Xs = Wt + 128 * 132;
    float* bs = Xs + 128 * 132;
    const int tid = threadIdx.x, wid = tid >> 5, l = tid & 31, g = l >> 2, tig = l & 3;
    const int m0 = (wid >> 1) * 16, n0 = (wid & 1) * 64;
    for (int i = tid; i < 128 * 128; i += 512) { int k = i >> 7, n = i & 127; Wt[n * 132 + k] = to_tf32(g_upW2[i]); }
    if (tid < 128) bs[tid] = g_upB2[tid];
    __syncthreads();
    for (int t = blockIdx.x; t < tiles; t += gridDim.x) {
        size_t base = (size_t)t * 128;
        for (int i = tid; i < 128 * 32; i += 512) {
            int r = i >> 5, kq = (i & 31) * 4;
            float4 v = *(const float4*)(g_u1 + (base + r) * 128 + kq);
            float* p = Xs + r * 132 + kq;
            p[0] = to_tf32(v.x); p[1] = to_tf32(v.y); p[2] = to_tf32(v.z); p[3] = to_tf32(v.w);
        }
        __syncthreads();
        float acc[8][4] = {};
        warp_gemm8<16>(Xs, 132, Wt, 132, m0, n0, acc);
#pragma unroll
        for (int nt = 0; nt < 8; nt++) {
            int cn = n0 + nt * 8 + 2 * tig;
            float2 v0 = make_float2(gelu_f(acc[nt][0] + bs[cn]), gelu_f(acc[nt][1] + bs[cn + 1]));
            float2 v1 = make_float2(gelu_f(acc[nt][2] + bs[cn]), gelu_f(acc[nt][3] + bs[cn + 1]));
            *(float2*)(out + (base + m0 + g) * 128 + cn)     = v0;
            *(float2*)(out + (base + m0 + g + 8) * 128 + cn) = v1;
        }
        __syncthreads();
    }
}

// ---------------- launch ----------------
extern "C" void kernel_launch(void* const* d_in, const int* in_sizes, int n_in,
                              void* d_out, int out_size) {
    const float* node_x = (const float*)d_in[0];
    const float* eattr  = (const float*)d_in[1];
    const float* bm_g1 = (const float*)d_in[2];
    const float* bm_b1 = (const float*)d_in[3];
    const float* bm_m1 = (const float*)d_in[4];
    const float* bm_v1 = (const float*)d_in[5];
    const float* bm_w1 = (const float*)d_in[6];
    const float* bm_bb1= (const float*)d_in[7];
    const float* bm_g2 = (const float*)d_in[8];
    const float* bm_b2 = (const float*)d_in[9];
    const float* bm_m2 = (const float*)d_in[10];
    const float* bm_v2 = (const float*)d_in[11];
    const float* bm_w2 = (const float*)d_in[12];
    const float* bm_bb2= (const float*)d_in[13];
    const float* et_w1 = (const float*)d_in[14];
    const float* et_b1 = (const float*)d_in[15];
    const float* et_w2 = (const float*)d_in[16];
    const float* et_b2 = (const float*)d_in[17];
    const float* up_g1 = (const float*)d_in[18];
    const float* up_b1 = (const float*)d_in[19];
    const float* up_m1 = (const float*)d_in[20];
    const float* up_v1 = (const float*)d_in[21];
    const float* up_w1 = (const float*)d_in[22];
    const float* up_bb1= (const float*)d_in[23];
    const float* up_g2 = (const float*)d_in[24];
    const float* up_b2 = (const float*)d_in[25];
    const float* up_m2 = (const float*)d_in[26];
    const float* up_v2 = (const float*)d_in[27];
    const float* up_w2 = (const float*)d_in[28];
    const float* up_bb2= (const float*)d_in[29];
    const int*   esrc  = (const int*)d_in[30];
    const int*   edst  = (const int*)d_in[31];
    float* out = (float*)d_out;

    cudaFuncSetAttribute(node_tc, cudaFuncAttributeMaxDynamicSharedMemorySize, SMN_TOT);
    cudaFuncSetAttribute(edge_tc, cudaFuncAttributeMaxDynamicSharedMemorySize, SME_TOT);
    cudaFuncSetAttribute(up1_tc,  cudaFuncAttributeMaxDynamicSharedMemorySize, SMU_TOT);
    cudaFuncSetAttribute(mlp1_tc, cudaFuncAttributeMaxDynamicSharedMemorySize, SMM_TOT);

    FoldArgs fa;
    fa.g[0] = bm_g1; fa.b[0] = bm_b1; fa.m[0] = bm_m1; fa.v[0] = bm_v1; fa.W[0] = bm_w1; fa.bb[0] = bm_bb1; fa.K[0] = DN;
    fa.g[1] = bm_g2; fa.b[1] = bm_b2; fa.m[1] = bm_m2; fa.v[1] = bm_v2; fa.W[1] = bm_w2; fa.bb[1] = bm_bb2; fa.K[1] = HH;
    fa.g[2] = up_g1; fa.b[2] = up_b1; fa.m[2] = up_m1; fa.v[2] = up_v1; fa.W[2] = up_w1; fa.bb[2] = up_bb1; fa.K[2] = DC;
    fa.g[3] = up_g2; fa.b[3] = up_b2; fa.m[3] = up_m2; fa.v[3] = up_v2; fa.W[3] = up_w2; fa.bb[3] = up_bb2; fa.K[3] = HH;
    fold_all<<<512, 256>>>(fa);

    zero_kernel<<<(NN * HH / 4 + 255) / 256, 256>>>();
    deg_kernel<<<(NE + 255) / 256, 256>>>(esrc);

    node_tc<<<148, 512, SMN_TOT>>>(node_x, NN / 128);
    edge_tc<<<148, 512, SME_TOT>>>(eattr, et_w1, et_b1, et_w2, et_b2, esrc, edst, NE / 128);
    up1_tc<<<148, 512, SMU_TOT>>>(node_x, NN / 128);
    mlp1_tc<<<148, 512, SMM_TOT>>>(out, NN / 128);
}

// round 14
// speedup vs baseline: 3.1047x; 1.0025x over previous
#include <cuda_runtime.h>
#include <math.h>
#include <stdint.h>

#define NN 65536
#define NE 524288
#define DN 128
#define DE 64
#define HH 128
#define DC (DN + HH)
#define EPSbn 1e-3f

// pitches (floats), all == 8 mod 32 for conflict-free LDS.64 fragment loads
#define XP128 136
#define XP64  72
#define XP256 264

// ---------------- scratch ----------------
__device__ float g_hmsg[(size_t)NN * HH];
__device__ float g_agg [(size_t)NN * HH];
__device__ float g_u1  [(size_t)NN * HH];
__device__ float g_cnt [NN];

__device__ float g_bmW1[DN * HH]; __device__ float g_bmB1[HH];
__device__ float g_bmW2[HH * HH]; __device__ float g_bmB2[HH];
__device__ float g_upW1[DC * HH]; __device__ float g_upB1[HH];
__device__ float g_upW2[HH * HH]; __device__ float g_upB2[HH];

// fast exact-enough gelu: 0.5*x*(1+erf(x/sqrt2)), erf via A&S 7.1.26 (|err|<1.5e-7)
__device__ __forceinline__ float gelu_f(float x) {
    float z  = x * 0.70710678118654752f;
    float az = fabsf(z);
    float t;
    asm("rcp.approx.f32 %0, %1;" : "=f"(t) : "f"(fmaf(0.3275911f, az, 1.0f)));
    float p = fmaf(1.061405429f, t, -1.453152027f);
    p = fmaf(p, t, 1.421413741f);
    p = fmaf(p, t, -0.284496736f);
    p = fmaf(p, t, 0.254829592f);
    p = p * t;
    float e = __expf(-z * z);
    float erfa = fmaf(-p, e, 1.0f);
    float erfz = copysignf(erfa, z);
    return 0.5f * x * (1.0f + erfz);
}

// tf32 round
__device__ __forceinline__ float to_tf32(float x) {
    uint32_t r; asm("cvt.rna.tf32.f32 %0, %1;" : "=r"(r) : "f"(x));
    return __uint_as_float(r);
}

// k-permutation within each 8-block: pairs (k, k+4) land adjacent -> LDS.64 fragments
__device__ __forceinline__ int kperm(int k) {
    return (k & ~7) | ((k & 3) << 1) | ((k >> 2) & 1);
}

// ---------------- warp-level tf32 MMA GEMM (16 rows x 64 cols), LDS.64 fragments ----------------
// Xs rows are k-permuted; Wt rows ([n][k]) are k-permuted. Pitches xp/wp == 8 mod 32.
template<int KT>
__device__ __forceinline__ void warp_gemm8(const float* __restrict__ Xs, int xp,
                                           const float* __restrict__ Wt, int wp,
                                           int m0, int n0, float (&acc)[8][4]) {
    const int l = threadIdx.x & 31, g = l >> 2, tig = l & 3;
    const float2* xr0 = (const float2*)(Xs + (m0 + g) * xp) + tig;
    const float2* xr1 = (const float2*)(Xs + (m0 + g + 8) * xp) + tig;
    const float2* wb  = (const float2*)(Wt + (n0 + g) * wp) + tig;
    const int wp2 = wp >> 1;
#pragma unroll 2
    for (int s = 0; s < KT; s++) {
        const int k2 = 4 * s;   // float2 offset of this 8-k block
        float2 A0 = xr0[k2];    // {x[g][k0+tig], x[g][k0+tig+4]}
        float2 A1 = xr1[k2];    // {x[g+8][k0+tig], x[g+8][k0+tig+4]}
#pragma unroll
        for (int nt = 0; nt < 8; nt++) {
            float2 B = wb[nt * 8 * wp2 + k2];   // {w[n][k0+tig], w[n][k0+tig+4]}
            asm volatile(
                "mma.sync.aligned.m16n8k8.row.col.f32.tf32.tf32.f32 "
                "{%0,%1,%2,%3}, {%4,%5,%6,%7}, {%8,%9}, {%0,%1,%2,%3};"
                : "+f"(acc[nt][0]), "+f"(acc[nt][1]), "+f"(acc[nt][2]), "+f"(acc[nt][3])
                : "r"(__float_as_uint(A0.x)), "r"(__float_as_uint(A1.x)),
                  "r"(__float_as_uint(A0.y)), "r"(__float_as_uint(A1.y)),
                  "r"(__float_as_uint(B.x)),  "r"(__float_as_uint(B.y)));
        }
    }
}

// ---------------- BN folding (all four in one launch) ----------------
struct FoldArgs {
    const float* g[4]; const float* b[4]; const float* m[4]; const float* v[4];
    const float* W[4]; const float* bb[4]; int K[4];
};

__global__ void fold_all(FoldArgs a) {
    const int which = blockIdx.x >> 7;
    const int j = blockIdx.x & 127;
    float* Wo; float* Bo;
    if      (which == 0) { Wo = g_bmW1; Bo = g_bmB1; }
    else if (which == 1) { Wo = g_bmW2; Bo = g_bmB2; }
    else if (which == 2) { Wo = g_upW1; Bo = g_upB1; }
    else                 { Wo = g_upW2; Bo = g_upB2; }
    const float* g = a.g[which]; const float* b = a.b[which];
    const float* m = a.m[which]; const float* v = a.v[which];
    const float* W = a.W[which]; const float* bb = a.bb[which];
    const int K = a.K[which];
    __shared__ float red[256];
    int tid = threadIdx.x;
    float acc = 0.f;
    for (int i = tid; i < K; i += 256) {
        float s = g[i] * rsqrtf(v[i] + EPSbn);
        float t = b[i] - m[i] * s;
        float w = W[i * HH + j];
        Wo[i * HH + j] = s * w;
        acc += t * w;
    }
    red[tid] = acc; __syncthreads();
    for (int o = 128; o > 0; o >>= 1) { if (tid < o) red[tid] += red[tid + o]; __syncthreads(); }
    if (tid == 0) Bo[j] = bb[j] + red[0];
}

__global__ void zero_kernel() {
    int i = blockIdx.x * blockDim.x + threadIdx.x;
    if (i < NN * HH / 4) ((float4*)g_agg)[i] = make_float4(0.f, 0.f, 0.f, 0.f);
    if (i < NN / 4)      ((float4*)g_cnt)[i] = make_float4(0.f, 0.f, 0.f, 0.f);
}

__global__ void deg_kernel(const int* __restrict__ src) {
    int i = blockIdx.x * blockDim.x + threadIdx.x;
    if (i < NE) atomicAdd(&g_cnt[src[i]], 1.0f);
}

// ============== node base-message MLP: two fused 128x128 GEMMs, 512 thr ==============
#define SMN_TOT ((3 * 128 * XP128 + 256) * 4)
__global__ void __launch_bounds__(512, 1)
node_tc(const float* __restrict__ X, int tiles) {
    extern __shared__ float sm[];
    float* W1t = sm;
    float* W2t = W1t + 128 * XP128;
    float* Xs  = W2t + 128 * XP128;
    float* b1s = Xs + 128 * XP128;
    float* b2s = b1s + 128;
    const int tid = threadIdx.x, wid = tid >> 5, l = tid & 31, g = l >> 2, tig = l & 3;
    const int m0 = (wid >> 1) * 16, n0 = (wid & 1) * 64;
    for (int i = tid; i < 128 * 128; i += 512) {
        int k = i >> 7, n = i & 127;
        W1t[n * XP128 + kperm(k)] = to_tf32(g_bmW1[i]);
        W2t[n * XP128 + kperm(k)] = to_tf32(g_bmW2[i]);
    }
    if (tid < 128) { b1s[tid] = g_bmB1[tid]; b2s[tid] = g_bmB2[tid]; }
    __syncthreads();
    for (int t = blockIdx.x; t < tiles; t += gridDim.x) {
        size_t base = (size_t)t * 128;
        for (int i = tid; i < 128 * 32; i += 512) {
            int r = i >> 5, kq = (i & 31) * 4;
            float4 v = *(const float4*)(X + (base + r) * 128 + kq);
            float* p = Xs + r * XP128;
            p[kperm(kq)]     = to_tf32(v.x);
            p[kperm(kq + 1)] = to_tf32(v.y);
            p[kperm(kq + 2)] = to_tf32(v.z);
            p[kperm(kq + 3)] = to_tf32(v.w);
        }
        __syncthreads();
        float acc[8][4] = {};
        warp_gemm8<16>(Xs, XP128, W1t, XP128, m0, n0, acc);
        __syncthreads();
#pragma unroll
        for (int nt = 0; nt < 8; nt++) {
            int cn = n0 + nt * 8 + 2 * tig;
            int p0 = kperm(cn), p1 = kperm(cn + 1);
            Xs[(m0 + g) * XP128 + p0]     = to_tf32(gelu_f(acc[nt][0] + b1s[cn]));
            Xs[(m0 + g) * XP128 + p1]     = to_tf32(gelu_f(acc[nt][1] + b1s[cn + 1]));
            Xs[(m0 + g + 8) * XP128 + p0] = to_tf32(gelu_f(acc[nt][2] + b1s[cn]));
            Xs[(m0 + g + 8) * XP128 + p1] = to_tf32(gelu_f(acc[nt][3] + b1s[cn + 1]));
        }
        __syncthreads();
        float acc2[8][4] = {};
        warp_gemm8<16>(Xs, XP128, W2t, XP128, m0, n0, acc2);
#pragma unroll
        for (int nt = 0; nt < 8; nt++) {
            int cn = n0 + nt * 8 + 2 * tig;
            float2 v0 = make_float2(gelu_f(acc2[nt][0] + b2s[cn]), gelu_f(acc2[nt][1] + b2s[cn + 1]));
            float2 v1 = make_float2(gelu_f(acc2[nt][2] + b2s[cn]), gelu_f(acc2[nt][3] + b2s[cn + 1]));
            *(float2*)(g_hmsg + (base + m0 + g) * 128 + cn)     = v0;
            *(float2*)(g_hmsg + (base + m0 + g + 8) * 128 + cn) = v1;
        }
        __syncthreads();
    }
}

// ============== edge kernel: e-MLP + gather + float2 atomic scatter, 512 thr ==============
#define SME_TOT ((2 * 128 * XP64 + 2 * 128 * XP128 + 256) * 4 + 256 * 4)
__global__ void __launch_bounds__(512, 1)
edge_tc(const float* __restrict__ EA,
        const float* __restrict__ W1, const float* __restrict__ B1,
        const float* __restrict__ W2, const float* __restrict__ B2,
        const int* __restrict__ esrc, const int* __restrict__ edst, int tiles) {
    extern __shared__ float sm[];
    float* W1t = sm;                         // 128 x XP64
    float* EAs = W1t + 128 * XP64;           // 128 x XP64
    float* W2t = EAs + 128 * XP64;           // 128 x XP128
    float* H1s = W2t + 128 * XP128;          // 128 x XP128
    float* b1s = H1s + 128 * XP128;
    float* b2s = b1s + 128;
    int* src_s = (int*)(b2s + 128);
    int* dst_s = src_s + 128;
    const int tid = threadIdx.x, wid = tid >> 5, l = tid & 31, g = l >> 2, tig = l & 3;
    const int m0 = (wid >> 1) * 16, n0 = (wid & 1) * 64;
    for (int i = tid; i < 64 * 128; i += 512) { int k = i >> 7, n = i & 127; W1t[n * XP64 + kperm(k)] = to_tf32(W1[i]); }
    for (int i = tid; i < 128 * 128; i += 512) { int k = i >> 7, n = i & 127; W2t[n * XP128 + kperm(k)] = to_tf32(W2[i]); }
    if (tid < 128) { b1s[tid] = B1[tid]; b2s[tid] = B2[tid]; }
    __syncthreads();
    for (int t = blockIdx.x; t < tiles; t += gridDim.x) {
        size_t base = (size_t)t * 128;
        for (int i = tid; i < 128 * 16; i += 512) {
            int r = i >> 4, kq = (i & 15) * 4;
            float4 v = *(const float4*)(EA + (base + r) * 64 + kq);
            float* p = EAs + r * XP64;
            p[kperm(kq)]     = to_tf32(v.x);
            p[kperm(kq + 1)] = to_tf32(v.y);
            p[kperm(kq + 2)] = to_tf32(v.z);
            p[kperm(kq + 3)] = to_tf32(v.w);
        }
        if (tid < 128)      src_s[tid] = esrc[base + tid];
        else if (tid < 256) dst_s[tid - 128] = edst[base + tid - 128];
        __syncthreads();
        float acc[8][4] = {};
        warp_gemm8<8>(EAs, XP64, W1t, XP64, m0, n0, acc);
#pragma unroll
        for (int nt = 0; nt < 8; nt++) {
            int cn = n0 + nt * 8 + 2 * tig;
            int p0 = kperm(cn), p1 = kperm(cn + 1);
            H1s[(m0 + g) * XP128 + p0]     = to_tf32(gelu_f(acc[nt][0] + b1s[cn]));
            H1s[(m0 + g) * XP128 + p1]     = to_tf32(gelu_f(acc[nt][1] + b1s[cn + 1]));
            H1s[(m0 + g + 8) * XP128 + p0] = to_tf32(gelu_f(acc[nt][2] + b1s[cn]));
            H1s[(m0 + g + 8) * XP128 + p1] = to_tf32(gelu_f(acc[nt][3] + b1s[cn + 1]));
        }
        __syncthreads();
        float acc2[8][4] = {};
        warp_gemm8<16>(H1s, XP128, W2t, XP128, m0, n0, acc2);
        {
            int r0 = m0 + g, r1 = m0 + g + 8;
            int dd0 = dst_s[r0], ss0 = src_s[r0];
            int dd1 = dst_s[r1], ss1 = src_s[r1];
            const float* hp0 = g_hmsg + (size_t)dd0 * 128;
            const float* hp1 = g_hmsg + (size_t)dd1 * 128;
            float* ap0 = g_agg + (size_t)ss0 * 128;
            float* ap1 = g_agg + (size_t)ss1 * 128;
#pragma unroll 4
            for (int nt = 0; nt < 8; nt++) {
                int cn = n0 + nt * 8 + 2 * tig;
                float2 h0 = *(const float2*)(hp0 + cn);
                float2 h1 = *(const float2*)(hp1 + cn);
                float2 m0v = make_float2(gelu_f(acc2[nt][0] + b2s[cn])     * h0.x,
                                         gelu_f(acc2[nt][1] + b2s[cn + 1]) * h0.y);
                float2 m1v = make_float2(gelu_f(acc2[nt][2] + b2s[cn])     * h1.x,
                                         gelu_f(acc2[nt][3] + b2s[cn + 1]) * h1.y);
                atomicAdd(reinterpret_cast<float2*>(ap0 + cn), m0v);
                atomicAdd(reinterpret_cast<float2*>(ap1 + cn), m1v);
            }
        }
        __syncthreads();
    }
}

// ============== update stage 1: [node_x | agg/cnt] @ upW1 (K=256), 512 thr ==============
#define SMU_TOT ((128 * XP256 + 128 * XP128 + 128) * 4)
__global__ void __launch_bounds__(512, 1)
up1_tc(const float* __restrict__ X, int tiles) {
    extern __shared__ float sm[];
    float* W1t = sm;                    // [n=128][k=256] pitch XP256
    float* Xs  = W1t + 128 * XP256;     // 128 x XP128
    float* b1s = Xs + 128 * XP128;
    const int tid = threadIdx.x, wid = tid >> 5, l = tid & 31, g = l >> 2, tig = l & 3;
    const int m0 = (wid >> 1) * 16, n0 = (wid & 1) * 64;
    for (int i = tid; i < 256 * 128; i += 512) { int k = i >> 7, n = i & 127; W1t[n * XP256 + kperm(k)] = to_tf32(g_upW1[i]); }
    if (tid < 128) b1s[tid] = g_upB1[tid];
    __syncthreads();
    for (int t = blockIdx.x; t < tiles; t += gridDim.x) {
        size_t base = (size_t)t * 128;
        for (int i = tid; i < 128 * 32; i += 512) {
            int r = i >> 5, kq = (i & 31) * 4;
            float4 v = *(const float4*)(X + (base + r) * 128 + kq);
            float* p = Xs + r * XP128;
            p[kperm(kq)]     = to_tf32(v.x);
            p[kperm(kq + 1)] = to_tf32(v.y);
            p[kperm(kq + 2)] = to_tf32(v.z);
            p[kperm(kq + 3)] = to_tf32(v.w);
        }
        __syncthreads();
        float acc[8][4] = {};
        warp_gemm8<16>(Xs, XP128, W1t, XP256, m0, n0, acc);
        __syncthreads();
        for (int i = tid; i < 128 * 32; i += 512) {
            int r = i >> 5, kq = (i & 31) * 4;
            float sc = 1.0f / fmaxf(g_cnt[base + r], 1.0f);
            float4 v = *(const float4*)(g_agg + (base + r) * 128 + kq);
            float* p = Xs + r * XP128;
            p[kperm(kq)]     = to_tf32(v.x * sc);
            p[kperm(kq + 1)] = to_tf32(v.y * sc);
            p[kperm(kq + 2)] = to_tf32(v.z * sc);
            p[kperm(kq + 3)] = to_tf32(v.w * sc);
        }
        __syncthreads();
        warp_gemm8<16>(Xs, XP128, W1t + 128, XP256, m0, n0, acc);
#pragma unroll
        for (int nt = 0; nt < 8; nt++) {
            int cn = n0 + nt * 8 + 2 * tig;
            float2 v0 = make_float2(gelu_f(acc[nt][0] + b1s[cn]), gelu_f(acc[nt][1] + b1s[cn + 1]));
            float2 v1 = make_float2(gelu_f(acc[nt][2] + b1s[cn]), gelu_f(acc[nt][3] + b1s[cn + 1]));
            *(float2*)(g_u1 + (base + m0 + g) * 128 + cn)     = v0;
            *(float2*)(g_u1 + (base + m0 + g + 8) * 128 + cn) = v1;
        }
        __syncthreads();
    }
}

// ============== update stage 2: g_u1 @ upW2 -> gelu -> out, 512 thr ==============
#define SMM_TOT ((2 * 128 * XP128 + 128) * 4)
__global__ void __launch_bounds__(512, 1)
mlp1_tc(float* __restrict__ out, int tiles) {
    extern __shared__ float sm[];
    float* Wt = sm;
    float* Xs = Wt + 128 * XP128;
    float* bs = Xs + 128 * XP128;
    const int tid = threadIdx.x, wid = tid >> 5, l = tid & 31, g = l >> 2, tig = l & 3;
    const int m0 = (wid >> 1) * 16, n0 = (wid & 1) * 64;
    for (int i = tid; i < 128 * 128; i += 512) { int k = i >> 7, n = i & 127; Wt[n * XP128 + kperm(k)] = to_tf32(g_upW2[i]); }
    if (tid < 128) bs[tid] = g_upB2[tid];
    __syncthreads();
    for (int t = blockIdx.x; t < tiles; t += gridDim.x) {
        size_t base = (size_t)t * 128;
        for (int i = tid; i < 128 * 32; i += 512) {
            int r = i >> 5, kq = (i & 31) * 4;
            float4 v = *(const float4*)(g_u1 + (base + r) * 128 + kq);
            float* p = Xs + r * XP128;
            p[kperm(kq)]     = to_tf32(v.x);
            p[kperm(kq + 1)] = to_tf32(v.y);
            p[kperm(kq + 2)] = to_tf32(v.z);
            p[kperm(kq + 3)] = to_tf32(v.w);
        }
        __syncthreads();
        float acc[8][4] = {};
        warp_gemm8<16>(Xs, XP128, Wt, XP128, m0, n0, acc);
#pragma unroll
        for (int nt = 0; nt < 8; nt++) {
            int cn = n0 + nt * 8 + 2 * tig;
            float2 v0 = make_float2(gelu_f(acc[nt][0] + bs[cn]), gelu_f(acc[nt][1] + bs[cn + 1]));
            float2 v1 = make_float2(gelu_f(acc[nt][2] + bs[cn]), gelu_f(acc[nt][3] + bs[cn + 1]));
            *(float2*)(out + (base + m0 + g) * 128 + cn)     = v0;
            *(float2*)(out + (base + m0 + g + 8) * 128 + cn) = v1;
        }
        __syncthreads();
    }
}

// ---------------- launch ----------------
extern "C" void kernel_launch(void* const* d_in, const int* in_sizes, int n_in,
                              void* d_out, int out_size) {
    const float* node_x = (const float*)d_in[0];
    const float* eattr  = (const float*)d_in[1];
    const float* bm_g1 = (const float*)d_in[2];
    const float* bm_b1 = (const float*)d_in[3];
    const float* bm_m1 = (const float*)d_in[4];
    const float* bm_v1 = (const float*)d_in[5];
    const float* bm_w1 = (const float*)d_in[6];
    const float* bm_bb1= (const float*)d_in[7];
    const float* bm_g2 = (const float*)d_in[8];
    const float* bm_b2 = (const float*)d_in[9];
    const float* bm_m2 = (const float*)d_in[10];
    const float* bm_v2 = (const float*)d_in[11];
    const float* bm_w2 = (const float*)d_in[12];
    const float* bm_bb2= (const float*)d_in[13];
    const float* et_w1 = (const float*)d_in[14];
    const float* et_b1 = (const float*)d_in[15];
    const float* et_w2 = (const float*)d_in[16];
    const float* et_b2 = (const float*)d_in[17];
    const float* up_g1 = (const float*)d_in[18];
    const float* up_b1 = (const float*)d_in[19];
    const float* up_m1 = (const float*)d_in[20];
    const float* up_v1 = (const float*)d_in[21];
    const float* up_w1 = (const float*)d_in[22];
    const float* up_bb1= (const float*)d_in[23];
    const float* up_g2 = (const float*)d_in[24];
    const float* up_b2 = (const float*)d_in[25];
    const float* up_m2 = (const float*)d_in[26];
    const float* up_v2 = (const float*)d_in[27];
    const float* up_w2 = (const float*)d_in[28];
    const float* up_bb2= (const float*)d_in[29];
    const int*   esrc  = (const int*)d_in[30];
    const int*   edst  = (const int*)d_in[31];
    float* out = (float*)d_out;

    cudaFuncSetAttribute(node_tc, cudaFuncAttributeMaxDynamicSharedMemorySize, SMN_TOT);
    cudaFuncSetAttribute(edge_tc, cudaFuncAttributeMaxDynamicSharedMemorySize, SME_TOT);
    cudaFuncSetAttribute(up1_tc,  cudaFuncAttributeMaxDynamicSharedMemorySize, SMU_TOT);
    cudaFuncSetAttribute(mlp1_tc, cudaFuncAttributeMaxDynamicSharedMemorySize, SMM_TOT);

    FoldArgs fa;
    fa.g[0] = bm_g1; fa.b[0] = bm_b1; fa.m[0] = bm_m1; fa.v[0] = bm_v1; fa.W[0] = bm_w1; fa.bb[0] = bm_bb1; fa.K[0] = DN;
    fa.g[1] = bm_g2; fa.b[1] = bm_b2; fa.m[1] = bm_m2; fa.v[1] = bm_v2; fa.W[1] = bm_w2; fa.bb[1] = bm_bb2; fa.K[1] = HH;
    fa.g[2] = up_g1; fa.b[2] = up_b1; fa.m[2] = up_m1; fa.v[2] = up_v1; fa.W[2] = up_w1; fa.bb[2] = up_bb1; fa.K[2] = DC;
    fa.g[3] = up_g2; fa.b[3] = up_b2; fa.m[3] = up_m2; fa.v[3] = up_v2; fa.W[3] = up_w2; fa.bb[3] = up_bb2; fa.K[3] = HH;
    fold_all<<<512, 256>>>(fa);

    zero_kernel<<<(NN * HH / 4 + 255) / 256, 256>>>();
    deg_kernel<<<(NE + 255) / 256, 256>>>(esrc);

    node_tc<<<148, 512, SMN_TOT>>>(node_x, NN / 128);
    edge_tc<<<148, 512, SME_TOT>>>(eattr, et_w1, et_b1, et_w2, et_b2, esrc, edst, NE / 128);
    up1_tc<<<148, 512, SMU_TOT>>>(node_x, NN / 128);
    mlp1_tc<<<148, 512, SMM_TOT>>>(out, NN / 128);
}

// round 15
// speedup vs baseline: 3.4445x; 1.1094x over previous
#include <cuda_runtime.h>
#include <math.h>
#include <stdint.h>

#define NN 65536
#define NE 524288
#define DN 128
#define DE 64
#define HH 128
#define DC (DN + HH)
#define EPSbn 1e-3f

// pitches (floats), all == 8 mod 32 for conflict-free LDS.64 fragment loads
#define XP128 136
#define XP64  72
#define XP256 264

// ---------------- scratch ----------------
__device__ float g_hmsg[(size_t)NN * HH];
__device__ float g_agg [(size_t)NN * HH];
__device__ float g_u1  [(size_t)NN * HH];
__device__ float g_cnt [NN];

__device__ float g_bmW1[DN * HH]; __device__ float g_bmB1[HH];
__device__ float g_bmW2[HH * HH]; __device__ float g_bmB2[HH];
__device__ float g_upW1[DC * HH]; __device__ float g_upB1[HH];
__device__ float g_upW2[HH * HH]; __device__ float g_upB2[HH];

// fast exact-enough gelu: 0.5*x*(1+erf(x/sqrt2)), erf via A&S 7.1.26 (|err|<1.5e-7)
__device__ __forceinline__ float gelu_f(float x) {
    float z  = x * 0.70710678118654752f;
    float az = fabsf(z);
    float t;
    asm("rcp.approx.f32 %0, %1;" : "=f"(t) : "f"(fmaf(0.3275911f, az, 1.0f)));
    float p = fmaf(1.061405429f, t, -1.453152027f);
    p = fmaf(p, t, 1.421413741f);
    p = fmaf(p, t, -0.284496736f);
    p = fmaf(p, t, 0.254829592f);
    p = p * t;
    float e = __expf(-z * z);
    float erfa = fmaf(-p, e, 1.0f);
    float erfz = copysignf(erfa, z);
    return 0.5f * x * (1.0f + erfz);
}

// tf32 round
__device__ __forceinline__ float to_tf32(float x) {
    uint32_t r; asm("cvt.rna.tf32.f32 %0, %1;" : "=r"(r) : "f"(x));
    return __uint_as_float(r);
}

// k-permutation within each 8-block: pairs (k, k+4) land adjacent -> LDS.64 fragments
__device__ __forceinline__ int kperm(int k) {
    return (k & ~7) | ((k & 3) << 1) | ((k >> 2) & 1);
}

// ---------------- warp-level tf32 MMA GEMM (16 rows x 32 cols), LDS.64 fragments ----------------
// Xs rows are k-permuted; Wt rows ([n][k]) are k-permuted. Pitches xp/wp == 8 mod 32.
template<int KT>
__device__ __forceinline__ void warp_gemm4(const float* __restrict__ Xs, int xp,
                                           const float* __restrict__ Wt, int wp,
                                           int m0, int n0, float (&acc)[4][4]) {
    const int l = threadIdx.x & 31, g = l >> 2, tig = l & 3;
    const float2* xr0 = (const float2*)(Xs + (m0 + g) * xp) + tig;
    const float2* xr1 = (const float2*)(Xs + (m0 + g + 8) * xp) + tig;
    const float2* wb  = (const float2*)(Wt + (n0 + g) * wp) + tig;
    const int wp2 = wp >> 1;
#pragma unroll 2
    for (int s = 0; s < KT; s++) {
        const int k2 = 4 * s;
        float2 A0 = xr0[k2];
        float2 A1 = xr1[k2];
#pragma unroll
        for (int nt = 0; nt < 4; nt++) {
            float2 B = wb[nt * 8 * wp2 + k2];
            asm volatile(
                "mma.sync.aligned.m16n8k8.row.col.f32.tf32.tf32.f32 "
                "{%0,%1,%2,%3}, {%4,%5,%6,%7}, {%8,%9}, {%0,%1,%2,%3};"
                : "+f"(acc[nt][0]), "+f"(acc[nt][1]), "+f"(acc[nt][2]), "+f"(acc[nt][3])
                : "r"(__float_as_uint(A0.x)), "r"(__float_as_uint(A1.x)),
                  "r"(__float_as_uint(A0.y)), "r"(__float_as_uint(A1.y)),
                  "r"(__float_as_uint(B.x)),  "r"(__float_as_uint(B.y)));
        }
    }
}

// ---------------- BN folding (all four in one launch) ----------------
struct FoldArgs {
    const float* g[4]; const float* b[4]; const float* m[4]; const float* v[4];
    const float* W[4]; const float* bb[4]; int K[4];
};

__global__ void fold_all(FoldArgs a) {
    const int which = blockIdx.x >> 7;
    const int j = blockIdx.x & 127;
    float* Wo; float* Bo;
    if      (which == 0) { Wo = g_bmW1; Bo = g_bmB1; }
    else if (which == 1) { Wo = g_bmW2; Bo = g_bmB2; }
    else if (which == 2) { Wo = g_upW1; Bo = g_upB1; }
    else                 { Wo = g_upW2; Bo = g_upB2; }
    const float* g = a.g[which]; const float* b = a.b[which];
    const float* m = a.m[which]; const float* v = a.v[which];
    const float* W = a.W[which]; const float* bb = a.bb[which];
    const int K = a.K[which];
    __shared__ float red[256];
    int tid = threadIdx.x;
    float acc = 0.f;
    for (int i = tid; i < K; i += 256) {
        float s = g[i] * rsqrtf(v[i] + EPSbn);
        float t = b[i] - m[i] * s;
        float w = W[i * HH + j];
        Wo[i * HH + j] = s * w;
        acc += t * w;
    }
    red[tid] = acc; __syncthreads();
    for (int o = 128; o > 0; o >>= 1) { if (tid < o) red[tid] += red[tid + o]; __syncthreads(); }
    if (tid == 0) Bo[j] = bb[j] + red[0];
}

__global__ void zero_kernel() {
    int i = blockIdx.x * blockDim.x + threadIdx.x;
    if (i < NN * HH / 4) ((float4*)g_agg)[i] = make_float4(0.f, 0.f, 0.f, 0.f);
    if (i < NN / 4)      ((float4*)g_cnt)[i] = make_float4(0.f, 0.f, 0.f, 0.f);
}

__global__ void deg_kernel(const int* __restrict__ src) {
    int i = blockIdx.x * blockDim.x + threadIdx.x;
    if (i < NE) atomicAdd(&g_cnt[src[i]], 1.0f);
}

// ============== node base-message MLP: two fused 128x128 GEMMs, 1024 thr (32 warps) ==============
#define SMN_TOT ((3 * 128 * XP128 + 256) * 4)
__global__ void __launch_bounds__(1024, 1)
node_tc(const float* __restrict__ X, int tiles) {
    extern __shared__ float sm[];
    float* W1t = sm;
    float* W2t = W1t + 128 * XP128;
    float* Xs  = W2t + 128 * XP128;
    float* b1s = Xs + 128 * XP128;
    float* b2s = b1s + 128;
    const int tid = threadIdx.x, wid = tid >> 5, l = tid & 31, g = l >> 2, tig = l & 3;
    const int m0 = (wid >> 2) * 16, n0 = (wid & 3) * 32;
    for (int i = tid; i < 128 * 128; i += 1024) {
        int k = i >> 7, n = i & 127;
        W1t[n * XP128 + kperm(k)] = to_tf32(g_bmW1[i]);
        W2t[n * XP128 + kperm(k)] = to_tf32(g_bmW2[i]);
    }
    if (tid < 128) { b1s[tid] = g_bmB1[tid]; b2s[tid] = g_bmB2[tid]; }
    __syncthreads();
    for (int t = blockIdx.x; t < tiles; t += gridDim.x) {
        size_t base = (size_t)t * 128;
        for (int i = tid; i < 128 * 32; i += 1024) {
            int r = i >> 5, kq = (i & 31) * 4;
            float4 v = *(const float4*)(X + (base + r) * 128 + kq);
            float* p = Xs + r * XP128;
            p[kperm(kq)]     = to_tf32(v.x);
            p[kperm(kq + 1)] = to_tf32(v.y);
            p[kperm(kq + 2)] = to_tf32(v.z);
            p[kperm(kq + 3)] = to_tf32(v.w);
        }
        __syncthreads();
        float acc[4][4] = {};
        warp_gemm4<16>(Xs, XP128, W1t, XP128, m0, n0, acc);
        __syncthreads();
#pragma unroll
        for (int nt = 0; nt < 4; nt++) {
            int cn = n0 + nt * 8 + 2 * tig;
            int p0 = kperm(cn), p1 = kperm(cn + 1);
            Xs[(m0 + g) * XP128 + p0]     = to_tf32(gelu_f(acc[nt][0] + b1s[cn]));
            Xs[(m0 + g) * XP128 + p1]     = to_tf32(gelu_f(acc[nt][1] + b1s[cn + 1]));
            Xs[(m0 + g + 8) * XP128 + p0] = to_tf32(gelu_f(acc[nt][2] + b1s[cn]));
            Xs[(m0 + g + 8) * XP128 + p1] = to_tf32(gelu_f(acc[nt][3] + b1s[cn + 1]));
        }
        __syncthreads();
        float acc2[4][4] = {};
        warp_gemm4<16>(Xs, XP128, W2t, XP128, m0, n0, acc2);
#pragma unroll
        for (int nt = 0; nt < 4; nt++) {
            int cn = n0 + nt * 8 + 2 * tig;
            float2 v0 = make_float2(gelu_f(acc2[nt][0] + b2s[cn]), gelu_f(acc2[nt][1] + b2s[cn + 1]));
            float2 v1 = make_float2(gelu_f(acc2[nt][2] + b2s[cn]), gelu_f(acc2[nt][3] + b2s[cn + 1]));
            *(float2*)(g_hmsg + (base + m0 + g) * 128 + cn)     = v0;
            *(float2*)(g_hmsg + (base + m0 + g + 8) * 128 + cn) = v1;
        }
        __syncthreads();
    }
}

// ============== edge kernel: e-MLP + gather + float2 atomic scatter, 1024 thr ==============
#define SME_TOT ((2 * 128 * XP64 + 2 * 128 * XP128 + 256) * 4 + 256 * 4)
__global__ void __launch_bounds__(1024, 1)
edge_tc(const float* __restrict__ EA,
        const float* __restrict__ W1, const float* __restrict__ B1,
        const float* __restrict__ W2, const float* __restrict__ B2,
        const int* __restrict__ esrc, const int* __restrict__ edst, int tiles) {
    extern __shared__ float sm[];
    float* W1t = sm;                         // 128 x XP64
    float* EAs = W1t + 128 * XP64;           // 128 x XP64
    float* W2t = EAs + 128 * XP64;           // 128 x XP128
    float* H1s = W2t + 128 * XP128;          // 128 x XP128
    float* b1s = H1s + 128 * XP128;
    float* b2s = b1s + 128;
    int* src_s = (int*)(b2s + 128);
    int* dst_s = src_s + 128;
    const int tid = threadIdx.x, wid = tid >> 5, l = tid & 31, g = l >> 2, tig = l & 3;
    const int m0 = (wid >> 2) * 16, n0 = (wid & 3) * 32;
    for (int i = tid; i < 64 * 128; i += 1024) { int k = i >> 7, n = i & 127; W1t[n * XP64 + kperm(k)] = to_tf32(W1[i]); }
    for (int i = tid; i < 128 * 128; i += 1024) { int k = i >> 7, n = i & 127; W2t[n * XP128 + kperm(k)] = to_tf32(W2[i]); }
    if (tid < 128) { b1s[tid] = B1[tid]; b2s[tid] = B2[tid]; }
    __syncthreads();
    for (int t = blockIdx.x; t < tiles; t += gridDim.x) {
        size_t base = (size_t)t * 128;
        for (int i = tid; i < 128 * 16; i += 1024) {
            int r = i >> 4, kq = (i & 15) * 4;
            float4 v = *(const float4*)(EA + (base + r) * 64 + kq);
            float* p = EAs + r * XP64;
            p[kperm(kq)]     = to_tf32(v.x);
            p[kperm(kq + 1)] = to_tf32(v.y);
            p[kperm(kq + 2)] = to_tf32(v.z);
            p[kperm(kq + 3)] = to_tf32(v.w);
        }
        if (tid < 128)      src_s[tid] = esrc[base + tid];
        else if (tid < 256) dst_s[tid - 128] = edst[base + tid - 128];
        __syncthreads();
        float acc[4][4] = {};
        warp_gemm4<8>(EAs, XP64, W1t, XP64, m0, n0, acc);
#pragma unroll
        for (int nt = 0; nt < 4; nt++) {
            int cn = n0 + nt * 8 + 2 * tig;
            int p0 = kperm(cn), p1 = kperm(cn + 1);
            H1s[(m0 + g) * XP128 + p0]     = to_tf32(gelu_f(acc[nt][0] + b1s[cn]));
            H1s[(m0 + g) * XP128 + p1]     = to_tf32(gelu_f(acc[nt][1] + b1s[cn + 1]));
            H1s[(m0 + g + 8) * XP128 + p0] = to_tf32(gelu_f(acc[nt][2] + b1s[cn]));
            H1s[(m0 + g + 8) * XP128 + p1] = to_tf32(gelu_f(acc[nt][3] + b1s[cn + 1]));
        }
        __syncthreads();
        float acc2[4][4] = {};
        warp_gemm4<16>(H1s, XP128, W2t, XP128, m0, n0, acc2);
        {
            int r0 = m0 + g, r1 = m0 + g + 8;
            int dd0 = dst_s[r0], ss0 = src_s[r0];
            int dd1 = dst_s[r1], ss1 = src_s[r1];
            const float* hp0 = g_hmsg + (size_t)dd0 * 128;
            const float* hp1 = g_hmsg + (size_t)dd1 * 128;
            float* ap0 = g_agg + (size_t)ss0 * 128;
            float* ap1 = g_agg + (size_t)ss1 * 128;
#pragma unroll
            for (int nt = 0; nt < 4; nt++) {
                int cn = n0 + nt * 8 + 2 * tig;
                float2 h0 = *(const float2*)(hp0 + cn);
                float2 h1 = *(const float2*)(hp1 + cn);
                float2 m0v = make_float2(gelu_f(acc2[nt][0] + b2s[cn])     * h0.x,
                                         gelu_f(acc2[nt][1] + b2s[cn + 1]) * h0.y);
                float2 m1v = make_float2(gelu_f(acc2[nt][2] + b2s[cn])     * h1.x,
                                         gelu_f(acc2[nt][3] + b2s[cn + 1]) * h1.y);
                atomicAdd(reinterpret_cast<float2*>(ap0 + cn), m0v);
                atomicAdd(reinterpret_cast<float2*>(ap1 + cn), m1v);
            }
        }
        __syncthreads();
    }
}

// ============== update stage 1: [node_x | agg/cnt] @ upW1 (K=256), 1024 thr ==============
#define SMU_TOT ((128 * XP256 + 128 * XP128 + 128) * 4)
__global__ void __launch_bounds__(1024, 1)
up1_tc(const float* __restrict__ X, int tiles) {
    extern __shared__ float sm[];
    float* W1t = sm;                    // [n=128][k=256] pitch XP256
    float* Xs  = W1t + 128 * XP256;     // 128 x XP128
    float* b1s = Xs + 128 * XP128;
    const int tid = threadIdx.x, wid = tid >> 5, l = tid & 31, g = l >> 2, tig = l & 3;
    const int m0 = (wid >> 2) * 16, n0 = (wid & 3) * 32;
    for (int i = tid; i < 256 * 128; i += 1024) { int k = i >> 7, n = i & 127; W1t[n * XP256 + kperm(k)] = to_tf32(g_upW1[i]); }
    if (tid < 128) b1s[tid] = g_upB1[tid];
    __syncthreads();
    for (int t = blockIdx.x; t < tiles; t += gridDim.x) {
        size_t base = (size_t)t * 128;
        for (int i = tid; i < 128 * 32; i += 1024) {
            int r = i >> 5, kq = (i & 31) * 4;
            float4 v = *(const float4*)(X + (base + r) * 128 + kq);
            float* p = Xs + r * XP128;
            p[kperm(kq)]     = to_tf32(v.x);
            p[kperm(kq + 1)] = to_tf32(v.y);
            p[kperm(kq + 2)] = to_tf32(v.z);
            p[kperm(kq + 3)] = to_tf32(v.w);
        }
        __syncthreads();
        float acc[4][4] = {};
        warp_gemm4<16>(Xs, XP128, W1t, XP256, m0, n0, acc);
        __syncthreads();
        for (int i = tid; i < 128 * 32; i += 1024) {
            int r = i >> 5, kq = (i & 31) * 4;
            float sc = 1.0f / fmaxf(g_cnt[base + r], 1.0f);
            float4 v = *(const float4*)(g_agg + (base + r) * 128 + kq);
            float* p = Xs + r * XP128;
            p[kperm(kq)]     = to_tf32(v.x * sc);
            p[kperm(kq + 1)] = to_tf32(v.y * sc);
            p[kperm(kq + 2)] = to_tf32(v.z * sc);
            p[kperm(kq + 3)] = to_tf32(v.w * sc);
        }
        __syncthreads();
        warp_gemm4<16>(Xs, XP128, W1t + 128, XP256, m0, n0, acc);
#pragma unroll
        for (int nt = 0; nt < 4; nt++) {
            int cn = n0 + nt * 8 + 2 * tig;
            float2 v0 = make_float2(gelu_f(acc[nt][0] + b1s[cn]), gelu_f(acc[nt][1] + b1s[cn + 1]));
            float2 v1 = make_float2(gelu_f(acc[nt][2] + b1s[cn]), gelu_f(acc[nt][3] + b1s[cn + 1]));
            *(float2*)(g_u1 + (base + m0 + g) * 128 + cn)     = v0;
            *(float2*)(g_u1 + (base + m0 + g + 8) * 128 + cn) = v1;
        }
        __syncthreads();
    }
}

// ============== update stage 2: g_u1 @ upW2 -> gelu -> out, 1024 thr ==============
#define SMM_TOT ((2 * 128 * XP128 + 128) * 4)
__global__ void __launch_bounds__(1024, 1)
mlp1_tc(float* __restrict__ out, int tiles) {
    extern __shared__ float sm[];
    float* Wt = sm;
    float* Xs = Wt + 128 * XP128;
    float* bs = Xs + 128 * XP128;
    const int tid = threadIdx.x, wid = tid >> 5, l = tid & 31, g = l >> 2, tig = l & 3;
    const int m0 = (wid >> 2) * 16, n0 = (wid & 3) * 32;
    for (int i = tid; i < 128 * 128; i += 1024) { int k = i >> 7, n = i & 127; Wt[n * XP128 + kperm(k)] = to_tf32(g_upW2[i]); }
    if (tid < 128) bs[tid] = g_upB2[tid];
    __syncthreads();
    for (int t = blockIdx.x; t < tiles; t += gridDim.x) {
        size_t base = (size_t)t * 128;
        for (int i = tid; i < 128 * 32; i += 1024) {
            int r = i >> 5, kq = (i & 31) * 4;
            float4 v = *(const float4*)(g_u1 + (base + r) * 128 + kq);
            float* p = Xs + r * XP128;
            p[kperm(kq)]     = to_tf32(v.x);
            p[kperm(kq + 1)] = to_tf32(v.y);
            p[kperm(kq + 2)] = to_tf32(v.z);
            p[kperm(kq + 3)] = to_tf32(v.w);
        }
        __syncthreads();
        float acc[4][4] = {};
        warp_gemm4<16>(Xs, XP128, Wt, XP128, m0, n0, acc);
#pragma unroll
        for (int nt = 0; nt < 4; nt++) {
            int cn = n0 + nt * 8 + 2 * tig;
            float2 v0 = make_float2(gelu_f(acc[nt][0] + bs[cn]), gelu_f(acc[nt][1] + bs[cn + 1]));
            float2 v1 = make_float2(gelu_f(acc[nt][2] + bs[cn]), gelu_f(acc[nt][3] + bs[cn + 1]));
            *(float2*)(out + (base + m0 + g) * 128 + cn)     = v0;
            *(float2*)(out + (base + m0 + g + 8) * 128 + cn) = v1;
        }
        __syncthreads();
    }
}

// ---------------- launch ----------------
extern "C" void kernel_launch(void* const* d_in, const int* in_sizes, int n_in,
                              void* d_out, int out_size) {
    const float* node_x = (const float*)d_in[0];
    const float* eattr  = (const float*)d_in[1];
    const float* bm_g1 = (const float*)d_in[2];
    const float* bm_b1 = (const float*)d_in[3];
    const float* bm_m1 = (const float*)d_in[4];
    const float* bm_v1 = (const float*)d_in[5];
    const float* bm_w1 = (const float*)d_in[6];
    const float* bm_bb1= (const float*)d_in[7];
    const float* bm_g2 = (const float*)d_in[8];
    const float* bm_b2 = (const float*)d_in[9];
    const float* bm_m2 = (const float*)d_in[10];
    const float* bm_v2 = (const float*)d_in[11];
    const float* bm_w2 = (const float*)d_in[12];
    const float* bm_bb2= (const float*)d_in[13];
    const float* et_w1 = (const float*)d_in[14];
    const float* et_b1 = (const float*)d_in[15];
    const float* et_w2 = (const float*)d_in[16];
    const float* et_b2 = (const float*)d_in[17];
    const float* up_g1 = (const float*)d_in[18];
    const float* up_b1 = (const float*)d_in[19];
    const float* up_m1 = (const float*)d_in[20];
    const float* up_v1 = (const float*)d_in[21];
    const float* up_w1 = (const float*)d_in[22];
    const float* up_bb1= (const float*)d_in[23];
    const float* up_g2 = (const float*)d_in[24];
    const float* up_b2 = (const float*)d_in[25];
    const float* up_m2 = (const float*)d_in[26];
    const float* up_v2 = (const float*)d_in[27];
    const float* up_w2 = (const float*)d_in[28];
    const float* up_bb2= (const float*)d_in[29];
    const int*   esrc  = (const int*)d_in[30];
    const int*   edst  = (const int*)d_in[31];
    float* out = (float*)d_out;

    cudaFuncSetAttribute(node_tc, cudaFuncAttributeMaxDynamicSharedMemorySize, SMN_TOT);
    cudaFuncSetAttribute(edge_tc, cudaFuncAttributeMaxDynamicSharedMemorySize, SME_TOT);
    cudaFuncSetAttribute(up1_tc,  cudaFuncAttributeMaxDynamicSharedMemorySize, SMU_TOT);
    cudaFuncSetAttribute(mlp1_tc, cudaFuncAttributeMaxDynamicSharedMemorySize, SMM_TOT);

    FoldArgs fa;
    fa.g[0] = bm_g1; fa.b[0] = bm_b1; fa.m[0] = bm_m1; fa.v[0] = bm_v1; fa.W[0] = bm_w1; fa.bb[0] = bm_bb1; fa.K[0] = DN;
    fa.g[1] = bm_g2; fa.b[1] = bm_b2; fa.m[1] = bm_m2; fa.v[1] = bm_v2; fa.W[1] = bm_w2; fa.bb[1] = bm_bb2; fa.K[1] = HH;
    fa.g[2] = up_g1; fa.b[2] = up_b1; fa.m[2] = up_m1; fa.v[2] = up_v1; fa.W[2] = up_w1; fa.bb[2] = up_bb1; fa.K[2] = DC;
    fa.g[3] = up_g2; fa.b[3] = up_b2; fa.m[3] = up_m2; fa.v[3] = up_v2; fa.W[3] = up_w2; fa.bb[3] = up_bb2; fa.K[3] = HH;
    fold_all<<<512, 256>>>(fa);

    zero_kernel<<<(NN * HH / 4 + 255) / 256, 256>>>();
    deg_kernel<<<(NE + 255) / 256, 256>>>(esrc);

    node_tc<<<148, 1024, SMN_TOT>>>(node_x, NN / 128);
    edge_tc<<<148, 1024, SME_TOT>>>(eattr, et_w1, et_b1, et_w2, et_b2, esrc, edst, NE / 128);
    up1_tc<<<148, 1024, SMU_TOT>>>(node_x, NN / 128);
    mlp1_tc<<<148, 1024, SMM_TOT>>>(out, NN / 128);
}

// round 16
// speedup vs baseline: 3.4617x; 1.0050x over previous
#include <cuda_runtime.h>
#include <math.h>
#include <stdint.h>

#define NN 65536
#define NE 524288
#define DN 128
#define DE 64
#define HH 128
#define DC (DN + HH)
#define EPSbn 1e-3f

// pitches (floats), all == 8 mod 32 for conflict-free LDS.64 fragment loads
#define XP128 136
#define XP64  72
#define XP256 264

// ---------------- scratch ----------------
__device__ float g_hmsg[(size_t)NN * HH];
__device__ float g_agg [(size_t)NN * HH];
__device__ float g_u1  [(size_t)NN * HH];
__device__ float g_cnt [NN];

__device__ float g_bmW1[DN * HH]; __device__ float g_bmB1[HH];
__device__ float g_bmW2[HH * HH]; __device__ float g_bmB2[HH];
__device__ float g_upW1[DC * HH]; __device__ float g_upB1[HH];
__device__ float g_upW2[HH * HH]; __device__ float g_upB2[HH];

// fast exact-enough gelu: 0.5*x*(1+erf(x/sqrt2)), erf via A&S 7.1.26 (|err|<1.5e-7)
__device__ __forceinline__ float gelu_f(float x) {
    float z  = x * 0.70710678118654752f;
    float az = fabsf(z);
    float t;
    asm("rcp.approx.f32 %0, %1;" : "=f"(t) : "f"(fmaf(0.3275911f, az, 1.0f)));
    float p = fmaf(1.061405429f, t, -1.453152027f);
    p = fmaf(p, t, 1.421413741f);
    p = fmaf(p, t, -0.284496736f);
    p = fmaf(p, t, 0.254829592f);
    p = p * t;
    float e = __expf(-z * z);
    float erfa = fmaf(-p, e, 1.0f);
    float erfz = copysignf(erfa, z);
    return 0.5f * x * (1.0f + erfz);
}

// tf32 round
__device__ __forceinline__ float to_tf32(float x) {
    uint32_t r; asm("cvt.rna.tf32.f32 %0, %1;" : "=r"(r) : "f"(x));
    return __uint_as_float(r);
}

// k-permutation within each 8-block: pairs (k, k+4) land adjacent -> LDS.64 fragments
__device__ __forceinline__ int kperm(int k) {
    return (k & ~7) | ((k & 3) << 1) | ((k >> 2) & 1);
}

// ---------------- warp-level tf32 MMA GEMM (16 rows x 32 cols), LDS.64 fragments ----------------
template<int KT>
__device__ __forceinline__ void warp_gemm4(const float* __restrict__ Xs, int xp,
                                           const float* __restrict__ Wt, int wp,
                                           int m0, int n0, float (&acc)[4][4]) {
    const int l = threadIdx.x & 31, g = l >> 2, tig = l & 3;
    const float2* xr0 = (const float2*)(Xs + (m0 + g) * xp) + tig;
    const float2* xr1 = (const float2*)(Xs + (m0 + g + 8) * xp) + tig;
    const float2* wb  = (const float2*)(Wt + (n0 + g) * wp) + tig;
    const int wp2 = wp >> 1;
#pragma unroll 4
    for (int s = 0; s < KT; s++) {
        const int k2 = 4 * s;
        float2 A0 = xr0[k2];
        float2 A1 = xr1[k2];
#pragma unroll
        for (int nt = 0; nt < 4; nt++) {
            float2 B = wb[nt * 8 * wp2 + k2];
            asm volatile(
                "mma.sync.aligned.m16n8k8.row.col.f32.tf32.tf32.f32 "
                "{%0,%1,%2,%3}, {%4,%5,%6,%7}, {%8,%9}, {%0,%1,%2,%3};"
                : "+f"(acc[nt][0]), "+f"(acc[nt][1]), "+f"(acc[nt][2]), "+f"(acc[nt][3])
                : "r"(__float_as_uint(A0.x)), "r"(__float_as_uint(A1.x)),
                  "r"(__float_as_uint(A0.y)), "r"(__float_as_uint(A1.y)),
                  "r"(__float_as_uint(B.x)),  "r"(__float_as_uint(B.y)));
        }
    }
}

// ---------------- BN folding + scratch zeroing, one launch ----------------
// blocks [0,512): fold the 4 weight matrices; blocks [512, 512+8192): zero g_agg/g_cnt
struct FoldArgs {
    const float* g[4]; const float* b[4]; const float* m[4]; const float* v[4];
    const float* W[4]; const float* bb[4]; int K[4];
};

#define ZBLOCKS (NN * HH / 4 / 256)   // 8192

__global__ void fold_all(FoldArgs a) {
    const int tid = threadIdx.x;
    if (blockIdx.x >= 512) {
        int i = (blockIdx.x - 512) * 256 + tid;
        if (i < NN * HH / 4) ((float4*)g_agg)[i] = make_float4(0.f, 0.f, 0.f, 0.f);
        if (i < NN / 4)      ((float4*)g_cnt)[i] = make_float4(0.f, 0.f, 0.f, 0.f);
        return;
    }
    const int which = blockIdx.x >> 7;
    const int j = blockIdx.x & 127;
    float* Wo; float* Bo;
    if      (which == 0) { Wo = g_bmW1; Bo = g_bmB1; }
    else if (which == 1) { Wo = g_bmW2; Bo = g_bmB2; }
    else if (which == 2) { Wo = g_upW1; Bo = g_upB1; }
    else                 { Wo = g_upW2; Bo = g_upB2; }
    const float* g = a.g[which]; const float* b = a.b[which];
    const float* m = a.m[which]; const float* v = a.v[which];
    const float* W = a.W[which]; const float* bb = a.bb[which];
    const int K = a.K[which];
    __shared__ float red[256];
    float acc = 0.f;
    for (int i = tid; i < K; i += 256) {
        float s = g[i] * rsqrtf(v[i] + EPSbn);
        float t = b[i] - m[i] * s;
        float w = W[i * HH + j];
        Wo[i * HH + j] = s * w;
        acc += t * w;
    }
    red[tid] = acc; __syncthreads();
    for (int o = 128; o > 0; o >>= 1) { if (tid < o) red[tid] += red[tid + o]; __syncthreads(); }
    if (tid == 0) Bo[j] = bb[j] + red[0];
}

__global__ void deg_kernel(const int* __restrict__ src) {
    int i = blockIdx.x * blockDim.x + threadIdx.x;
    if (i < NE) atomicAdd(&g_cnt[src[i]], 1.0f);
}

// ============== node base-message MLP: two fused 128x128 GEMMs, 1024 thr (32 warps) ==============
#define SMN_TOT ((3 * 128 * XP128 + 256) * 4)
__global__ void __launch_bounds__(1024, 1)
node_tc(const float* __restrict__ X, int tiles) {
    extern __shared__ float sm[];
    float* W1t = sm;
    float* W2t = W1t + 128 * XP128;
    float* Xs  = W2t + 128 * XP128;
    float* b1s = Xs + 128 * XP128;
    float* b2s = b1s + 128;
    const int tid = threadIdx.x, wid = tid >> 5, l = tid & 31, g = l >> 2, tig = l & 3;
    const int m0 = (wid >> 2) * 16, n0 = (wid & 3) * 32;
    for (int i = tid; i < 128 * 128; i += 1024) {
        int k = i >> 7, n = i & 127;
        W1t[n * XP128 + kperm(k)] = to_tf32(g_bmW1[i]);
        W2t[n * XP128 + kperm(k)] = to_tf32(g_bmW2[i]);
    }
    if (tid < 128) { b1s[tid] = g_bmB1[tid]; b2s[tid] = g_bmB2[tid]; }
    __syncthreads();
    for (int t = blockIdx.x; t < tiles; t += gridDim.x) {
        size_t base = (size_t)t * 128;
        for (int i = tid; i < 128 * 32; i += 1024) {
            int r = i >> 5, kq = (i & 31) * 4;
            float4 v = *(const float4*)(X + (base + r) * 128 + kq);
            float* p = Xs + r * XP128;
            p[kperm(kq)]     = to_tf32(v.x);
            p[kperm(kq + 1)] = to_tf32(v.y);
            p[kperm(kq + 2)] = to_tf32(v.z);
            p[kperm(kq + 3)] = to_tf32(v.w);
        }
        __syncthreads();
        float acc[4][4] = {};
        warp_gemm4<16>(Xs, XP128, W1t, XP128, m0, n0, acc);
        __syncthreads();
#pragma unroll
        for (int nt = 0; nt < 4; nt++) {
            int cn = n0 + nt * 8 + 2 * tig;
            int p0 = kperm(cn), p1 = kperm(cn + 1);
            Xs[(m0 + g) * XP128 + p0]     = to_tf32(gelu_f(acc[nt][0] + b1s[cn]));
            Xs[(m0 + g) * XP128 + p1]     = to_tf32(gelu_f(acc[nt][1] + b1s[cn + 1]));
            Xs[(m0 + g + 8) * XP128 + p0] = to_tf32(gelu_f(acc[nt][2] + b1s[cn]));
            Xs[(m0 + g + 8) * XP128 + p1] = to_tf32(gelu_f(acc[nt][3] + b1s[cn + 1]));
        }
        __syncthreads();
        float acc2[4][4] = {};
        warp_gemm4<16>(Xs, XP128, W2t, XP128, m0, n0, acc2);
#pragma unroll
        for (int nt = 0; nt < 4; nt++) {
            int cn = n0 + nt * 8 + 2 * tig;
            float2 v0 = make_float2(gelu_f(acc2[nt][0] + b2s[cn]), gelu_f(acc2[nt][1] + b2s[cn + 1]));
            float2 v1 = make_float2(gelu_f(acc2[nt][2] + b2s[cn]), gelu_f(acc2[nt][3] + b2s[cn + 1]));
            *(float2*)(g_hmsg + (base + m0 + g) * 128 + cn)     = v0;
            *(float2*)(g_hmsg + (base + m0 + g + 8) * 128 + cn) = v1;
        }
        __syncthreads();
    }
}

// ============== edge kernel: e-MLP + gather + float2 atomic scatter, 1024 thr ==============
#define SME_TOT ((2 * 128 * XP64 + 2 * 128 * XP128 + 256) * 4 + 256 * 4)
__global__ void __launch_bounds__(1024, 1)
edge_tc(const float* __restrict__ EA,
        const float* __restrict__ W1, const float* __restrict__ B1,
        const float* __restrict__ W2, const float* __restrict__ B2,
        const int* __restrict__ esrc, const int* __restrict__ edst, int tiles) {
    extern __shared__ float sm[];
    float* W1t = sm;                         // 128 x XP64
    float* EAs = W1t + 128 * XP64;           // 128 x XP64
    float* W2t = EAs + 128 * XP64;           // 128 x XP128
    float* H1s = W2t + 128 * XP128;          // 128 x XP128
    float* b1s = H1s + 128 * XP128;
    float* b2s = b1s + 128;
    int* src_s = (int*)(b2s + 128);
    int* dst_s = src_s + 128;
    const int tid = threadIdx.x, wid = tid >> 5, l = tid & 31, g = l >> 2, tig = l & 3;
    const int m0 = (wid >> 2) * 16, n0 = (wid & 3) * 32;
    for (int i = tid; i < 64 * 128; i += 1024) { int k = i >> 7, n = i & 127; W1t[n * XP64 + kperm(k)] = to_tf32(W1[i]); }
    for (int i = tid; i < 128 * 128; i += 1024) { int k = i >> 7, n = i & 127; W2t[n * XP128 + kperm(k)] = to_tf32(W2[i]); }
    if (tid < 128) { b1s[tid] = B1[tid]; b2s[tid] = B2[tid]; }
    __syncthreads();
    for (int t = blockIdx.x; t < tiles; t += gridDim.x) {
        size_t base = (size_t)t * 128;
        for (int i = tid; i < 128 * 16; i += 1024) {
            int r = i >> 4, kq = (i & 15) * 4;
            float4 v = *(const float4*)(EA + (base + r) * 64 + kq);
            float* p = EAs + r * XP64;
            p[kperm(kq)]     = to_tf32(v.x);
            p[kperm(kq + 1)] = to_tf32(v.y);
            p[kperm(kq + 2)] = to_tf32(v.z);
            p[kperm(kq + 3)] = to_tf32(v.w);
        }
        if (tid < 128)      src_s[tid] = esrc[base + tid];
        else if (tid < 256) dst_s[tid - 128] = edst[base + tid - 128];
        __syncthreads();
        float acc[4][4] = {};
        warp_gemm4<8>(EAs, XP64, W1t, XP64, m0, n0, acc);
#pragma unroll
        for (int nt = 0; nt < 4; nt++) {
            int cn = n0 + nt * 8 + 2 * tig;
            int p0 = kperm(cn), p1 = kperm(cn + 1);
            H1s[(m0 + g) * XP128 + p0]     = to_tf32(gelu_f(acc[nt][0] + b1s[cn]));
            H1s[(m0 + g) * XP128 + p1]     = to_tf32(gelu_f(acc[nt][1] + b1s[cn + 1]));
            H1s[(m0 + g + 8) * XP128 + p0] = to_tf32(gelu_f(acc[nt][2] + b1s[cn]));
            H1s[(m0 + g + 8) * XP128 + p1] = to_tf32(gelu_f(acc[nt][3] + b1s[cn + 1]));
        }
        __syncthreads();
        float acc2[4][4] = {};
        warp_gemm4<16>(H1s, XP128, W2t, XP128, m0, n0, acc2);
        {
            int r0 = m0 + g, r1 = m0 + g + 8;
            int dd0 = dst_s[r0], ss0 = src_s[r0];
            int dd1 = dst_s[r1], ss1 = src_s[r1];
            const float* hp0 = g_hmsg + (size_t)dd0 * 128;
            const float* hp1 = g_hmsg + (size_t)dd1 * 128;
            float* ap0 = g_agg + (size_t)ss0 * 128;
            float* ap1 = g_agg + (size_t)ss1 * 128;
#pragma unroll
            for (int nt = 0; nt < 4; nt++) {
                int cn = n0 + nt * 8 + 2 * tig;
                float2 h0 = *(const float2*)(hp0 + cn);
                float2 h1 = *(const float2*)(hp1 + cn);
                float2 m0v = make_float2(gelu_f(acc2[nt][0] + b2s[cn])     * h0.x,
                                         gelu_f(acc2[nt][1] + b2s[cn + 1]) * h0.y);
                float2 m1v = make_float2(gelu_f(acc2[nt][2] + b2s[cn])     * h1.x,
                                         gelu_f(acc2[nt][3] + b2s[cn + 1]) * h1.y);
                atomicAdd(reinterpret_cast<float2*>(ap0 + cn), m0v);
                atomicAdd(reinterpret_cast<float2*>(ap1 + cn), m1v);
            }
        }
        __syncthreads();
    }
}

// ============== update stage 1: [node_x | agg/cnt] @ upW1 (K=256), 1024 thr ==============
#define SMU_TOT ((128 * XP256 + 128 * XP128 + 128) * 4)
__global__ void __launch_bounds__(1024, 1)
up1_tc(const float* __restrict__ X, int tiles) {
    extern __shared__ float sm[];
    float* W1t = sm;
    float* Xs  = W1t + 128 * XP256;
    float* b1s = Xs + 128 * XP128;
    const int tid = threadIdx.x, wid = tid >> 5, l = tid & 31, g = l >> 2, tig = l & 3;
    const int m0 = (wid >> 2) * 16, n0 = (wid & 3) * 32;
    for (int i = tid; i < 256 * 128; i += 1024) { int k = i >> 7, n = i & 127; W1t[n * XP256 + kperm(k)] = to_tf32(g_upW1[i]); }
    if (tid < 128) b1s[tid] = g_upB1[tid];
    __syncthreads();
    for (int t = blockIdx.x; t < tiles; t += gridDim.x) {
        size_t base = (size_t)t * 128;
        for (int i = tid; i < 128 * 32; i += 1024) {
            int r = i >> 5, kq = (i & 31) * 4;
            float4 v = *(const float4*)(X + (base + r) * 128 + kq);
            float* p = Xs + r * XP128;
            p[kperm(kq)]     = to_tf32(v.x);
            p[kperm(kq + 1)] = to_tf32(v.y);
            p[kperm(kq + 2)] = to_tf32(v.z);
            p[kperm(kq + 3)] = to_tf32(v.w);
        }
        __syncthreads();
        float acc[4][4] = {};
        warp_gemm4<16>(Xs, XP128, W1t, XP256, m0, n0, acc);
        __syncthreads();
        for (int i = tid; i < 128 * 32; i += 1024) {
            int r = i >> 5, kq = (i & 31) * 4;
            float sc = 1.0f / fmaxf(g_cnt[base + r], 1.0f);
            float4 v = *(const float4*)(g_agg + (base + r) * 128 + kq);
            float* p = Xs + r * XP128;
            p[kperm(kq)]     = to_tf32(v.x * sc);
            p[kperm(kq + 1)] = to_tf32(v.y * sc);
            p[kperm(kq + 2)] = to_tf32(v.z * sc);
            p[kperm(kq + 3)] = to_tf32(v.w * sc);
        }
        __syncthreads();
        warp_gemm4<16>(Xs, XP128, W1t + 128, XP256, m0, n0, acc);
#pragma unroll
        for (int nt = 0; nt < 4; nt++) {
            int cn = n0 + nt * 8 + 2 * tig;
            float2 v0 = make_float2(gelu_f(acc[nt][0] + b1s[cn]), gelu_f(acc[nt][1] + b1s[cn + 1]));
            float2 v1 = make_float2(gelu_f(acc[nt][2] + b1s[cn]), gelu_f(acc[nt][3] + b1s[cn + 1]));
            *(float2*)(g_u1 + (base + m0 + g) * 128 + cn)     = v0;
            *(float2*)(g_u1 + (base + m0 + g + 8) * 128 + cn) = v1;
        }
        __syncthreads();
    }
}

// ============== update stage 2: g_u1 @ upW2 -> gelu -> out, 1024 thr ==============
#define SMM_TOT ((2 * 128 * XP128 + 128) * 4)
__global__ void __launch_bounds__(1024, 1)
mlp1_tc(float* __restrict__ out, int tiles) {
    extern __shared__ float sm[];
    float* Wt = sm;
    float* Xs = Wt + 128 * XP128;
    float* bs = Xs + 128 * XP128;
    const int tid = threadIdx.x, wid = tid >> 5, l = tid & 31, g = l >> 2, tig = l & 3;
    const int m0 = (wid >> 2) * 16, n0 = (wid & 3) * 32;
    for (int i = tid; i < 128 * 128; i += 1024) { int k = i >> 7, n = i & 127; Wt[n * XP128 + kperm(k)] = to_tf32(g_upW2[i]); }
    if (tid < 128) bs[tid] = g_upB2[tid];
    __syncthreads();
    for (int t = blockIdx.x; t < tiles; t += gridDim.x) {
        size_t base = (size_t)t * 128;
        for (int i = tid; i < 128 * 32; i += 1024) {
            int r = i >> 5, kq = (i & 31) * 4;
            float4 v = *(const float4*)(g_u1 + (base + r) * 128 + kq);
            float* p = Xs + r * XP128;
            p[kperm(kq)]     = to_tf32(v.x);
            p[kperm(kq + 1)] = to_tf32(v.y);
            p[kperm(kq + 2)] = to_tf32(v.z);
            p[kperm(kq + 3)] = to_tf32(v.w);
        }
        __syncthreads();
        float acc[4][4] = {};
        warp_gemm4<16>(Xs, XP128, Wt, XP128, m0, n0, acc);
#pragma unroll
        for (int nt = 0; nt < 4; nt++) {
            int cn = n0 + nt * 8 + 2 * tig;
            float2 v0 = make_float2(gelu_f(acc[nt][0] + bs[cn]), gelu_f(acc[nt][1] + bs[cn + 1]));
            float2 v1 = make_float2(gelu_f(acc[nt][2] + bs[cn]), gelu_f(acc[nt][3] + bs[cn + 1]));
            *(float2*)(out + (base + m0 + g) * 128 + cn)     = v0;
            *(float2*)(out + (base + m0 + g + 8) * 128 + cn) = v1;
        }
        __syncthreads();
    }
}

// ---------------- launch ----------------
extern "C" void kernel_launch(void* const* d_in, const int* in_sizes, int n_in,
                              void* d_out, int out_size) {
    const float* node_x = (const float*)d_in[0];
    const float* eattr  = (const float*)d_in[1];
    const float* bm_g1 = (const float*)d_in[2];
    const float* bm_b1 = (const float*)d_in[3];
    const float* bm_m1 = (const float*)d_in[4];
    const float* bm_v1 = (const float*)d_in[5];
    const float* bm_w1 = (const float*)d_in[6];
    const float* bm_bb1= (const float*)d_in[7];
    const float* bm_g2 = (const float*)d_in[8];
    const float* bm_b2 = (const float*)d_in[9];
    const float* bm_m2 = (const float*)d_in[10];
    const float* bm_v2 = (const float*)d_in[11];
    const float* bm_w2 = (const float*)d_in[12];
    const float* bm_bb2= (const float*)d_in[13];
    const float* et_w1 = (const float*)d_in[14];
    const float* et_b1 = (const float*)d_in[15];
    const float* et_w2 = (const float*)d_in[16];
    const float* et_b2 = (const float*)d_in[17];
    const float* up_g1 = (const float*)d_in[18];
    const float* up_b1 = (const float*)d_in[19];
    const float* up_m1 = (const float*)d_in[20];
    const float* up_v1 = (const float*)d_in[21];
    const float* up_w1 = (const float*)d_in[22];
    const float* up_bb1= (const float*)d_in[23];
    const float* up_g2 = (const float*)d_in[24];
    const float* up_b2 = (const float*)d_in[25];
    const float* up_m2 = (const float*)d_in[26];
    const float* up_v2 = (const float*)d_in[27];
    const float* up_w2 = (const float*)d_in[28];
    const float* up_bb2= (const float*)d_in[29];
    const int*   esrc  = (const int*)d_in[30];
    const int*   edst  = (const int*)d_in[31];
    float* out = (float*)d_out;

    cudaFuncSetAttribute(node_tc, cudaFuncAttributeMaxDynamicSharedMemorySize, SMN_TOT);
    cudaFuncSetAttribute(edge_tc, cudaFuncAttributeMaxDynamicSharedMemorySize, SME_TOT);
    cudaFuncSetAttribute(up1_tc,  cudaFuncAttributeMaxDynamicSharedMemorySize, SMU_TOT);
    cudaFuncSetAttribute(mlp1_tc, cudaFuncAttributeMaxDynamicSharedMemorySize, SMM_TOT);

    FoldArgs fa;
    fa.g[0] = bm_g1; fa.b[0] = bm_b1; fa.m[0] = bm_m1; fa.v[0] = bm_v1; fa.W[0] = bm_w1; fa.bb[0] = bm_bb1; fa.K[0] = DN;
    fa.g[1] = bm_g2; fa.b[1] = bm_b2; fa.m[1] = bm_m2; fa.v[1] = bm_v2; fa.W[1] = bm_w2; fa.bb[1] = bm_bb2; fa.K[1] = HH;
    fa.g[2] = up_g1; fa.b[2] = up_b1; fa.m[2] = up_m1; fa.v[2] = up_v1; fa.W[2] = up_w1; fa.bb[2] = up_bb1; fa.K[2] = DC;
    fa.g[3] = up_g2; fa.b[3] = up_b2; fa.m[3] = up_m2; fa.v[3] = up_v2; fa.W[3] = up_w2; fa.bb[3] = up_bb2; fa.K[3] = HH;
    fold_all<<<512 + ZBLOCKS, 256>>>(fa);          // fold + zero agg/cnt in one launch

    deg_kernel<<<(NE + 255) / 256, 256>>>(esrc);

    node_tc<<<148, 1024, SMN_TOT>>>(node_x, NN / 128);
    edge_tc<<<148, 1024, SME_TOT>>>(eattr, et_w1, et_b1, et_w2, et_b2, esrc, edst, NE / 128);
    up1_tc<<<148, 1024, SMU_TOT>>>(node_x, NN / 128);
    mlp1_tc<<<148, 1024, SMM_TOT>>>(out, NN / 128);
}

// round 17
// speedup vs baseline: 3.7576x; 1.0855x over previous
#include <cuda_runtime.h>
#include <math.h>
#include <stdint.h>

#define NN 65536
#define NE 524288
#define DN 128
#define DE 64
#define HH 128
#define DC (DN + HH)
#define EPSbn 1e-3f

// pitches (floats), all == 8 mod 32 for conflict-free LDS.64 fragment loads
#define XP128 136
#define XP64  72
#define XP256 264

// ---------------- scratch ----------------
__device__ float g_hmsg[(size_t)NN * HH];
__device__ float g_agg [(size_t)NN * HH];
__device__ float g_u1  [(size_t)NN * HH];
__device__ float g_cnt [NN];

__device__ float g_bmW1[DN * HH]; __device__ float g_bmB1[HH];
__device__ float g_bmW2[HH * HH]; __device__ float g_bmB2[HH];
__device__ float g_upW1[DC * HH]; __device__ float g_upB1[HH];
__device__ float g_upW2[HH * HH]; __device__ float g_upB2[HH];

// fast exact-enough gelu: 0.5*x*(1+erf(x/sqrt2)), erf via A&S 7.1.26 (|err|<1.5e-7)
__device__ __forceinline__ float gelu_f(float x) {
    float z  = x * 0.70710678118654752f;
    float az = fabsf(z);
    float t;
    asm("rcp.approx.f32 %0, %1;" : "=f"(t) : "f"(fmaf(0.3275911f, az, 1.0f)));
    float p = fmaf(1.061405429f, t, -1.453152027f);
    p = fmaf(p, t, 1.421413741f);
    p = fmaf(p, t, -0.284496736f);
    p = fmaf(p, t, 0.254829592f);
    p = p * t;
    float e = __expf(-z * z);
    float erfa = fmaf(-p, e, 1.0f);
    float erfz = copysignf(erfa, z);
    return 0.5f * x * (1.0f + erfz);
}

// tf32 round
__device__ __forceinline__ float to_tf32(float x) {
    uint32_t r; asm("cvt.rna.tf32.f32 %0, %1;" : "=r"(r) : "f"(x));
    return __uint_as_float(r);
}

// k-permutation within each 8-block: pairs (k, k+4) land adjacent -> LDS.64 fragments
__device__ __forceinline__ int kperm(int k) {
    return (k & ~7) | ((k & 3) << 1) | ((k >> 2) & 1);
}

// ---------------- warp-level tf32 MMA GEMM (16 rows x 32 cols), LDS.64 fragments ----------------
template<int KT>
__device__ __forceinline__ void warp_gemm4(const float* __restrict__ Xs, int xp,
                                           const float* __restrict__ Wt, int wp,
                                           int m0, int n0, float (&acc)[4][4]) {
    const int l = threadIdx.x & 31, g = l >> 2, tig = l & 3;
    const float2* xr0 = (const float2*)(Xs + (m0 + g) * xp) + tig;
    const float2* xr1 = (const float2*)(Xs + (m0 + g + 8) * xp) + tig;
    const float2* wb  = (const float2*)(Wt + (n0 + g) * wp) + tig;
    const int wp2 = wp >> 1;
#pragma unroll 4
    for (int s = 0; s < KT; s++) {
        const int k2 = 4 * s;
        float2 A0 = xr0[k2];
        float2 A1 = xr1[k2];
#pragma unroll
        for (int nt = 0; nt < 4; nt++) {
            float2 B = wb[nt * 8 * wp2 + k2];
            asm volatile(
                "mma.sync.aligned.m16n8k8.row.col.f32.tf32.tf32.f32 "
                "{%0,%1,%2,%3}, {%4,%5,%6,%7}, {%8,%9}, {%0,%1,%2,%3};"
                : "+f"(acc[nt][0]), "+f"(acc[nt][1]), "+f"(acc[nt][2]), "+f"(acc[nt][3])
                : "r"(__float_as_uint(A0.x)), "r"(__float_as_uint(A1.x)),
                  "r"(__float_as_uint(A0.y)), "r"(__float_as_uint(A1.y)),
                  "r"(__float_as_uint(B.x)),  "r"(__float_as_uint(B.y)));
        }
    }
}

// ---------------- BN folding + scratch zeroing, one launch ----------------
struct FoldArgs {
    const float* g[4]; const float* b[4]; const float* m[4]; const float* v[4];
    const float* W[4]; const float* bb[4]; int K[4];
};

#define ZBLOCKS (NN * HH / 4 / 256)   // 8192

__global__ void fold_all(FoldArgs a) {
    const int tid = threadIdx.x;
    if (blockIdx.x >= 512) {
        int i = (blockIdx.x - 512) * 256 + tid;
        if (i < NN * HH / 4) ((float4*)g_agg)[i] = make_float4(0.f, 0.f, 0.f, 0.f);
        if (i < NN / 4)      ((float4*)g_cnt)[i] = make_float4(0.f, 0.f, 0.f, 0.f);
        return;
    }
    const int which = blockIdx.x >> 7;
    const int j = blockIdx.x & 127;
    float* Wo; float* Bo;
    if      (which == 0) { Wo = g_bmW1; Bo = g_bmB1; }
    else if (which == 1) { Wo = g_bmW2; Bo = g_bmB2; }
    else if (which == 2) { Wo = g_upW1; Bo = g_upB1; }
    else                 { Wo = g_upW2; Bo = g_upB2; }
    const float* g = a.g[which]; const float* b = a.b[which];
    const float* m = a.m[which]; const float* v = a.v[which];
    const float* W = a.W[which]; const float* bb = a.bb[which];
    const int K = a.K[which];
    __shared__ float red[256];
    float acc = 0.f;
    for (int i = tid; i < K; i += 256) {
        float s = g[i] * rsqrtf(v[i] + EPSbn);
        float t = b[i] - m[i] * s;
        float w = W[i * HH + j];
        Wo[i * HH + j] = s * w;
        acc += t * w;
    }
    red[tid] = acc; __syncthreads();
    for (int o = 128; o > 0; o >>= 1) { if (tid < o) red[tid] += red[tid + o]; __syncthreads(); }
    if (tid == 0) Bo[j] = bb[j] + red[0];
}

__global__ void deg_kernel(const int* __restrict__ src) {
    int i = blockIdx.x * blockDim.x + threadIdx.x;
    if (i < NE) atomicAdd(&g_cnt[src[i]], 1.0f);
}

// ============== node base-message MLP: two fused 128x128 GEMMs, 1024 thr (32 warps) ==============
#define SMN_TOT ((3 * 128 * XP128 + 256) * 4)
__global__ void __launch_bounds__(1024, 1)
node_tc(const float* __restrict__ X, int tiles) {
    extern __shared__ float sm[];
    float* W1t = sm;
    float* W2t = W1t + 128 * XP128;
    float* Xs  = W2t + 128 * XP128;
    float* b1s = Xs + 128 * XP128;
    float* b2s = b1s + 128;
    const int tid = threadIdx.x, wid = tid >> 5, l = tid & 31, g = l >> 2, tig = l & 3;
    const int m0 = (wid >> 2) * 16, n0 = (wid & 3) * 32;
    for (int i = tid; i < 128 * 128; i += 1024) {
        int k = i >> 7, n = i & 127;
        W1t[n * XP128 + kperm(k)] = to_tf32(g_bmW1[i]);
        W2t[n * XP128 + kperm(k)] = to_tf32(g_bmW2[i]);
    }
    if (tid < 128) { b1s[tid] = g_bmB1[tid]; b2s[tid] = g_bmB2[tid]; }
    __syncthreads();
    for (int t = blockIdx.x; t < tiles; t += gridDim.x) {
        size_t base = (size_t)t * 128;
        for (int i = tid; i < 128 * 32; i += 1024) {
            int r = i >> 5, kq = (i & 31) * 4;
            float4 v = *(const float4*)(X + (base + r) * 128 + kq);
            float* p = Xs + r * XP128;
            p[kperm(kq)]     = to_tf32(v.x);
            p[kperm(kq + 1)] = to_tf32(v.y);
            p[kperm(kq + 2)] = to_tf32(v.z);
            p[kperm(kq + 3)] = to_tf32(v.w);
        }
        __syncthreads();
        float acc[4][4] = {};
        warp_gemm4<16>(Xs, XP128, W1t, XP128, m0, n0, acc);
        __syncthreads();
#pragma unroll
        for (int nt = 0; nt < 4; nt++) {
            int cn = n0 + nt * 8 + 2 * tig;
            int p0 = kperm(cn), p1 = kperm(cn + 1);
            Xs[(m0 + g) * XP128 + p0]     = to_tf32(gelu_f(acc[nt][0] + b1s[cn]));
            Xs[(m0 + g) * XP128 + p1]     = to_tf32(gelu_f(acc[nt][1] + b1s[cn + 1]));
            Xs[(m0 + g + 8) * XP128 + p0] = to_tf32(gelu_f(acc[nt][2] + b1s[cn]));
            Xs[(m0 + g + 8) * XP128 + p1] = to_tf32(gelu_f(acc[nt][3] + b1s[cn + 1]));
        }
        __syncthreads();
        float acc2[4][4] = {};
        warp_gemm4<16>(Xs, XP128, W2t, XP128, m0, n0, acc2);
#pragma unroll
        for (int nt = 0; nt < 4; nt++) {
            int cn = n0 + nt * 8 + 2 * tig;
            float2 v0 = make_float2(gelu_f(acc2[nt][0] + b2s[cn]), gelu_f(acc2[nt][1] + b2s[cn + 1]));
            float2 v1 = make_float2(gelu_f(acc2[nt][2] + b2s[cn]), gelu_f(acc2[nt][3] + b2s[cn + 1]));
            *(float2*)(g_hmsg + (base + m0 + g) * 128 + cn)     = v0;
            *(float2*)(g_hmsg + (base + m0 + g + 8) * 128 + cn) = v1;
        }
        __syncthreads();
    }
}

// ============== edge kernel: DUAL 512-thread pipelines, 64-edge tiles, named barriers ==============
// smem: W1t 128*XP64 | W2t 128*XP128 | b1 128 | b2 128 | EA 2x64*XP64 | H1 2x64*XP128 | idx 256 ints
#define SME_TOT ((128 * XP64 + 128 * XP128 + 256 + 2 * 64 * XP64 + 2 * 64 * XP128) * 4 + 256 * 4)
__global__ void __launch_bounds__(1024, 1)
edge_tc(const float* __restrict__ EA,
        const float* __restrict__ W1, const float* __restrict__ B1,
        const float* __restrict__ W2, const float* __restrict__ B2,
        const int* __restrict__ esrc, const int* __restrict__ edst, int tiles) {
    extern __shared__ float sm[];
    float* W1t = sm;                          // 128 x XP64
    float* W2t = W1t + 128 * XP64;            // 128 x XP128
    float* b1s = W2t + 128 * XP128;
    float* b2s = b1s + 128;
    float* EAb = b2s + 128;                   // 2 x 64 x XP64
    float* H1b = EAb + 2 * 64 * XP64;         // 2 x 64 x XP128
    int*   idx = (int*)(H1b + 2 * 64 * XP128);
    const int tid = threadIdx.x;
    for (int i = tid; i < 64 * 128; i += 1024) { int k = i >> 7, n = i & 127; W1t[n * XP64 + kperm(k)] = to_tf32(W1[i]); }
    for (int i = tid; i < 128 * 128; i += 1024) { int k = i >> 7, n = i & 127; W2t[n * XP128 + kperm(k)] = to_tf32(W2[i]); }
    if (tid < 128) { b1s[tid] = B1[tid]; b2s[tid] = B2[tid]; }
    __syncthreads();
    // split into two independent pipelines
    const int h = tid >> 9, ltid = tid & 511;
    const int lwid = ltid >> 5, l = ltid & 31, g = l >> 2, tig = l & 3;
    const int m0 = (lwid >> 2) * 16, n0 = (lwid & 3) * 32;
    float* EAs = EAb + h * 64 * XP64;
    float* H1s = H1b + h * 64 * XP128;
    int* src_s = idx + h * 128;
    int* dst_s = src_s + 64;
    const uint32_t barid = h + 1;
    for (int t = blockIdx.x * 2 + h; t < tiles; t += gridDim.x * 2) {
        size_t base = (size_t)t * 64;
        for (int i = ltid; i < 64 * 16; i += 512) {
            int r = i >> 4, kq = (i & 15) * 4;
            float4 v = *(const float4*)(EA + (base + r) * 64 + kq);
            float* p = EAs + r * XP64;
            p[kperm(kq)]     = to_tf32(v.x);
            p[kperm(kq + 1)] = to_tf32(v.y);
            p[kperm(kq + 2)] = to_tf32(v.z);
            p[kperm(kq + 3)] = to_tf32(v.w);
        }
        if (ltid < 64)       src_s[ltid] = esrc[base + ltid];
        else if (ltid < 128) dst_s[ltid - 64] = edst[base + ltid - 64];
        asm volatile("bar.sync %0, 512;" :: "r"(barid) : "memory");
        float acc[4][4] = {};
        warp_gemm4<8>(EAs, XP64, W1t, XP64, m0, n0, acc);
#pragma unroll
        for (int nt = 0; nt < 4; nt++) {
            int cn = n0 + nt * 8 + 2 * tig;
            int p0 = kperm(cn), p1 = kperm(cn + 1);
            H1s[(m0 + g) * XP128 + p0]     = to_tf32(gelu_f(acc[nt][0] + b1s[cn]));
            H1s[(m0 + g) * XP128 + p1]     = to_tf32(gelu_f(acc[nt][1] + b1s[cn + 1]));
            H1s[(m0 + g + 8) * XP128 + p0] = to_tf32(gelu_f(acc[nt][2] + b1s[cn]));
            H1s[(m0 + g + 8) * XP128 + p1] = to_tf32(gelu_f(acc[nt][3] + b1s[cn + 1]));
        }
        asm volatile("bar.sync %0, 512;" :: "r"(barid) : "memory");
        float acc2[4][4] = {};
        warp_gemm4<16>(H1s, XP128, W2t, XP128, m0, n0, acc2);
        {
            int r0 = m0 + g, r1 = m0 + g + 8;
            int dd0 = dst_s[r0], ss0 = src_s[r0];
            int dd1 = dst_s[r1], ss1 = src_s[r1];
            const float* hp0 = g_hmsg + (size_t)dd0 * 128;
            const float* hp1 = g_hmsg + (size_t)dd1 * 128;
            float* ap0 = g_agg + (size_t)ss0 * 128;
            float* ap1 = g_agg + (size_t)ss1 * 128;
#pragma unroll
            for (int nt = 0; nt < 4; nt++) {
                int cn = n0 + nt * 8 + 2 * tig;
                float2 h0 = *(const float2*)(hp0 + cn);
                float2 h1 = *(const float2*)(hp1 + cn);
                float2 m0v = make_float2(gelu_f(acc2[nt][0] + b2s[cn])     * h0.x,
                                         gelu_f(acc2[nt][1] + b2s[cn + 1]) * h0.y);
                float2 m1v = make_float2(gelu_f(acc2[nt][2] + b2s[cn])     * h1.x,
                                         gelu_f(acc2[nt][3] + b2s[cn + 1]) * h1.y);
                atomicAdd(reinterpret_cast<float2*>(ap0 + cn), m0v);
                atomicAdd(reinterpret_cast<float2*>(ap1 + cn), m1v);
            }
        }
        asm volatile("bar.sync %0, 512;" :: "r"(barid) : "memory");
    }
}

// ============== update stage 1: [node_x | agg/cnt] @ upW1 (K=256), 1024 thr ==============
#define SMU_TOT ((128 * XP256 + 128 * XP128 + 128) * 4)
__global__ void __launch_bounds__(1024, 1)
up1_tc(const float* __restrict__ X, int tiles) {
    extern __shared__ float sm[];
    float* W1t = sm;
    float* Xs  = W1t + 128 * XP256;
    float* b1s = Xs + 128 * XP128;
    const int tid = threadIdx.x, wid = tid >> 5, l = tid & 31, g = l >> 2, tig = l & 3;
    const int m0 = (wid >> 2) * 16, n0 = (wid & 3) * 32;
    for (int i = tid; i < 256 * 128; i += 1024) { int k = i >> 7, n = i & 127; W1t[n * XP256 + kperm(k)] = to_tf32(g_upW1[i]); }
    if (tid < 128) b1s[tid] = g_upB1[tid];
    __syncthreads();
    for (int t = blockIdx.x; t < tiles; t += gridDim.x) {
        size_t base = (size_t)t * 128;
        for (int i = tid; i < 128 * 32; i += 1024) {
            int r = i >> 5, kq = (i & 31) * 4;
            float4 v = *(const float4*)(X + (base + r) * 128 + kq);
            float* p = Xs + r * XP128;
            p[kperm(kq)]     = to_tf32(v.x);
            p[kperm(kq + 1)] = to_tf32(v.y);
            p[kperm(kq + 2)] = to_tf32(v.z);
            p[kperm(kq + 3)] = to_tf32(v.w);
        }
        __syncthreads();
        float acc[4][4] = {};
        warp_gemm4<16>(Xs, XP128, W1t, XP256, m0, n0, acc);
        __syncthreads();
        for (int i = tid; i < 128 * 32; i += 1024) {
            int r = i >> 5, kq = (i & 31) * 4;
            float sc = 1.0f / fmaxf(g_cnt[base + r], 1.0f);
            float4 v = *(const float4*)(g_agg + (base + r) * 128 + kq);
            float* p = Xs + r * XP128;
            p[kperm(kq)]     = to_tf32(v.x * sc);
            p[kperm(kq + 1)] = to_tf32(v.y * sc);
            p[kperm(kq + 2)] = to_tf32(v.z * sc);
            p[kperm(kq + 3)] = to_tf32(v.w * sc);
        }
        __syncthreads();
        warp_gemm4<16>(Xs, XP128, W1t + 128, XP256, m0, n0, acc);
#pragma unroll
        for (int nt = 0; nt < 4; nt++) {
            int cn = n0 + nt * 8 + 2 * tig;
            float2 v0 = make_float2(gelu_f(acc[nt][0] + b1s[cn]), gelu_f(acc[nt][1] + b1s[cn + 1]));
            float2 v1 = make_float2(gelu_f(acc[nt][2] + b1s[cn]), gelu_f(acc[nt][3] + b1s[cn + 1]));
            *(float2*)(g_u1 + (base + m0 + g) * 128 + cn)     = v0;
            *(float2*)(g_u1 + (base + m0 + g + 8) * 128 + cn) = v1;
        }
        __syncthreads();
    }
}

// ============== update stage 2: g_u1 @ upW2 -> gelu -> out, 1024 thr ==============
#define SMM_TOT ((2 * 128 * XP128 + 128) * 4)
__global__ void __launch_bounds__(1024, 1)
mlp1_tc(float* __restrict__ out, int tiles) {
    extern __shared__ float sm[];
    float* Wt = sm;
    float* Xs = Wt + 128 * XP128;
    float* bs = Xs + 128 * XP128;
    const int tid = threadIdx.x, wid = tid >> 5, l = tid & 31, g = l >> 2, tig = l & 3;
    const int m0 = (wid >> 2) * 16, n0 = (wid & 3) * 32;
    for (int i = tid; i < 128 * 128; i += 1024) { int k = i >> 7, n = i & 127; Wt[n * XP128 + kperm(k)] = to_tf32(g_upW2[i]); }
    if (tid < 128) bs[tid] = g_upB2[tid];
    __syncthreads();
    for (int t = blockIdx.x; t < tiles; t += gridDim.x) {
        size_t base = (size_t)t * 128;
        for (int i = tid; i < 128 * 32; i += 1024) {
            int r = i >> 5, kq = (i & 31) * 4;
            float4 v = *(const float4*)(g_u1 + (base + r) * 128 + kq);
            float* p = Xs + r * XP128;
            p[kperm(kq)]     = to_tf32(v.x);
            p[kperm(kq + 1)] = to_tf32(v.y);
            p[kperm(kq + 2)] = to_tf32(v.z);
            p[kperm(kq + 3)] = to_tf32(v.w);
        }
        __syncthreads();
        float acc[4][4] = {};
        warp_gemm4<16>(Xs, XP128, Wt, XP128, m0, n0, acc);
#pragma unroll
        for (int nt = 0; nt < 4; nt++) {
            int cn = n0 + nt * 8 + 2 * tig;
            float2 v0 = make_float2(gelu_f(acc[nt][0] + bs[cn]), gelu_f(acc[nt][1] + bs[cn + 1]));
            float2 v1 = make_float2(gelu_f(acc[nt][2] + bs[cn]), gelu_f(acc[nt][3] + bs[cn + 1]));
            *(float2*)(out + (base + m0 + g) * 128 + cn)     = v0;
            *(float2*)(out + (base + m0 + g + 8) * 128 + cn) = v1;
        }
        __syncthreads();
    }
}

// ---------------- launch ----------------
extern "C" void kernel_launch(void* const* d_in, const int* in_sizes, int n_in,
                              void* d_out, int out_size) {
    const float* node_x = (const float*)d_in[0];
    const float* eattr  = (const float*)d_in[1];
    const float* bm_g1 = (const float*)d_in[2];
    const float* bm_b1 = (const float*)d_in[3];
    const float* bm_m1 = (const float*)d_in[4];
    const float* bm_v1 = (const float*)d_in[5];
    const float* bm_w1 = (const float*)d_in[6];
    const float* bm_bb1= (const float*)d_in[7];
    const float* bm_g2 = (const float*)d_in[8];
    const float* bm_b2 = (const float*)d_in[9];
    const float* bm_m2 = (const float*)d_in[10];
    const float* bm_v2 = (const float*)d_in[11];
    const float* bm_w2 = (const float*)d_in[12];
    const float* bm_bb2= (const float*)d_in[13];
    const float* et_w1 = (const float*)d_in[14];
    const float* et_b1 = (const float*)d_in[15];
    const float* et_w2 = (const float*)d_in[16];
    const float* et_b2 = (const float*)d_in[17];
    const float* up_g1 = (const float*)d_in[18];
    const float* up_b1 = (const float*)d_in[19];
    const float* up_m1 = (const float*)d_in[20];
    const float* up_v1 = (const float*)d_in[21];
    const float* up_w1 = (const float*)d_in[22];
    const float* up_bb1= (const float*)d_in[23];
    const float* up_g2 = (const float*)d_in[24];
    const float* up_b2 = (const float*)d_in[25];
    const float* up_m2 = (const float*)d_in[26];
    const float* up_v2 = (const float*)d_in[27];
    const float* up_w2 = (const float*)d_in[28];
    const float* up_bb2= (const float*)d_in[29];
    const int*   esrc  = (const int*)d_in[30];
    const int*   edst  = (const int*)d_in[31];
    float* out = (float*)d_out;

    cudaFuncSetAttribute(node_tc, cudaFuncAttributeMaxDynamicSharedMemorySize, SMN_TOT);
    cudaFuncSetAttribute(edge_tc, cudaFuncAttributeMaxDynamicSharedMemorySize, SME_TOT);
    cudaFuncSetAttribute(up1_tc,  cudaFuncAttributeMaxDynamicSharedMemorySize, SMU_TOT);
    cudaFuncSetAttribute(mlp1_tc, cudaFuncAttributeMaxDynamicSharedMemorySize, SMM_TOT);

    FoldArgs fa;
    fa.g[0] = bm_g1; fa.b[0] = bm_b1; fa.m[0] = bm_m1; fa.v[0] = bm_v1; fa.W[0] = bm_w1; fa.bb[0] = bm_bb1; fa.K[0] = DN;
    fa.g[1] = bm_g2; fa.b[1] = bm_b2; fa.m[1] = bm_m2; fa.v[1] = bm_v2; fa.W[1] = bm_w2; fa.bb[1] = bm_bb2; fa.K[1] = HH;
    fa.g[2] = up_g1; fa.b[2] = up_b1; fa.m[2] = up_m1; fa.v[2] = up_v1; fa.W[2] = up_w1; fa.bb[2] = up_bb1; fa.K[2] = DC;
    fa.g[3] = up_g2; fa.b[3] = up_b2; fa.m[3] = up_m2; fa.v[3] = up_v2; fa.W[3] = up_w2; fa.bb[3] = up_bb2; fa.K[3] = HH;
    fold_all<<<512 + ZBLOCKS, 256>>>(fa);

    deg_kernel<<<(NE + 255) / 256, 256>>>(esrc);

    node_tc<<<148, 1024, SMN_TOT>>>(node_x, NN / 128);
    edge_tc<<<148, 1024, SME_TOT>>>(eattr, et_w1, et_b1, et_w2, et_b2, esrc, edst, NE / 64);
    up1_tc<<<148, 1024, SMU_TOT>>>(node_x, NN / 128);
    mlp1_tc<<<148, 1024, SMM_TOT>>>(out, NN / 128);
}